// round 1
// baseline (speedup 1.0000x reference)
#include <cuda_runtime.h>
#include <cuda_bf16.h>

#define NBATCH 16
#define NSEQ   1024
#define NDIM   768
#define NHEADS 12
#define NHD    64
#define ATT_SCALE 0.125f

// Scratch (static device globals: allocation-free per harness rules)
__device__ float g_q[NBATCH*NHEADS*NSEQ*NHD];   // [B*H, N, D]
__device__ float g_k[NBATCH*NHEADS*NSEQ*NHD];
__device__ float g_v[NBATCH*NHEADS*NSEQ*NHD];
__device__ float g_o[NBATCH*NSEQ*NDIM];         // [B*N, C]

typedef unsigned long long u64;

// ---------- packed f32x2 helpers (FFMA2 path, sm_103a) ----------
__device__ __forceinline__ u64 pack2(float x, float y){
    u64 r; asm("mov.b64 %0, {%1, %2};" : "=l"(r) : "r"(__float_as_uint(x)), "r"(__float_as_uint(y))); return r;
}
__device__ __forceinline__ u64 splat2(float x){
    u64 r; asm("mov.b64 %0, {%1, %1};" : "=l"(r) : "r"(__float_as_uint(x))); return r;
}
__device__ __forceinline__ void fma2(u64& d, u64 a, u64 b){
    asm("fma.rn.f32x2 %0, %1, %2, %0;" : "+l"(d) : "l"(a), "l"(b));
}
__device__ __forceinline__ u64 mul2(u64 a, u64 b){
    u64 r; asm("mul.rn.f32x2 %0, %1, %2;" : "=l"(r) : "l"(a), "l"(b)); return r;
}
__device__ __forceinline__ float2 unpack2(u64 v){
    unsigned lo, hi; asm("mov.b64 {%0, %1}, %2;" : "=r"(lo), "=r"(hi) : "l"(v));
    return make_float2(__uint_as_float(lo), __uint_as_float(hi));
}

// ---------- fast exp on the FMA pipe (no MUFU) ----------
// exp(x) for x <= 0; abs poly error ~2.4e-6 on 2^f, f in [-0.5, 0.5]
__device__ __forceinline__ float fast_exp(float x){
    x = fmaxf(x, -80.0f);
    float t  = x * 1.4426950408889634f;
    float tr = t + 12582912.0f;                 // round-to-nearest-int magic (1.5*2^23)
    int   n  = __float_as_int(tr) - 0x4B400000;
    float rn = tr - 12582912.0f;
    float f  = t - rn;
    float p = 1.3333558146428443e-3f;
    p = fmaf(p, f, 9.618129107628477e-3f);
    p = fmaf(p, f, 5.550410866482158e-2f);
    p = fmaf(p, f, 2.402265069591007e-1f);
    p = fmaf(p, f, 6.931471805599453e-1f);
    p = fmaf(p, f, 1.0f);
    return p * __int_as_float((n + 127) << 23);
}

// =====================================================================
// Tiled SGEMM: C[M,Nc] = A[M,768] * B[Nc,768]^T  (both row-major, K=768)
// BM=BN=128, BK=16, 256 threads, 8x8 microtile as 8x(4 f32x2).
// =====================================================================
__device__ __forceinline__ void gemm_mainloop(
    const float* __restrict__ A, const float* __restrict__ Bm,
    int m0, int n0, int tid, int tx, int ty,
    u64 acc[8][4], float (*As)[132], float (*Bs)[132])
{
    for (int k0 = 0; k0 < 768; k0 += 16) {
        #pragma unroll
        for (int it = 0; it < 2; it++) {
            int f   = tid + 256*it;
            int row = f >> 2;
            int kq  = (f & 3) << 2;
            float4 av = *(const float4*)(A  + (m0+row)*768 + k0 + kq);
            As[kq+0][row]=av.x; As[kq+1][row]=av.y; As[kq+2][row]=av.z; As[kq+3][row]=av.w;
            float4 bv = *(const float4*)(Bm + (n0+row)*768 + k0 + kq);
            Bs[kq+0][row]=bv.x; Bs[kq+1][row]=bv.y; Bs[kq+2][row]=bv.z; Bs[kq+3][row]=bv.w;
        }
        __syncthreads();
        #pragma unroll
        for (int kk = 0; kk < 16; kk++) {
            float4 a0 = *(const float4*)(&As[kk][ty*8]);
            float4 a1 = *(const float4*)(&As[kk][ty*8+4]);
            float4 b0 = *(const float4*)(&Bs[kk][tx*8]);
            float4 b1 = *(const float4*)(&Bs[kk][tx*8+4]);
            u64 bb0 = pack2(b0.x, b0.y);
            u64 bb1 = pack2(b0.z, b0.w);
            u64 bb2 = pack2(b1.x, b1.y);
            u64 bb3 = pack2(b1.z, b1.w);
            float av[8] = {a0.x,a0.y,a0.z,a0.w,a1.x,a1.y,a1.z,a1.w};
            #pragma unroll
            for (int i = 0; i < 8; i++) {
                u64 aa = splat2(av[i]);
                fma2(acc[i][0], aa, bb0);
                fma2(acc[i][1], aa, bb1);
                fma2(acc[i][2], aa, bb2);
                fma2(acc[i][3], aa, bb3);
            }
        }
        __syncthreads();
    }
}

// ---- qkv GEMM: X[16384,768] x Wqkv[2304,768]^T, scatter into q/k/v [B*H,N,D]
__global__ __launch_bounds__(256) void gemm_qkv_kernel(
    const float* __restrict__ X, const float* __restrict__ W)
{
    __shared__ float As[16][132];
    __shared__ float Bs[16][132];
    int tid = threadIdx.x, tx = tid & 15, ty = tid >> 4;
    int m0 = blockIdx.y * 128, n0 = blockIdx.x * 128;

    u64 acc[8][4];
    #pragma unroll
    for (int i = 0; i < 8; i++)
        #pragma unroll
        for (int j = 0; j < 4; j++) acc[i][j] = 0ull;

    gemm_mainloop(X, W, m0, n0, tid, tx, ty, acc, As, Bs);

    // epilogue: e = n0+tx*8+j decomposes (t, h, d); 768|128-block boundaries -> constant per thread
    int e0    = n0 + tx*8;
    int t_sel = e0 / 768;
    int rr    = e0 - t_sel*768;
    int h     = rr >> 6;
    int d0    = rr & 63;
    float* dst = (t_sel == 0) ? g_q : ((t_sel == 1) ? g_k : g_v);
    #pragma unroll
    for (int i = 0; i < 8; i++) {
        int mrow = m0 + ty*8 + i;
        int b = mrow >> 10, n = mrow & 1023;
        float2 v0 = unpack2(acc[i][0]);
        float2 v1 = unpack2(acc[i][1]);
        float2 v2 = unpack2(acc[i][2]);
        float2 v3 = unpack2(acc[i][3]);
        float* base = dst + ((b*NHEADS + h)*NSEQ + n)*NHD + d0;
        *(float4*)(base)     = make_float4(v0.x, v0.y, v1.x, v1.y);
        *(float4*)(base + 4) = make_float4(v2.x, v2.y, v3.x, v3.y);
    }
}

// ---- proj GEMM: O[16384,768] x Wproj[768,768]^T + bias -> d_out
__global__ __launch_bounds__(256) void gemm_proj_kernel(
    const float* __restrict__ W, const float* __restrict__ bias, float* __restrict__ out)
{
    __shared__ float As[16][132];
    __shared__ float Bs[16][132];
    int tid = threadIdx.x, tx = tid & 15, ty = tid >> 4;
    int m0 = blockIdx.y * 128, n0 = blockIdx.x * 128;

    u64 acc[8][4];
    #pragma unroll
    for (int i = 0; i < 8; i++)
        #pragma unroll
        for (int j = 0; j < 4; j++) acc[i][j] = 0ull;

    gemm_mainloop(g_o, W, m0, n0, tid, tx, ty, acc, As, Bs);

    float4 bs0 = *(const float4*)(bias + n0 + tx*8);
    float4 bs1 = *(const float4*)(bias + n0 + tx*8 + 4);
    #pragma unroll
    for (int i = 0; i < 8; i++) {
        int mrow = m0 + ty*8 + i;
        float2 v0 = unpack2(acc[i][0]);
        float2 v1 = unpack2(acc[i][1]);
        float2 v2 = unpack2(acc[i][2]);
        float2 v3 = unpack2(acc[i][3]);
        float* base = out + mrow*768 + n0 + tx*8;
        *(float4*)(base)     = make_float4(v0.x+bs0.x, v0.y+bs0.y, v1.x+bs0.z, v1.y+bs0.w);
        *(float4*)(base + 4) = make_float4(v2.x+bs1.x, v2.y+bs1.y, v3.x+bs1.z, v3.y+bs1.w);
    }
}

// =====================================================================
// Flash attention, fp32, BQ=128, BKV=64, D=64. 256 threads (16x16),
// thread owns 8 q-rows x 4 kv-cols (S) / 4 d-cols (O).
// smem: Qs[d][r] (stride 132), Ks[d][c] (stride 68), Vs[c][d] (64), Ps[r][c] (64)
// =====================================================================
#define QS_STRIDE 132
#define KS_STRIDE 68
#define FLASH_SMEM_FLOATS (64*QS_STRIDE + 64*KS_STRIDE + 64*64 + 128*64)

__global__ __launch_bounds__(256, 2) void flash_kernel()
{
    extern __shared__ float sm[];
    float* Qs = sm;                       // [64][132]
    float* Ks = Qs + 64*QS_STRIDE;        // [64][68]
    float* Vs = Ks + 64*KS_STRIDE;        // [64][64]
    float* Ps = Vs + 64*64;               // [128][64]

    int tid = threadIdx.x, tx = tid & 15, ty = tid >> 4;
    int q0 = blockIdx.x * 128;
    int bh = blockIdx.y;
    const float* qg = g_q + bh*NSEQ*NHD;
    const float* kg = g_k + bh*NSEQ*NHD;
    const float* vg = g_v + bh*NSEQ*NHD;

    // load Q tile transposed+scaled: Qs[d][r]
    #pragma unroll
    for (int it = 0; it < 8; it++) {
        int f = tid + 256*it;
        int w = f >> 5, l = f & 31;
        int r = (w & 15)*8 + (l & 7);
        int g = (w >> 4)*4 + (l >> 3);
        float4 v = *(const float4*)(qg + (q0 + r)*NHD + g*4);
        Qs[(g*4+0)*QS_STRIDE + r] = v.x * ATT_SCALE;
        Qs[(g*4+1)*QS_STRIDE + r] = v.y * ATT_SCALE;
        Qs[(g*4+2)*QS_STRIDE + r] = v.z * ATT_SCALE;
        Qs[(g*4+3)*QS_STRIDE + r] = v.w * ATT_SCALE;
    }

    float m_i[8], l_i[8];
    u64 O2[8][2];
    #pragma unroll
    for (int i = 0; i < 8; i++) { m_i[i] = -1e30f; l_i[i] = 0.0f; O2[i][0] = 0ull; O2[i][1] = 0ull; }

    for (int t = 0; t < 16; t++) {
        int c0 = t * 64;
        __syncthreads();   // prev-iter smem reads done (also orders Qs stores before first use)
        // K tile transposed: Ks[d][c]
        #pragma unroll
        for (int it = 0; it < 4; it++) {
            int f = tid + 256*it;
            int w = f >> 5, l = f & 31;
            int c = (w & 7)*8 + (l & 7);
            int g = (w >> 3)*4 + (l >> 3);
            float4 v = *(const float4*)(kg + (c0 + c)*NHD + g*4);
            Ks[(g*4+0)*KS_STRIDE + c] = v.x;
            Ks[(g*4+1)*KS_STRIDE + c] = v.y;
            Ks[(g*4+2)*KS_STRIDE + c] = v.z;
            Ks[(g*4+3)*KS_STRIDE + c] = v.w;
        }
        // V tile natural: Vs[c][d]
        #pragma unroll
        for (int it = 0; it < 4; it++) {
            int f = tid + 256*it;
            int c = f >> 4, g = f & 15;
            *(float4*)(Vs + c*64 + g*4) = *(const float4*)(vg + (c0 + c)*NHD + g*4);
        }
        __syncthreads();

        // S = (Q*scale) K^T : s2[i][jp] packs cols (tx*4+2jp, +1)
        u64 s2[8][2];
        #pragma unroll
        for (int i = 0; i < 8; i++) { s2[i][0] = 0ull; s2[i][1] = 0ull; }
        #pragma unroll 4
        for (int kk = 0; kk < 64; kk++) {
            float4 a0 = *(const float4*)(Qs + kk*QS_STRIDE + ty*8);
            float4 a1 = *(const float4*)(Qs + kk*QS_STRIDE + ty*8 + 4);
            float4 b  = *(const float4*)(Ks + kk*KS_STRIDE + tx*4);
            u64 b01 = pack2(b.x, b.y);
            u64 b23 = pack2(b.z, b.w);
            float av[8] = {a0.x,a0.y,a0.z,a0.w,a1.x,a1.y,a1.z,a1.w};
            #pragma unroll
            for (int i = 0; i < 8; i++) {
                u64 aa = splat2(av[i]);
                fma2(s2[i][0], aa, b01);
                fma2(s2[i][1], aa, b23);
            }
        }

        // streaming softmax (row state replicated across the 16 tx lanes)
        #pragma unroll
        for (int i = 0; i < 8; i++) {
            float2 sA = unpack2(s2[i][0]);
            float2 sB = unpack2(s2[i][1]);
            float mx = fmaxf(fmaxf(sA.x, sA.y), fmaxf(sB.x, sB.y));
            #pragma unroll
            for (int off = 8; off >= 1; off >>= 1)
                mx = fmaxf(mx, __shfl_xor_sync(0xffffffffu, mx, off));
            float mnew = fmaxf(m_i[i], mx);
            float corr = fast_exp(m_i[i] - mnew);
            m_i[i] = mnew;
            float p0 = fast_exp(sA.x - mnew);
            float p1 = fast_exp(sA.y - mnew);
            float p2 = fast_exp(sB.x - mnew);
            float p3 = fast_exp(sB.y - mnew);
            float ps = (p0 + p1) + (p2 + p3);
            #pragma unroll
            for (int off = 8; off >= 1; off >>= 1)
                ps += __shfl_xor_sync(0xffffffffu, ps, off);
            l_i[i] = l_i[i]*corr + ps;
            u64 cc = splat2(corr);
            O2[i][0] = mul2(O2[i][0], cc);
            O2[i][1] = mul2(O2[i][1], cc);
            *(float4*)(Ps + (ty*8 + i)*64 + tx*4) = make_float4(p0, p1, p2, p3);
        }
        __syncthreads();

        // O += P V : per c-step, P reads are warp-broadcast, V is a contiguous row read
        #pragma unroll 2
        for (int c = 0; c < 64; c++) {
            float4 v = *(const float4*)(Vs + c*64 + tx*4);
            u64 v01 = pack2(v.x, v.y);
            u64 v23 = pack2(v.z, v.w);
            const float* pcol = Ps + ty*8*64 + c;
            #pragma unroll
            for (int i = 0; i < 8; i++) {
                u64 aa = splat2(pcol[i*64]);
                fma2(O2[i][0], aa, v01);
                fma2(O2[i][1], aa, v23);
            }
        }
    }

    // finalize: O /= l, write to g_o[b*N+n][h*64+d]
    int b = bh / NHEADS, h = bh % NHEADS;
    #pragma unroll
    for (int i = 0; i < 8; i++) {
        float inv = 1.0f / l_i[i];
        float2 o0 = unpack2(O2[i][0]);
        float2 o1 = unpack2(O2[i][1]);
        int r = q0 + ty*8 + i;
        *(float4*)(g_o + (b*NSEQ + r)*NDIM + h*NHD + tx*4) =
            make_float4(o0.x*inv, o0.y*inv, o1.x*inv, o1.y*inv);
    }
}

// =====================================================================
extern "C" void kernel_launch(void* const* d_in, const int* in_sizes, int n_in,
                              void* d_out, int out_size)
{
    const float* x      = (const float*)d_in[0];
    const float* w_qkv  = (const float*)d_in[1];
    const float* w_proj = (const float*)d_in[2];
    const float* b_proj = (const float*)d_in[3];
    float* out = (float*)d_out;

    cudaFuncSetAttribute(flash_kernel, cudaFuncAttributeMaxDynamicSharedMemorySize,
                         FLASH_SMEM_FLOATS * (int)sizeof(float));

    gemm_qkv_kernel<<<dim3(2304/128, 16384/128), 256>>>(x, w_qkv);
    flash_kernel<<<dim3(NSEQ/128, NBATCH*NHEADS), 256, FLASH_SMEM_FLOATS*(int)sizeof(float)>>>();
    gemm_proj_kernel<<<dim3(768/128, 16384/128), 256>>>(w_proj, b_proj, out);
}

// round 4
// speedup vs baseline: 1.2114x; 1.2114x over previous
#include <cuda_runtime.h>
#include <cuda_bf16.h>
#include <cstdint>

typedef unsigned long long u64;
typedef unsigned int u32;

#define NBATCH 16
#define NSEQ   1024
#define NDIM   768
#define NHEADS 12
#define NHD    64
#define ATT_SCALE 0.125f

// Scratch (static device globals: allocation-free per harness rules)
__device__ float g_q[NBATCH*NHEADS*NSEQ*NHD];   // [B*H, N, D]
__device__ float g_k[NBATCH*NHEADS*NSEQ*NHD];
__device__ float g_v[NBATCH*NHEADS*NSEQ*NHD];
__device__ float g_o[NBATCH*NSEQ*NDIM];         // [B*N, C]

// ---------- common helpers ----------
__device__ __forceinline__ u32 smem_u32(const void* p){
    u32 a; asm("{ .reg .u64 t; cvta.to.shared.u64 t, %1; cvt.u32.u64 %0, t; }" : "=r"(a) : "l"(p));
    return a;
}
__device__ __forceinline__ u64 pack2(float x, float y){
    u64 r; asm("mov.b64 %0, {%1, %2};" : "=l"(r) : "r"(__float_as_uint(x)), "r"(__float_as_uint(y))); return r;
}
__device__ __forceinline__ u64 splat2(float x){
    u64 r; asm("mov.b64 %0, {%1, %1};" : "=l"(r) : "r"(__float_as_uint(x))); return r;
}
__device__ __forceinline__ void fma2(u64& d, u64 a, u64 b){
    asm("fma.rn.f32x2 %0, %1, %2, %0;" : "+l"(d) : "l"(a), "l"(b));
}
__device__ __forceinline__ u64 mul2(u64 a, u64 b){
    u64 r; asm("mul.rn.f32x2 %0, %1, %2;" : "=l"(r) : "l"(a), "l"(b)); return r;
}
__device__ __forceinline__ float2 unpack2(u64 v){
    unsigned lo, hi; asm("mov.b64 {%0, %1}, %2;" : "=r"(lo), "=r"(hi) : "l"(v));
    return make_float2(__uint_as_float(lo), __uint_as_float(hi));
}

// fast exp on the FMA pipe (no MUFU), x <= ~0
__device__ __forceinline__ float fast_exp(float x){
    x = fmaxf(x, -80.0f);
    float t  = x * 1.4426950408889634f;
    float tr = t + 12582912.0f;
    int   n  = __float_as_int(tr) - 0x4B400000;
    float rn = tr - 12582912.0f;
    float f  = t - rn;
    float p = 1.3333558146428443e-3f;
    p = fmaf(p, f, 9.618129107628477e-3f);
    p = fmaf(p, f, 5.550410866482158e-2f);
    p = fmaf(p, f, 2.402265069591007e-1f);
    p = fmaf(p, f, 6.931471805599453e-1f);
    p = fmaf(p, f, 1.0f);
    return p * __int_as_float((n + 127) << 23);
}

// ---------- mma.sync tf32 + ldmatrix primitives (baseline PTX, sm_80+) ----------
__device__ __forceinline__ void ldsm4(u32* r, u32 addr){
    asm volatile("ldmatrix.sync.aligned.m8n8.x4.shared.b16 {%0,%1,%2,%3}, [%4];"
        : "=r"(r[0]), "=r"(r[1]), "=r"(r[2]), "=r"(r[3]) : "r"(addr));
}
__device__ __forceinline__ void mma_tf32(float* c, const u32* a, u32 b0, u32 b1){
    asm volatile("mma.sync.aligned.m16n8k8.row.col.f32.tf32.tf32.f32 "
        "{%0,%1,%2,%3}, {%4,%5,%6,%7}, {%8,%9}, {%0,%1,%2,%3};"
        : "+f"(c[0]), "+f"(c[1]), "+f"(c[2]), "+f"(c[3])
        : "r"(a[0]), "r"(a[1]), "r"(a[2]), "r"(a[3]), "r"(b0), "r"(b1));
}
// tf32x3 split: hi = rna(x), lo = rna(x - hi). Layout-preserving, in-register.
__device__ __forceinline__ void split_tf32(u32 x, u32& hi, u32& lo){
    float xf = __uint_as_float(x);
    asm("cvt.rna.tf32.f32 %0, %1;" : "=r"(hi) : "f"(xf));
    float d = xf - __uint_as_float(hi);
    asm("cvt.rna.tf32.f32 %0, %1;" : "=r"(lo) : "f"(d));
}
__device__ __forceinline__ void cp16(u32 dst, const void* src){
    asm volatile("cp.async.cg.shared.global [%0], [%1], 16;" :: "r"(dst), "l"(src));
}
__device__ __forceinline__ void cp_commit(){ asm volatile("cp.async.commit_group;" ::: "memory"); }
template<int N> __device__ __forceinline__ void cp_wait(){
    asm volatile("cp.async.wait_group %0;" :: "n"(N) : "memory");
}

// =====================================================================
// tf32x3 mma.sync GEMM: C[M, Ncols] = A[M,768] * B[Ncols,768]^T (+bias)
// Block tile 128x128, BK=16, 4-stage cp.async, 8 warps (4M x 2N),
// warp tile 32x64 via m16n8k8. Smem pitch 20 floats (conflict-free LDSM).
// Precision: per-fragment hi/lo split, C += ah*bh + al*bh + ah*bl.
// mode 0: scatter into g_q/g_k/g_v; mode 1: A=g_o, out = C + bias.
// =====================================================================
#define PITCH      20
#define A_FLOATS   (128*PITCH)                 // 2560 floats
#define STAGE_B    (2*A_FLOATS*4)              // A + B = 20480 bytes
#define GEMM_SMEM  (4*STAGE_B)                 // 81920 bytes

__global__ __launch_bounds__(256, 2) void mma_gemm_kernel(
    const float* __restrict__ Ag_in, const float* __restrict__ Bg,
    const float* __restrict__ bias, float* __restrict__ out, int mode)
{
    extern __shared__ float smf[];
    const float* Ag = (mode == 1) ? (const float*)g_o : Ag_in;

    int tid = threadIdx.x;
    int lane = tid & 31, warp = tid >> 5;
    int wm = warp & 3, wn = warp >> 2;            // 4 M-warps x 2 N-warps
    int m0 = blockIdx.y * 128, n0 = blockIdx.x * 128;

    u32 sbase = smem_u32(smf);

    // LDSM per-thread base offsets (bytes within a stage)
    int a_row = wm*32 + (lane & 7) + ((lane >> 3) & 1)*8;   // + fm*16
    int a_col = (lane >> 4)*4;
    int b_row = wn*64 + ((lane >> 4) & 1)*8 + (lane & 7);   // + np*16
    int b_col = ((lane >> 3) & 1)*4;
    u32 aoff = (u32)((a_row*PITCH + a_col)*4);
    u32 boff = (u32)(A_FLOATS*4 + (b_row*PITCH + b_col)*4);

    float c[2][8][4];
    #pragma unroll
    for (int i = 0; i < 2; i++)
        #pragma unroll
        for (int j = 0; j < 8; j++)
            #pragma unroll
            for (int q = 0; q < 4; q++) c[i][j][q] = 0.0f;

    auto load_chunk = [&](int chunk){
        int st = chunk & 3;
        u32 stb = sbase + st*STAGE_B;
        int kf = chunk*16;
        #pragma unroll
        for (int it = 0; it < 2; it++){
            int f = tid + 256*it;
            int row = f >> 2, cu = f & 3;
            cp16(stb + row*(PITCH*4) + cu*16,
                 Ag + (size_t)(m0 + row)*768 + kf + cu*4);
            cp16(stb + (u32)(A_FLOATS*4) + row*(PITCH*4) + cu*16,
                 Bg + (size_t)(n0 + row)*768 + kf + cu*4);
        }
        cp_commit();
    };

    load_chunk(0); load_chunk(1); load_chunk(2);

    #pragma unroll 1
    for (int i = 0; i < 48; i++){
        if (i < 46)       cp_wait<2>();
        else if (i == 46) cp_wait<1>();
        else              cp_wait<0>();
        __syncthreads();

        u32 stb = sbase + (i & 3)*STAGE_B;
        #pragma unroll
        for (int s = 0; s < 2; s++){
            u32 kb = (u32)(s*32);                 // 8 floats
            // A fragments + split
            u32 ah[2][4], al[2][4];
            #pragma unroll
            for (int fm = 0; fm < 2; fm++){
                u32 aA[4];
                ldsm4(aA, stb + aoff + fm*(16*PITCH*4) + kb);
                #pragma unroll
                for (int j = 0; j < 4; j++) split_tf32(aA[j], ah[fm][j], al[fm][j]);
            }
            // B fragments per np + split, then 3 MMAs per (fm, n-half)
            #pragma unroll
            for (int np = 0; np < 4; np++){
                u32 bB[4];
                ldsm4(bB, stb + boff + np*(16*PITCH*4) + kb);
                u32 bh[4], bl[4];
                #pragma unroll
                for (int j = 0; j < 4; j++) split_tf32(bB[j], bh[j], bl[j]);
                #pragma unroll
                for (int fm = 0; fm < 2; fm++){
                    mma_tf32(c[fm][2*np+0], ah[fm], bh[0], bh[1]);
                    mma_tf32(c[fm][2*np+0], al[fm], bh[0], bh[1]);
                    mma_tf32(c[fm][2*np+0], ah[fm], bl[0], bl[1]);
                    mma_tf32(c[fm][2*np+1], ah[fm], bh[2], bh[3]);
                    mma_tf32(c[fm][2*np+1], al[fm], bh[2], bh[3]);
                    mma_tf32(c[fm][2*np+1], ah[fm], bl[2], bl[3]);
                }
            }
        }

        if (i + 3 < 48) load_chunk(i + 3);
    }

    // ---------------- epilogue ----------------
    int g = lane >> 2, tig = lane & 3;
    int colbase = n0 + wn*64;                     // 64-aligned
    if (mode == 0){
        int hblk = colbase >> 6;                  // 0..35
        int t_sel = hblk / NHEADS;
        int h     = hblk - t_sel*NHEADS;
        float* dp = (t_sel == 0) ? g_q : ((t_sel == 1) ? g_k : g_v);
        #pragma unroll
        for (int fm = 0; fm < 2; fm++){
            int row0 = m0 + wm*32 + fm*16 + g;
            #pragma unroll
            for (int half = 0; half < 2; half++){
                int row = row0 + half*8;
                int b = row >> 10, n = row & 1023;
                float* base = dp + ((size_t)((b*NHEADS + h)*NSEQ + n))*NHD;
                #pragma unroll
                for (int nf = 0; nf < 8; nf++){
                    int d0 = nf*8 + tig*2;
                    *(float2*)(base + d0) =
                        make_float2(c[fm][nf][half*2], c[fm][nf][half*2+1]);
                }
            }
        }
    } else {
        #pragma unroll
        for (int fm = 0; fm < 2; fm++){
            int row0 = m0 + wm*32 + fm*16 + g;
            #pragma unroll
            for (int half = 0; half < 2; half++){
                int row = row0 + half*8;
                float* base = out + (size_t)row*768 + colbase;
                #pragma unroll
                for (int nf = 0; nf < 8; nf++){
                    int cg = nf*8 + tig*2;
                    float2 bv = *(const float2*)(bias + colbase + cg);
                    *(float2*)(base + cg) =
                        make_float2(c[fm][nf][half*2] + bv.x,
                                    c[fm][nf][half*2+1] + bv.y);
                }
            }
        }
    }
}

// =====================================================================
// Flash attention, fp32, BQ=128, BKV=64, D=64 (unchanged from R1)
// =====================================================================
#define QS_STRIDE 132
#define KS_STRIDE 68
#define FLASH_SMEM_FLOATS (64*QS_STRIDE + 64*KS_STRIDE + 64*64 + 128*64)

__global__ __launch_bounds__(256, 2) void flash_kernel()
{
    extern __shared__ float fsm[];
    float* Qs = fsm;
    float* Ks = Qs + 64*QS_STRIDE;
    float* Vs = Ks + 64*KS_STRIDE;
    float* Ps = Vs + 64*64;

    int tid = threadIdx.x, tx = tid & 15, ty = tid >> 4;
    int q0 = blockIdx.x * 128;
    int bh = blockIdx.y;
    const float* qg = g_q + (size_t)bh*NSEQ*NHD;
    const float* kg = g_k + (size_t)bh*NSEQ*NHD;
    const float* vg = g_v + (size_t)bh*NSEQ*NHD;

    #pragma unroll
    for (int it = 0; it < 8; it++) {
        int f = tid + 256*it;
        int w = f >> 5, l = f & 31;
        int r = (w & 15)*8 + (l & 7);
        int g = (w >> 4)*4 + (l >> 3);
        float4 v = *(const float4*)(qg + (q0 + r)*NHD + g*4);
        Qs[(g*4+0)*QS_STRIDE + r] = v.x * ATT_SCALE;
        Qs[(g*4+1)*QS_STRIDE + r] = v.y * ATT_SCALE;
        Qs[(g*4+2)*QS_STRIDE + r] = v.z * ATT_SCALE;
        Qs[(g*4+3)*QS_STRIDE + r] = v.w * ATT_SCALE;
    }

    float m_i[8], l_i[8];
    u64 O2[8][2];
    #pragma unroll
    for (int i = 0; i < 8; i++) { m_i[i] = -1e30f; l_i[i] = 0.0f; O2[i][0] = 0ull; O2[i][1] = 0ull; }

    for (int t = 0; t < 16; t++) {
        int c0 = t * 64;
        __syncthreads();
        #pragma unroll
        for (int it = 0; it < 4; it++) {
            int f = tid + 256*it;
            int w = f >> 5, l = f & 31;
            int cc = (w & 7)*8 + (l & 7);
            int g = (w >> 3)*4 + (l >> 3);
            float4 v = *(const float4*)(kg + (c0 + cc)*NHD + g*4);
            Ks[(g*4+0)*KS_STRIDE + cc] = v.x;
            Ks[(g*4+1)*KS_STRIDE + cc] = v.y;
            Ks[(g*4+2)*KS_STRIDE + cc] = v.z;
            Ks[(g*4+3)*KS_STRIDE + cc] = v.w;
        }
        #pragma unroll
        for (int it = 0; it < 4; it++) {
            int f = tid + 256*it;
            int cc = f >> 4, g = f & 15;
            *(float4*)(Vs + cc*64 + g*4) = *(const float4*)(vg + (c0 + cc)*NHD + g*4);
        }
        __syncthreads();

        u64 s2[8][2];
        #pragma unroll
        for (int i = 0; i < 8; i++) { s2[i][0] = 0ull; s2[i][1] = 0ull; }
        #pragma unroll 4
        for (int kk = 0; kk < 64; kk++) {
            float4 a0 = *(const float4*)(Qs + kk*QS_STRIDE + ty*8);
            float4 a1 = *(const float4*)(Qs + kk*QS_STRIDE + ty*8 + 4);
            float4 b  = *(const float4*)(Ks + kk*KS_STRIDE + tx*4);
            u64 b01 = pack2(b.x, b.y);
            u64 b23 = pack2(b.z, b.w);
            float av[8] = {a0.x,a0.y,a0.z,a0.w,a1.x,a1.y,a1.z,a1.w};
            #pragma unroll
            for (int i = 0; i < 8; i++) {
                u64 aa = splat2(av[i]);
                fma2(s2[i][0], aa, b01);
                fma2(s2[i][1], aa, b23);
            }
        }

        #pragma unroll
        for (int i = 0; i < 8; i++) {
            float2 sA = unpack2(s2[i][0]);
            float2 sB = unpack2(s2[i][1]);
            float mx = fmaxf(fmaxf(sA.x, sA.y), fmaxf(sB.x, sB.y));
            #pragma unroll
            for (int off = 8; off >= 1; off >>= 1)
                mx = fmaxf(mx, __shfl_xor_sync(0xffffffffu, mx, off));
            float mnew = fmaxf(m_i[i], mx);
            float corr = fast_exp(m_i[i] - mnew);
            m_i[i] = mnew;
            float p0 = fast_exp(sA.x - mnew);
            float p1 = fast_exp(sA.y - mnew);
            float p2 = fast_exp(sB.x - mnew);
            float p3 = fast_exp(sB.y - mnew);
            float ps = (p0 + p1) + (p2 + p3);
            #pragma unroll
            for (int off = 8; off >= 1; off >>= 1)
                ps += __shfl_xor_sync(0xffffffffu, ps, off);
            l_i[i] = l_i[i]*corr + ps;
            u64 cc = splat2(corr);
            O2[i][0] = mul2(O2[i][0], cc);
            O2[i][1] = mul2(O2[i][1], cc);
            *(float4*)(Ps + (ty*8 + i)*64 + tx*4) = make_float4(p0, p1, p2, p3);
        }
        __syncthreads();

        #pragma unroll 2
        for (int cc = 0; cc < 64; cc++) {
            float4 v = *(const float4*)(Vs + cc*64 + tx*4);
            u64 v01 = pack2(v.x, v.y);
            u64 v23 = pack2(v.z, v.w);
            const float* pcol = Ps + ty*8*64 + cc;
            #pragma unroll
            for (int i = 0; i < 8; i++) {
                u64 aa = splat2(pcol[i*64]);
                fma2(O2[i][0], aa, v01);
                fma2(O2[i][1], aa, v23);
            }
        }
    }

    int b = bh / NHEADS, h = bh % NHEADS;
    #pragma unroll
    for (int i = 0; i < 8; i++) {
        float inv = 1.0f / l_i[i];
        float2 o0 = unpack2(O2[i][0]);
        float2 o1 = unpack2(O2[i][1]);
        int r = q0 + ty*8 + i;
        *(float4*)(g_o + (size_t)(b*NSEQ + r)*NDIM + h*NHD + tx*4) =
            make_float4(o0.x*inv, o0.y*inv, o1.x*inv, o1.y*inv);
    }
}

// =====================================================================
extern "C" void kernel_launch(void* const* d_in, const int* in_sizes, int n_in,
                              void* d_out, int out_size)
{
    const float* x      = (const float*)d_in[0];
    const float* w_qkv  = (const float*)d_in[1];
    const float* w_proj = (const float*)d_in[2];
    const float* b_proj = (const float*)d_in[3];
    float* out = (float*)d_out;

    cudaFuncSetAttribute(mma_gemm_kernel, cudaFuncAttributeMaxDynamicSharedMemorySize, GEMM_SMEM);
    cudaFuncSetAttribute(flash_kernel, cudaFuncAttributeMaxDynamicSharedMemorySize,
                         FLASH_SMEM_FLOATS * (int)sizeof(float));

    // qkv: [16384,768] x [2304,768]^T -> scatter q/k/v
    mma_gemm_kernel<<<dim3(2304/128, 16384/128), 256, GEMM_SMEM>>>(x, w_qkv, nullptr, nullptr, 0);
    // attention
    flash_kernel<<<dim3(NSEQ/128, NBATCH*NHEADS), 256, FLASH_SMEM_FLOATS*(int)sizeof(float)>>>();
    // proj: g_o[16384,768] x [768,768]^T + bias -> out
    mma_gemm_kernel<<<dim3(768/128, 16384/128), 256, GEMM_SMEM>>>(nullptr, w_proj, b_proj, out, 1);
}

// round 5
// speedup vs baseline: 1.3209x; 1.0904x over previous
#include <cuda_runtime.h>
#include <cuda_bf16.h>
#include <cstdint>

typedef unsigned long long u64;
typedef unsigned int u32;

#define NBATCH 16
#define NSEQ   1024
#define NDIM   768
#define NHEADS 12
#define NHD    64
#define ATT_SCALE 0.125f

// Scratch (static device globals: allocation-free per harness rules)
__device__ float g_q[NBATCH*NHEADS*NSEQ*NHD];   // [B*H, N, D]
__device__ float g_k[NBATCH*NHEADS*NSEQ*NHD];
__device__ float g_v[NBATCH*NHEADS*NSEQ*NHD];
__device__ float g_o[NBATCH*NSEQ*NDIM];         // [B*N, C]

// ---------- common helpers ----------
__device__ __forceinline__ u32 smem_u32(const void* p){
    u32 a; asm("{ .reg .u64 t; cvta.to.shared.u64 t, %1; cvt.u32.u64 %0, t; }" : "=r"(a) : "l"(p));
    return a;
}

// fast exp on the FMA pipe (no MUFU), x <= ~0
__device__ __forceinline__ float fast_exp(float x){
    x = fmaxf(x, -80.0f);
    float t  = x * 1.4426950408889634f;
    float tr = t + 12582912.0f;
    int   n  = __float_as_int(tr) - 0x4B400000;
    float rn = tr - 12582912.0f;
    float f  = t - rn;
    float p = 1.3333558146428443e-3f;
    p = fmaf(p, f, 9.618129107628477e-3f);
    p = fmaf(p, f, 5.550410866482158e-2f);
    p = fmaf(p, f, 2.402265069591007e-1f);
    p = fmaf(p, f, 6.931471805599453e-1f);
    p = fmaf(p, f, 1.0f);
    return p * __int_as_float((n + 127) << 23);
}

// ---------- mma.sync tf32 + ldmatrix primitives (baseline PTX, sm_80+) ----------
__device__ __forceinline__ void ldsm4(u32* r, u32 addr){
    asm volatile("ldmatrix.sync.aligned.m8n8.x4.shared.b16 {%0,%1,%2,%3}, [%4];"
        : "=r"(r[0]), "=r"(r[1]), "=r"(r[2]), "=r"(r[3]) : "r"(addr));
}
__device__ __forceinline__ void mma_tf32(float* c, const u32* a, u32 b0, u32 b1){
    asm volatile("mma.sync.aligned.m16n8k8.row.col.f32.tf32.tf32.f32 "
        "{%0,%1,%2,%3}, {%4,%5,%6,%7}, {%8,%9}, {%0,%1,%2,%3};"
        : "+f"(c[0]), "+f"(c[1]), "+f"(c[2]), "+f"(c[3])
        : "r"(a[0]), "r"(a[1]), "r"(a[2]), "r"(a[3]), "r"(b0), "r"(b1));
}
// tf32x3 split: hi = rna(x), lo = rna(x - hi). Layout-preserving, in-register.
__device__ __forceinline__ void split_tf32(u32 x, u32& hi, u32& lo){
    float xf = __uint_as_float(x);
    asm("cvt.rna.tf32.f32 %0, %1;" : "=r"(hi) : "f"(xf));
    float d = xf - __uint_as_float(hi);
    asm("cvt.rna.tf32.f32 %0, %1;" : "=r"(lo) : "f"(d));
}
__device__ __forceinline__ void cp16(u32 dst, const void* src){
    asm volatile("cp.async.cg.shared.global [%0], [%1], 16;" :: "r"(dst), "l"(src));
}
__device__ __forceinline__ void cp_commit(){ asm volatile("cp.async.commit_group;" ::: "memory"); }
template<int N> __device__ __forceinline__ void cp_wait(){
    asm volatile("cp.async.wait_group %0;" :: "n"(N) : "memory");
}

// =====================================================================
// tf32x3 mma.sync GEMM (unchanged from R4, verified)
// =====================================================================
#define PITCH      20
#define A_FLOATS   (128*PITCH)
#define STAGE_B    (2*A_FLOATS*4)
#define GEMM_SMEM  (4*STAGE_B)

__global__ __launch_bounds__(256, 2) void mma_gemm_kernel(
    const float* __restrict__ Ag_in, const float* __restrict__ Bg,
    const float* __restrict__ bias, float* __restrict__ out, int mode)
{
    extern __shared__ float smf[];
    const float* Ag = (mode == 1) ? (const float*)g_o : Ag_in;

    int tid = threadIdx.x;
    int lane = tid & 31, warp = tid >> 5;
    int wm = warp & 3, wn = warp >> 2;
    int m0 = blockIdx.y * 128, n0 = blockIdx.x * 128;

    u32 sbase = smem_u32(smf);

    int a_row = wm*32 + (lane & 7) + ((lane >> 3) & 1)*8;
    int a_col = (lane >> 4)*4;
    int b_row = wn*64 + ((lane >> 4) & 1)*8 + (lane & 7);
    int b_col = ((lane >> 3) & 1)*4;
    u32 aoff = (u32)((a_row*PITCH + a_col)*4);
    u32 boff = (u32)(A_FLOATS*4 + (b_row*PITCH + b_col)*4);

    float c[2][8][4];
    #pragma unroll
    for (int i = 0; i < 2; i++)
        #pragma unroll
        for (int j = 0; j < 8; j++)
            #pragma unroll
            for (int q = 0; q < 4; q++) c[i][j][q] = 0.0f;

    auto load_chunk = [&](int chunk){
        int st = chunk & 3;
        u32 stb = sbase + st*STAGE_B;
        int kf = chunk*16;
        #pragma unroll
        for (int it = 0; it < 2; it++){
            int f = tid + 256*it;
            int row = f >> 2, cu = f & 3;
            cp16(stb + row*(PITCH*4) + cu*16,
                 Ag + (size_t)(m0 + row)*768 + kf + cu*4);
            cp16(stb + (u32)(A_FLOATS*4) + row*(PITCH*4) + cu*16,
                 Bg + (size_t)(n0 + row)*768 + kf + cu*4);
        }
        cp_commit();
    };

    load_chunk(0); load_chunk(1); load_chunk(2);

    #pragma unroll 1
    for (int i = 0; i < 48; i++){
        if (i < 46)       cp_wait<2>();
        else if (i == 46) cp_wait<1>();
        else              cp_wait<0>();
        __syncthreads();

        u32 stb = sbase + (i & 3)*STAGE_B;
        #pragma unroll
        for (int s = 0; s < 2; s++){
            u32 kb = (u32)(s*32);
            u32 ah[2][4], al[2][4];
            #pragma unroll
            for (int fm = 0; fm < 2; fm++){
                u32 aA[4];
                ldsm4(aA, stb + aoff + fm*(16*PITCH*4) + kb);
                #pragma unroll
                for (int j = 0; j < 4; j++) split_tf32(aA[j], ah[fm][j], al[fm][j]);
            }
            #pragma unroll
            for (int np = 0; np < 4; np++){
                u32 bB[4];
                ldsm4(bB, stb + boff + np*(16*PITCH*4) + kb);
                u32 bh[4], bl[4];
                #pragma unroll
                for (int j = 0; j < 4; j++) split_tf32(bB[j], bh[j], bl[j]);
                #pragma unroll
                for (int fm = 0; fm < 2; fm++){
                    mma_tf32(c[fm][2*np+0], ah[fm], bh[0], bh[1]);
                    mma_tf32(c[fm][2*np+0], al[fm], bh[0], bh[1]);
                    mma_tf32(c[fm][2*np+0], ah[fm], bl[0], bl[1]);
                    mma_tf32(c[fm][2*np+1], ah[fm], bh[2], bh[3]);
                    mma_tf32(c[fm][2*np+1], al[fm], bh[2], bh[3]);
                    mma_tf32(c[fm][2*np+1], ah[fm], bl[2], bl[3]);
                }
            }
        }

        if (i + 3 < 48) load_chunk(i + 3);
    }

    int g = lane >> 2, tig = lane & 3;
    int colbase = n0 + wn*64;
    if (mode == 0){
        int hblk = colbase >> 6;
        int t_sel = hblk / NHEADS;
        int h     = hblk - t_sel*NHEADS;
        float* dp = (t_sel == 0) ? g_q : ((t_sel == 1) ? g_k : g_v);
        #pragma unroll
        for (int fm = 0; fm < 2; fm++){
            int row0 = m0 + wm*32 + fm*16 + g;
            #pragma unroll
            for (int half = 0; half < 2; half++){
                int row = row0 + half*8;
                int b = row >> 10, n = row & 1023;
                float* base = dp + ((size_t)((b*NHEADS + h)*NSEQ + n))*NHD;
                #pragma unroll
                for (int nf = 0; nf < 8; nf++){
                    int d0 = nf*8 + tig*2;
                    *(float2*)(base + d0) =
                        make_float2(c[fm][nf][half*2], c[fm][nf][half*2+1]);
                }
            }
        }
    } else {
        #pragma unroll
        for (int fm = 0; fm < 2; fm++){
            int row0 = m0 + wm*32 + fm*16 + g;
            #pragma unroll
            for (int half = 0; half < 2; half++){
                int row = row0 + half*8;
                float* base = out + (size_t)row*768 + colbase;
                #pragma unroll
                for (int nf = 0; nf < 8; nf++){
                    int cg = nf*8 + tig*2;
                    float2 bv = *(const float2*)(bias + colbase + cg);
                    *(float2*)(base + cg) =
                        make_float2(c[fm][nf][half*2] + bv.x,
                                    c[fm][nf][half*2+1] + bv.y);
                }
            }
        }
    }
}

// =====================================================================
// Flash attention via mma.sync tf32x3.
// BQ=128 (8 warps x m16), BKV=64, D=64.
// Smem tiles, pitch FP=68 floats (68 mod 32 = 4 -> conflict-free ldsm):
//   Qs[128][FP]  q rows, d cols (pre-scaled)
//   Ks[64][FP]   kv rows, d cols (K natural; B operand of QK^T)
//   Vs[64][FP]   d rows, kv cols (V transposed; B operand of PV)
//   Ps[128][FP]  q rows, kv cols (P round-trip; A operand of PV)
// Softmax on C fragments with quad-lane shfl reductions.
// =====================================================================
#define FP 68
#define FLASH_SMEM_B ((128 + 64 + 64 + 128) * FP * 4)   // 104448 bytes

__global__ __launch_bounds__(256, 2) void flash_mma_kernel()
{
    extern __shared__ float fsm[];
    float* Qs = fsm;
    float* Ks = Qs + 128*FP;
    float* Vs = Ks + 64*FP;
    float* Ps = Vs + 64*FP;

    int tid = threadIdx.x, lane = tid & 31, warp = tid >> 5;
    int q0 = blockIdx.x * 128;
    int bh = blockIdx.y;
    const float* qg = g_q + (size_t)bh*NSEQ*NHD;
    const float* kg = g_k + (size_t)bh*NSEQ*NHD;
    const float* vg = g_v + (size_t)bh*NSEQ*NHD;

    u32 qb = smem_u32(Qs), kb = smem_u32(Ks), vb = smem_u32(Vs), pb = smem_u32(Ps);

    // ldsm per-thread offsets (verified recipe from GEMM)
    int a_row = warp*16 + (lane & 7) + ((lane >> 3) & 1)*8;
    int a_col = (lane >> 4)*4;
    u32 aoff = (u32)((a_row*FP + a_col)*4);
    int b_row = ((lane >> 4) & 1)*8 + (lane & 7);
    int b_col = ((lane >> 3) & 1)*4;
    u32 boff = (u32)((b_row*FP + b_col)*4);

    // load Q natural [q][d], pre-scaled
    #pragma unroll
    for (int it = 0; it < 8; it++){
        int f = tid + 256*it;
        int row = f >> 4, g = f & 15;
        float4 v = *(const float4*)(qg + (size_t)(q0 + row)*NHD + g*4);
        *(float4*)(Qs + row*FP + g*4) = make_float4(
            v.x*ATT_SCALE, v.y*ATT_SCALE, v.z*ATT_SCALE, v.w*ATT_SCALE);
    }

    float o[8][4];
    #pragma unroll
    for (int j = 0; j < 8; j++)
        #pragma unroll
        for (int q = 0; q < 4; q++) o[j][q] = 0.0f;
    float m0f = -1e30f, m1f = -1e30f, l0 = 0.0f, l1 = 0.0f;

    #pragma unroll 1
    for (int t = 0; t < 16; t++){
        int c0 = t * 64;
        __syncthreads();   // all PV reads of Ks/Vs from prev iter done
        // K natural [kv][d]
        #pragma unroll
        for (int it = 0; it < 4; it++){
            int f = tid + 256*it;
            int row = f >> 4, g = f & 15;
            *(float4*)(Ks + row*FP + g*4) =
                *(const float4*)(kg + (size_t)(c0 + row)*NHD + g*4);
        }
        // V transposed [d][kv]
        #pragma unroll
        for (int it = 0; it < 4; it++){
            int f = tid + 256*it;
            int row = f >> 4, g = f & 15;
            float4 v = *(const float4*)(vg + (size_t)(c0 + row)*NHD + g*4);
            Vs[(g*4+0)*FP + row] = v.x;
            Vs[(g*4+1)*FP + row] = v.y;
            Vs[(g*4+2)*FP + row] = v.z;
            Vs[(g*4+3)*FP + row] = v.w;
        }
        __syncthreads();

        // ---- S = Q K^T (tf32x3) ----
        float s[8][4];
        #pragma unroll
        for (int j = 0; j < 8; j++)
            #pragma unroll
            for (int q = 0; q < 4; q++) s[j][q] = 0.0f;

        #pragma unroll
        for (int kc = 0; kc < 8; kc++){
            u32 aA[4], ah[4], al[4];
            ldsm4(aA, qb + aoff + kc*32);
            #pragma unroll
            for (int j = 0; j < 4; j++) split_tf32(aA[j], ah[j], al[j]);
            #pragma unroll
            for (int np = 0; np < 4; np++){
                u32 bB[4], bh[4], bl[4];
                ldsm4(bB, kb + boff + np*(16*FP*4) + kc*32);
                #pragma unroll
                for (int j = 0; j < 4; j++) split_tf32(bB[j], bh[j], bl[j]);
                mma_tf32(s[2*np+0], ah, bh[0], bh[1]);
                mma_tf32(s[2*np+0], al, bh[0], bh[1]);
                mma_tf32(s[2*np+0], ah, bl[0], bl[1]);
                mma_tf32(s[2*np+1], ah, bh[2], bh[3]);
                mma_tf32(s[2*np+1], al, bh[2], bh[3]);
                mma_tf32(s[2*np+1], ah, bl[2], bl[3]);
            }
        }

        // ---- streaming softmax on C fragments ----
        // thread rows: r0 = lane>>2, r1 = r0+8 (warp-local)
        float mx0 = -1e30f, mx1 = -1e30f;
        #pragma unroll
        for (int j = 0; j < 8; j++){
            mx0 = fmaxf(mx0, fmaxf(s[j][0], s[j][1]));
            mx1 = fmaxf(mx1, fmaxf(s[j][2], s[j][3]));
        }
        #pragma unroll
        for (int off = 1; off <= 2; off <<= 1){
            mx0 = fmaxf(mx0, __shfl_xor_sync(0xffffffffu, mx0, off));
            mx1 = fmaxf(mx1, __shfl_xor_sync(0xffffffffu, mx1, off));
        }
        float mn0 = fmaxf(m0f, mx0), mn1 = fmaxf(m1f, mx1);
        float corr0 = fast_exp(m0f - mn0), corr1 = fast_exp(m1f - mn1);
        m0f = mn0; m1f = mn1;

        int r0 = lane >> 2;
        int colq = 2*(lane & 3);
        float sum0 = 0.0f, sum1 = 0.0f;
        #pragma unroll
        for (int j = 0; j < 8; j++){
            float p00 = fast_exp(s[j][0] - mn0);
            float p01 = fast_exp(s[j][1] - mn0);
            float p10 = fast_exp(s[j][2] - mn1);
            float p11 = fast_exp(s[j][3] - mn1);
            sum0 += p00 + p01;
            sum1 += p10 + p11;
            *(float2*)(Ps + (warp*16 + r0    )*FP + colq + 8*j) = make_float2(p00, p01);
            *(float2*)(Ps + (warp*16 + r0 + 8)*FP + colq + 8*j) = make_float2(p10, p11);
        }
        #pragma unroll
        for (int off = 1; off <= 2; off <<= 1){
            sum0 += __shfl_xor_sync(0xffffffffu, sum0, off);
            sum1 += __shfl_xor_sync(0xffffffffu, sum1, off);
        }
        l0 = l0*corr0 + sum0;
        l1 = l1*corr1 + sum1;
        #pragma unroll
        for (int j = 0; j < 8; j++){
            o[j][0] *= corr0; o[j][1] *= corr0;
            o[j][2] *= corr1; o[j][3] *= corr1;
        }
        __syncwarp();   // P stores visible to own warp's ldsm

        // ---- O += P V (tf32x3) ----
        #pragma unroll
        for (int kc = 0; kc < 8; kc++){
            u32 aA[4], ah[4], al[4];
            ldsm4(aA, pb + aoff + kc*32);
            #pragma unroll
            for (int j = 0; j < 4; j++) split_tf32(aA[j], ah[j], al[j]);
            #pragma unroll
            for (int np = 0; np < 4; np++){
                u32 bB[4], bh[4], bl[4];
                ldsm4(bB, vb + boff + np*(16*FP*4) + kc*32);
                #pragma unroll
                for (int j = 0; j < 4; j++) split_tf32(bB[j], bh[j], bl[j]);
                mma_tf32(o[2*np+0], ah, bh[0], bh[1]);
                mma_tf32(o[2*np+0], al, bh[0], bh[1]);
                mma_tf32(o[2*np+0], ah, bl[0], bl[1]);
                mma_tf32(o[2*np+1], ah, bh[2], bh[3]);
                mma_tf32(o[2*np+1], al, bh[2], bh[3]);
                mma_tf32(o[2*np+1], ah, bl[2], bl[3]);
            }
        }
    }

    // ---- finalize: O /= l, write g_o[b*N+n][h*64+d] ----
    int b = bh / NHEADS, h = bh % NHEADS;
    float inv0 = 1.0f / l0, inv1 = 1.0f / l1;
    int r0 = lane >> 2, colq = 2*(lane & 3);
    int gq0 = q0 + warp*16 + r0;
    float* base0 = g_o + (size_t)(b*NSEQ + gq0    )*NDIM + h*NHD;
    float* base1 = g_o + (size_t)(b*NSEQ + gq0 + 8)*NDIM + h*NHD;
    #pragma unroll
    for (int j = 0; j < 8; j++){
        int d0 = 8*j + colq;
        *(float2*)(base0 + d0) = make_float2(o[j][0]*inv0, o[j][1]*inv0);
        *(float2*)(base1 + d0) = make_float2(o[j][2]*inv1, o[j][3]*inv1);
    }
}

// =====================================================================
extern "C" void kernel_launch(void* const* d_in, const int* in_sizes, int n_in,
                              void* d_out, int out_size)
{
    const float* x      = (const float*)d_in[0];
    const float* w_qkv  = (const float*)d_in[1];
    const float* w_proj = (const float*)d_in[2];
    const float* b_proj = (const float*)d_in[3];
    float* out = (float*)d_out;

    cudaFuncSetAttribute(mma_gemm_kernel, cudaFuncAttributeMaxDynamicSharedMemorySize, GEMM_SMEM);
    cudaFuncSetAttribute(flash_mma_kernel, cudaFuncAttributeMaxDynamicSharedMemorySize, FLASH_SMEM_B);

    // qkv: [16384,768] x [2304,768]^T -> scatter q/k/v
    mma_gemm_kernel<<<dim3(2304/128, 16384/128), 256, GEMM_SMEM>>>(x, w_qkv, nullptr, nullptr, 0);
    // attention (tensorized flash)
    flash_mma_kernel<<<dim3(NSEQ/128, NBATCH*NHEADS), 256, FLASH_SMEM_B>>>();
    // proj: g_o[16384,768] x [768,768]^T + bias -> out
    mma_gemm_kernel<<<dim3(768/128, 16384/128), 256, GEMM_SMEM>>>(nullptr, w_proj, b_proj, out, 1);
}

// round 6
// speedup vs baseline: 2.2605x; 1.7113x over previous
#include <cuda_runtime.h>
#include <cuda_bf16.h>
#include <cstdint>

typedef unsigned long long u64;
typedef unsigned int u32;

#define NBATCH 16
#define NSEQ   1024
#define NDIM   768
#define NHEADS 12
#define NHD    64
#define ATT_SCALE 0.125f
#define QKV_ELEMS (NBATCH*NHEADS*NSEQ*NHD)    // 12582912
#define X_ELEMS   (NBATCH*NSEQ*NDIM)          // 12582912

// ---------------- static scratch (allocation-free) ----------------
__device__ __nv_bfloat16 g_xhi[X_ELEMS], g_xlo[X_ELEMS];
__device__ __nv_bfloat16 g_wqh[2304*768], g_wql[2304*768];
__device__ __nv_bfloat16 g_wph[768*768],  g_wpl[768*768];
__device__ __nv_bfloat16 g_qhi[QKV_ELEMS], g_qlo[QKV_ELEMS];   // [B*H, N, D], pre-scaled
__device__ __nv_bfloat16 g_khi[QKV_ELEMS], g_klo[QKV_ELEMS];
__device__ float         g_v[QKV_ELEMS];
__device__ __nv_bfloat16 g_ohi[X_ELEMS], g_olo[X_ELEMS];       // [B*N, C]

// ---------------- helpers ----------------
__device__ __forceinline__ u32 smem_u32(const void* p){
    u32 a; asm("{ .reg .u64 t; cvta.to.shared.u64 t, %1; cvt.u32.u64 %0, t; }" : "=r"(a) : "l"(p));
    return a;
}
__device__ __forceinline__ u32 bfpair(__nv_bfloat16 a, __nv_bfloat16 b){
    u32 lo = (u32)__bfloat16_as_ushort(a);
    u32 hi = (u32)__bfloat16_as_ushort(b);
    return lo | (hi << 16);
}
__device__ __forceinline__ void split1(float x, __nv_bfloat16& h, __nv_bfloat16& l){
    h = __float2bfloat16(x);
    l = __float2bfloat16(x - __bfloat162float(h));
}

// fast exp on the FMA pipe (no MUFU), x <= ~0
__device__ __forceinline__ float fast_exp(float x){
    x = fmaxf(x, -80.0f);
    float t  = x * 1.4426950408889634f;
    float tr = t + 12582912.0f;
    int   n  = __float_as_int(tr) - 0x4B400000;
    float rn = tr - 12582912.0f;
    float f  = t - rn;
    float p = 1.3333558146428443e-3f;
    p = fmaf(p, f, 9.618129107628477e-3f);
    p = fmaf(p, f, 5.550410866482158e-2f);
    p = fmaf(p, f, 2.402265069591007e-1f);
    p = fmaf(p, f, 6.931471805599453e-1f);
    p = fmaf(p, f, 1.0f);
    return p * __int_as_float((n + 127) << 23);
}

// ---------------- mma/ldsm/cp.async primitives ----------------
__device__ __forceinline__ void ldsm4(u32* r, u32 addr){
    asm volatile("ldmatrix.sync.aligned.m8n8.x4.shared.b16 {%0,%1,%2,%3}, [%4];"
        : "=r"(r[0]), "=r"(r[1]), "=r"(r[2]), "=r"(r[3]) : "r"(addr));
}
__device__ __forceinline__ void mma_bf16(float* c, const u32* a, u32 b0, u32 b1){
    asm volatile("mma.sync.aligned.m16n8k16.row.col.f32.bf16.bf16.f32 "
        "{%0,%1,%2,%3}, {%4,%5,%6,%7}, {%8,%9}, {%0,%1,%2,%3};"
        : "+f"(c[0]), "+f"(c[1]), "+f"(c[2]), "+f"(c[3])
        : "r"(a[0]), "r"(a[1]), "r"(a[2]), "r"(a[3]), "r"(b0), "r"(b1));
}
__device__ __forceinline__ void cp16(u32 dst, const void* src){
    asm volatile("cp.async.cg.shared.global [%0], [%1], 16;" :: "r"(dst), "l"(src));
}
__device__ __forceinline__ void cp_commit(){ asm volatile("cp.async.commit_group;" ::: "memory"); }
template<int N> __device__ __forceinline__ void cp_wait(){
    asm volatile("cp.async.wait_group %0;" :: "n"(N) : "memory");
}

// =====================================================================
// Prep: split f32 arrays into bf16 hi/lo pairs in gmem
// mode 0: x -> g_xhi/lo ; 1: w_qkv -> g_wqh/l ; 2: w_proj -> g_wph/l
// =====================================================================
__global__ __launch_bounds__(256) void split_kernel(const float* __restrict__ src, int mode, int n)
{
    __nv_bfloat16 *hp, *lp;
    if (mode == 0){ hp = g_xhi; lp = g_xlo; }
    else if (mode == 1){ hp = g_wqh; lp = g_wql; }
    else { hp = g_wph; lp = g_wpl; }
    int i = (blockIdx.x*blockDim.x + threadIdx.x)*4;
    if (i >= n) return;
    float4 v = *(const float4*)(src + i);
    __nv_bfloat16 h0,h1,h2,h3,l0,l1,l2,l3;
    split1(v.x,h0,l0); split1(v.y,h1,l1); split1(v.z,h2,l2); split1(v.w,h3,l3);
    *(u32*)(hp+i)   = bfpair(h0,h1);
    *(u32*)(hp+i+2) = bfpair(h2,h3);
    *(u32*)(lp+i)   = bfpair(l0,l1);
    *(u32*)(lp+i+2) = bfpair(l2,l3);
}

// =====================================================================
// bf16x3 mma.sync GEMM: C[M,Nc] = A[M,768] * B[Nc,768]^T (+bias)
// Block 128x128, BK=16 bf16, 4-stage cp.async over pre-split hi/lo tiles,
// 8 warps (4M x 2N), warp tile 32x64 via m16n8k16.
// C += ah*bh + al*bh + ah*bl.
// mode 0: A=x, B=w_qkv, scatter q(scaled,split)/k(split)/v(f32).
// mode 1: A=O(split), B=w_proj, out = C + bias (f32).
// =====================================================================
#define BPITCH      24                    // bf16 per row (48B); 12 words mod 32 distinct
#define TILE_BYTES  (128*BPITCH*2)        // 6144
#define STAGE_BYTES (4*TILE_BYTES)        // Ah,Al,Bh,Bl = 24576
#define GEMM_SMEM   (4*STAGE_BYTES)       // 98304

__global__ __launch_bounds__(256, 2) void mma_gemm_kernel(
    const float* __restrict__ bias, float* __restrict__ out, int mode)
{
    extern __shared__ __nv_bfloat16 smb[];
    const __nv_bfloat16 *Ahi, *Alo, *Bhi, *Blo;
    if (mode == 0){ Ahi = g_xhi; Alo = g_xlo; Bhi = g_wqh; Blo = g_wql; }
    else          { Ahi = g_ohi; Alo = g_olo; Bhi = g_wph; Blo = g_wpl; }

    int tid = threadIdx.x;
    int lane = tid & 31, warp = tid >> 5;
    int wm = warp & 3, wn = warp >> 2;
    int m0 = blockIdx.y * 128, n0 = blockIdx.x * 128;

    u32 sbase = smem_u32(smb);

    // ldsm thread offsets (bytes within a tile)
    u32 aoff = (u32)((wm*32 + (lane & 15))*48 + (lane >> 4)*16);
    u32 boff = (u32)((wn*64 + (lane & 7) + ((lane >> 4) & 1)*8)*48 + ((lane >> 3) & 1)*16);

    float c[2][8][4];
    #pragma unroll
    for (int i = 0; i < 2; i++)
        #pragma unroll
        for (int j = 0; j < 8; j++)
            #pragma unroll
            for (int q = 0; q < 4; q++) c[i][j][q] = 0.0f;

    int lrow = tid >> 1, lhalf = tid & 1;
    auto load_chunk = [&](int chunk){
        int st = chunk & 3;
        u32 stb = sbase + st*STAGE_BYTES;
        int kf = chunk*16;
        const __nv_bfloat16* s0 = Ahi + (size_t)(m0 + lrow)*768 + kf + lhalf*8;
        const __nv_bfloat16* s1 = Alo + (size_t)(m0 + lrow)*768 + kf + lhalf*8;
        const __nv_bfloat16* s2 = Bhi + (size_t)(n0 + lrow)*768 + kf + lhalf*8;
        const __nv_bfloat16* s3 = Blo + (size_t)(n0 + lrow)*768 + kf + lhalf*8;
        u32 d = stb + lrow*48 + lhalf*16;
        cp16(d,                s0);
        cp16(d + TILE_BYTES,   s1);
        cp16(d + 2*TILE_BYTES, s2);
        cp16(d + 3*TILE_BYTES, s3);
        cp_commit();
    };

    load_chunk(0); load_chunk(1); load_chunk(2);

    #pragma unroll 1
    for (int i = 0; i < 48; i++){
        if (i < 46)       cp_wait<2>();
        else if (i == 46) cp_wait<1>();
        else              cp_wait<0>();
        __syncthreads();

        u32 stb = sbase + (i & 3)*STAGE_BYTES;
        u32 ah[2][4], al[2][4];
        #pragma unroll
        for (int fm = 0; fm < 2; fm++){
            ldsm4(ah[fm], stb + aoff + fm*(16*48));
            ldsm4(al[fm], stb + TILE_BYTES + aoff + fm*(16*48));
        }
        #pragma unroll
        for (int i4 = 0; i4 < 4; i4++){
            u32 bh4[4], bl4[4];
            ldsm4(bh4, stb + 2*TILE_BYTES + boff + i4*(16*48));
            ldsm4(bl4, stb + 3*TILE_BYTES + boff + i4*(16*48));
            #pragma unroll
            for (int fm = 0; fm < 2; fm++){
                mma_bf16(c[fm][2*i4+0], ah[fm], bh4[0], bh4[1]);
                mma_bf16(c[fm][2*i4+0], al[fm], bh4[0], bh4[1]);
                mma_bf16(c[fm][2*i4+0], ah[fm], bl4[0], bl4[1]);
                mma_bf16(c[fm][2*i4+1], ah[fm], bh4[2], bh4[3]);
                mma_bf16(c[fm][2*i4+1], al[fm], bh4[2], bh4[3]);
                mma_bf16(c[fm][2*i4+1], ah[fm], bl4[2], bl4[3]);
            }
        }

        if (i + 3 < 48) load_chunk(i + 3);
    }

    // ---------------- epilogue ----------------
    int g = lane >> 2, tig = lane & 3;
    int colbase = n0 + wn*64;
    if (mode == 0){
        int hblk = colbase >> 6;
        int t_sel = hblk / NHEADS;
        int h     = hblk - t_sel*NHEADS;
        float sc  = (t_sel == 0) ? ATT_SCALE : 1.0f;
        #pragma unroll
        for (int fm = 0; fm < 2; fm++){
            int row0 = m0 + wm*32 + fm*16 + g;
            #pragma unroll
            for (int half = 0; half < 2; half++){
                int row = row0 + half*8;
                int b = row >> 10, n = row & 1023;
                size_t base_e = ((size_t)((b*NHEADS + h)*NSEQ + n))*NHD;
                if (t_sel == 2){
                    float* vp = g_v + base_e;
                    #pragma unroll
                    for (int nf = 0; nf < 8; nf++){
                        int d0 = nf*8 + tig*2;
                        *(float2*)(vp + d0) =
                            make_float2(c[fm][nf][half*2], c[fm][nf][half*2+1]);
                    }
                } else {
                    __nv_bfloat16* hip = (t_sel == 0) ? g_qhi : g_khi;
                    __nv_bfloat16* lop = (t_sel == 0) ? g_qlo : g_klo;
                    #pragma unroll
                    for (int nf = 0; nf < 8; nf++){
                        int d0 = nf*8 + tig*2;
                        float x0 = c[fm][nf][half*2]*sc, x1 = c[fm][nf][half*2+1]*sc;
                        __nv_bfloat16 h0,h1,l0,l1;
                        split1(x0,h0,l0); split1(x1,h1,l1);
                        *(u32*)(hip + base_e + d0) = bfpair(h0,h1);
                        *(u32*)(lop + base_e + d0) = bfpair(l0,l1);
                    }
                }
            }
        }
    } else {
        #pragma unroll
        for (int fm = 0; fm < 2; fm++){
            int row0 = m0 + wm*32 + fm*16 + g;
            #pragma unroll
            for (int half = 0; half < 2; half++){
                int row = row0 + half*8;
                float* base = out + (size_t)row*768 + colbase;
                #pragma unroll
                for (int nf = 0; nf < 8; nf++){
                    int cg = nf*8 + tig*2;
                    float2 bv = *(const float2*)(bias + colbase + cg);
                    *(float2*)(base + cg) =
                        make_float2(c[fm][nf][half*2] + bv.x,
                                    c[fm][nf][half*2+1] + bv.y);
                }
            }
        }
    }
}

// =====================================================================
// Flash attention, bf16x3 mma.sync. BQ=128 (8 warps x m16), BKV=64, D=64.
// Smem (bf16, pitch FPB=72 -> 36 words, conflict-free ldsm):
//   Qhi/Qlo[128][72]  (q rows, d cols; cp.async from pre-split, scaled)
//   Khi/Klo[64][72]   (kv rows, d cols; cp.async)
//   VThi/VTlo[64][72] (d rows, kv cols; in-kernel transpose+split of f32 V)
//   Phi/Plo[128][72]  (q rows, kv cols; in-register split of P)
// =====================================================================
#define FPB        72
#define QT_E       (128*FPB)   // 9216 elems
#define KT_E       (64*FPB)    // 4608
#define FLASH_SMEM ((2*QT_E + 4*KT_E + 2*QT_E)*2)   // 110592 bytes

__global__ __launch_bounds__(256, 2) void flash_mma_kernel()
{
    extern __shared__ __nv_bfloat16 fbm[];
    __nv_bfloat16* sQh = fbm;
    __nv_bfloat16* sQl = sQh + QT_E;
    __nv_bfloat16* sKh = sQl + QT_E;
    __nv_bfloat16* sKl = sKh + KT_E;
    __nv_bfloat16* sVh = sKl + KT_E;
    __nv_bfloat16* sVl = sVh + KT_E;
    __nv_bfloat16* sPh = sVl + KT_E;
    __nv_bfloat16* sPl = sPh + QT_E;

    int tid = threadIdx.x, lane = tid & 31, warp = tid >> 5;
    int q0 = blockIdx.x * 128;
    int bh = blockIdx.y;
    size_t hb = (size_t)bh * NSEQ * NHD;

    u32 qhb = smem_u32(sQh), qlb = smem_u32(sQl);
    u32 khb = smem_u32(sKh), klb = smem_u32(sKl);
    u32 vhb = smem_u32(sVh), vlb = smem_u32(sVl);
    u32 phb = smem_u32(sPh), plb = smem_u32(sPl);

    // ldsm thread offsets (bytes)
    u32 aoffp = (u32)((warp*16 + (lane & 15))*144 + (lane >> 4)*16);
    u32 boffp = (u32)(((lane & 7) + ((lane >> 4) & 1)*8)*144 + ((lane >> 3) & 1)*16);

    // Q hi/lo via cp.async (8 cp16/thread)
    {
        int f2 = tid & 255;
        #pragma unroll
        for (int it = 0; it < 8; it++){
            int f = f2 + 256*it;
            int tile = it >> 2;              // 0: hi, 1: lo
            int fr = f & 1023;
            int row = fr >> 3, half = fr & 7;
            const __nv_bfloat16* sp = (tile ? g_qlo : g_qhi) + hb + (size_t)(q0 + row)*NHD + half*8;
            cp16((tile ? qlb : qhb) + row*144 + half*16, sp);
        }
        cp_commit();
    }

    float o[8][4];
    #pragma unroll
    for (int j = 0; j < 8; j++)
        #pragma unroll
        for (int q = 0; q < 4; q++) o[j][q] = 0.0f;
    float m0f = -1e30f, m1f = -1e30f, l0s = 0.0f, l1s = 0.0f;

    #pragma unroll 1
    for (int t = 0; t < 16; t++){
        int c0 = t * 64;
        __syncthreads();   // prev-iter smem reads done

        // K hi/lo via cp.async (4 cp16/thread)
        #pragma unroll
        for (int it = 0; it < 4; it++){
            int f = tid + 256*it;
            int tile = it >> 1;              // 0: hi, 1: lo
            int fr = f & 511;
            int row = fr >> 3, half = fr & 7;
            const __nv_bfloat16* sp = (tile ? g_klo : g_khi) + hb + (size_t)(c0 + row)*NHD + half*8;
            cp16((tile ? klb : khb) + row*144 + half*16, sp);
        }
        cp_commit();

        // V transpose + split: f32 -> VT hi/lo
        #pragma unroll
        for (int it = 0; it < 4; it++){
            int f = tid + 256*it;
            int row = f >> 4, g = f & 15;
            float4 v = *(const float4*)(g_v + hb + (size_t)(c0 + row)*NHD + g*4);
            float vv[4] = {v.x, v.y, v.z, v.w};
            #pragma unroll
            for (int j = 0; j < 4; j++){
                int d = g*4 + j;
                __nv_bfloat16 hh, ll;
                split1(vv[j], hh, ll);
                sVh[d*FPB + row] = hh;
                sVl[d*FPB + row] = ll;
            }
        }
        cp_wait<0>();
        __syncthreads();

        // ---- S = Q K^T (bf16x3) ----
        float s[8][4];
        #pragma unroll
        for (int j = 0; j < 8; j++)
            #pragma unroll
            for (int q = 0; q < 4; q++) s[j][q] = 0.0f;

        #pragma unroll
        for (int kc = 0; kc < 4; kc++){
            u32 qh4[4], ql4[4];
            ldsm4(qh4, qhb + aoffp + kc*32);
            ldsm4(ql4, qlb + aoffp + kc*32);
            #pragma unroll
            for (int i4 = 0; i4 < 4; i4++){
                u32 bh4[4], bl4[4];
                ldsm4(bh4, khb + boffp + i4*(16*144) + kc*32);
                ldsm4(bl4, klb + boffp + i4*(16*144) + kc*32);
                mma_bf16(s[2*i4+0], qh4, bh4[0], bh4[1]);
                mma_bf16(s[2*i4+0], ql4, bh4[0], bh4[1]);
                mma_bf16(s[2*i4+0], qh4, bl4[0], bl4[1]);
                mma_bf16(s[2*i4+1], qh4, bh4[2], bh4[3]);
                mma_bf16(s[2*i4+1], ql4, bh4[2], bh4[3]);
                mma_bf16(s[2*i4+1], qh4, bl4[2], bl4[3]);
            }
        }

        // ---- streaming softmax ----
        float mx0 = -1e30f, mx1 = -1e30f;
        #pragma unroll
        for (int j = 0; j < 8; j++){
            mx0 = fmaxf(mx0, fmaxf(s[j][0], s[j][1]));
            mx1 = fmaxf(mx1, fmaxf(s[j][2], s[j][3]));
        }
        #pragma unroll
        for (int off = 1; off <= 2; off <<= 1){
            mx0 = fmaxf(mx0, __shfl_xor_sync(0xffffffffu, mx0, off));
            mx1 = fmaxf(mx1, __shfl_xor_sync(0xffffffffu, mx1, off));
        }
        float mn0 = fmaxf(m0f, mx0), mn1 = fmaxf(m1f, mx1);
        float corr0 = fast_exp(m0f - mn0), corr1 = fast_exp(m1f - mn1);
        m0f = mn0; m1f = mn1;

        int r0 = lane >> 2;
        int colq = 2*(lane & 3);
        float sum0 = 0.0f, sum1 = 0.0f;
        #pragma unroll
        for (int j = 0; j < 8; j++){
            float p00 = fast_exp(s[j][0] - mn0);
            float p01 = fast_exp(s[j][1] - mn0);
            float p10 = fast_exp(s[j][2] - mn1);
            float p11 = fast_exp(s[j][3] - mn1);
            sum0 += p00 + p01;
            sum1 += p10 + p11;
            __nv_bfloat16 h00,h01,h10,h11,l00,l01,l10,l11;
            split1(p00,h00,l00); split1(p01,h01,l01);
            split1(p10,h10,l10); split1(p11,h11,l11);
            int e0 = (warp*16 + r0    )*FPB + colq + 8*j;
            int e1 = (warp*16 + r0 + 8)*FPB + colq + 8*j;
            *(u32*)(sPh + e0) = bfpair(h00,h01);
            *(u32*)(sPl + e0) = bfpair(l00,l01);
            *(u32*)(sPh + e1) = bfpair(h10,h11);
            *(u32*)(sPl + e1) = bfpair(l10,l11);
        }
        #pragma unroll
        for (int off = 1; off <= 2; off <<= 1){
            sum0 += __shfl_xor_sync(0xffffffffu, sum0, off);
            sum1 += __shfl_xor_sync(0xffffffffu, sum1, off);
        }
        l0s = l0s*corr0 + sum0;
        l1s = l1s*corr1 + sum1;
        #pragma unroll
        for (int j = 0; j < 8; j++){
            o[j][0] *= corr0; o[j][1] *= corr0;
            o[j][2] *= corr1; o[j][3] *= corr1;
        }
        __syncwarp();   // own-warp P rows visible to own-warp ldsm

        // ---- O += P V (bf16x3) ----
        #pragma unroll
        for (int kc = 0; kc < 4; kc++){
            u32 ph4[4], pl4[4];
            ldsm4(ph4, phb + aoffp + kc*32);
            ldsm4(pl4, plb + aoffp + kc*32);
            #pragma unroll
            for (int i4 = 0; i4 < 4; i4++){
                u32 bh4[4], bl4[4];
                ldsm4(bh4, vhb + boffp + i4*(16*144) + kc*32);
                ldsm4(bl4, vlb + boffp + i4*(16*144) + kc*32);
                mma_bf16(o[2*i4+0], ph4, bh4[0], bh4[1]);
                mma_bf16(o[2*i4+0], pl4, bh4[0], bh4[1]);
                mma_bf16(o[2*i4+0], ph4, bl4[0], bl4[1]);
                mma_bf16(o[2*i4+1], ph4, bh4[2], bh4[3]);
                mma_bf16(o[2*i4+1], pl4, bh4[2], bh4[3]);
                mma_bf16(o[2*i4+1], ph4, bl4[2], bl4[3]);
            }
        }
    }

    // ---- finalize: O /= l, split, write g_ohi/g_olo[b*N+n][h*64+d] ----
    int b = bh / NHEADS, h = bh % NHEADS;
    float inv0 = 1.0f / l0s, inv1 = 1.0f / l1s;
    int r0 = lane >> 2, colq = 2*(lane & 3);
    int gq0 = q0 + warp*16 + r0;
    size_t base0 = (size_t)(b*NSEQ + gq0    )*NDIM + h*NHD;
    size_t base1 = (size_t)(b*NSEQ + gq0 + 8)*NDIM + h*NHD;
    #pragma unroll
    for (int j = 0; j < 8; j++){
        int d0 = 8*j + colq;
        float x0 = o[j][0]*inv0, x1 = o[j][1]*inv0;
        float y0 = o[j][2]*inv1, y1 = o[j][3]*inv1;
        __nv_bfloat16 hx0,hx1,hy0,hy1,lx0,lx1,ly0,ly1;
        split1(x0,hx0,lx0); split1(x1,hx1,lx1);
        split1(y0,hy0,ly0); split1(y1,hy1,ly1);
        *(u32*)(g_ohi + base0 + d0) = bfpair(hx0,hx1);
        *(u32*)(g_olo + base0 + d0) = bfpair(lx0,lx1);
        *(u32*)(g_ohi + base1 + d0) = bfpair(hy0,hy1);
        *(u32*)(g_olo + base1 + d0) = bfpair(ly0,ly1);
    }
}

// =====================================================================
extern "C" void kernel_launch(void* const* d_in, const int* in_sizes, int n_in,
                              void* d_out, int out_size)
{
    const float* x      = (const float*)d_in[0];
    const float* w_qkv  = (const float*)d_in[1];
    const float* w_proj = (const float*)d_in[2];
    const float* b_proj = (const float*)d_in[3];
    float* out = (float*)d_out;

    cudaFuncSetAttribute(mma_gemm_kernel, cudaFuncAttributeMaxDynamicSharedMemorySize, GEMM_SMEM);
    cudaFuncSetAttribute(flash_mma_kernel, cudaFuncAttributeMaxDynamicSharedMemorySize, FLASH_SMEM);

    // 1. split inputs into bf16 hi/lo
    split_kernel<<<X_ELEMS/1024, 256>>>(x, 0, X_ELEMS);
    split_kernel<<<(2304*768)/1024, 256>>>(w_qkv, 1, 2304*768);
    split_kernel<<<(768*768)/1024, 256>>>(w_proj, 2, 768*768);
    // 2. qkv GEMM -> q(split,scaled)/k(split)/v(f32)
    mma_gemm_kernel<<<dim3(2304/128, 16384/128), 256, GEMM_SMEM>>>(nullptr, nullptr, 0);
    // 3. flash attention -> O split
    flash_mma_kernel<<<dim3(NSEQ/128, NBATCH*NHEADS), 256, FLASH_SMEM>>>();
    // 4. proj GEMM + bias -> out (f32)
    mma_gemm_kernel<<<dim3(768/128, 16384/128), 256, GEMM_SMEM>>>(b_proj, out, 1);
}

// round 7
// speedup vs baseline: 2.6037x; 1.1518x over previous
#include <cuda_runtime.h>
#include <cuda_bf16.h>
#include <cstdint>

typedef unsigned long long u64;
typedef unsigned int u32;

#define NBATCH 16
#define NSEQ   1024
#define NDIM   768
#define NHEADS 12
#define NHD    64
#define ATT_SCALE 0.125f
#define QKV_ELEMS (NBATCH*NHEADS*NSEQ*NHD)    // 12582912
#define X_ELEMS   (NBATCH*NSEQ*NDIM)          // 12582912

// ---------------- static scratch (allocation-free) ----------------
__device__ __nv_bfloat16 g_xhi[X_ELEMS], g_xlo[X_ELEMS];
__device__ __nv_bfloat16 g_wqh[2304*768], g_wql[2304*768];
__device__ __nv_bfloat16 g_wph[768*768],  g_wpl[768*768];
__device__ __nv_bfloat16 g_qhi[QKV_ELEMS], g_qlo[QKV_ELEMS];   // [B*H, N, D], pre-scaled
__device__ __nv_bfloat16 g_khi[QKV_ELEMS], g_klo[QKV_ELEMS];   // [B*H, N, D]
__device__ __nv_bfloat16 g_vthi[QKV_ELEMS], g_vtlo[QKV_ELEMS]; // [B*H, D, N] (transposed)
__device__ __nv_bfloat16 g_ohi[X_ELEMS], g_olo[X_ELEMS];       // [B*N, C]

// ---------------- helpers ----------------
__device__ __forceinline__ u32 smem_u32(const void* p){
    u32 a; asm("{ .reg .u64 t; cvta.to.shared.u64 t, %1; cvt.u32.u64 %0, t; }" : "=r"(a) : "l"(p));
    return a;
}
__device__ __forceinline__ u32 bfpair(__nv_bfloat16 a, __nv_bfloat16 b){
    u32 lo = (u32)__bfloat16_as_ushort(a);
    u32 hi = (u32)__bfloat16_as_ushort(b);
    return lo | (hi << 16);
}
__device__ __forceinline__ void split1(float x, __nv_bfloat16& h, __nv_bfloat16& l){
    h = __float2bfloat16(x);
    l = __float2bfloat16(x - __bfloat162float(h));
}

// fast exp on the FMA pipe (no MUFU), x <= ~0
__device__ __forceinline__ float fast_exp(float x){
    x = fmaxf(x, -80.0f);
    float t  = x * 1.4426950408889634f;
    float tr = t + 12582912.0f;
    int   n  = __float_as_int(tr) - 0x4B400000;
    float rn = tr - 12582912.0f;
    float f  = t - rn;
    float p = 1.3333558146428443e-3f;
    p = fmaf(p, f, 9.618129107628477e-3f);
    p = fmaf(p, f, 5.550410866482158e-2f);
    p = fmaf(p, f, 2.402265069591007e-1f);
    p = fmaf(p, f, 6.931471805599453e-1f);
    p = fmaf(p, f, 1.0f);
    return p * __int_as_float((n + 127) << 23);
}

// ---------------- mma/ldsm/cp.async primitives ----------------
__device__ __forceinline__ void ldsm4(u32* r, u32 addr){
    asm volatile("ldmatrix.sync.aligned.m8n8.x4.shared.b16 {%0,%1,%2,%3}, [%4];"
        : "=r"(r[0]), "=r"(r[1]), "=r"(r[2]), "=r"(r[3]) : "r"(addr));
}
__device__ __forceinline__ void mma_bf16(float* c, const u32* a, u32 b0, u32 b1){
    asm volatile("mma.sync.aligned.m16n8k16.row.col.f32.bf16.bf16.f32 "
        "{%0,%1,%2,%3}, {%4,%5,%6,%7}, {%8,%9}, {%0,%1,%2,%3};"
        : "+f"(c[0]), "+f"(c[1]), "+f"(c[2]), "+f"(c[3])
        : "r"(a[0]), "r"(a[1]), "r"(a[2]), "r"(a[3]), "r"(b0), "r"(b1));
}
__device__ __forceinline__ void cp16(u32 dst, const void* src){
    asm volatile("cp.async.cg.shared.global [%0], [%1], 16;" :: "r"(dst), "l"(src));
}
__device__ __forceinline__ void cp_commit(){ asm volatile("cp.async.commit_group;" ::: "memory"); }
template<int N> __device__ __forceinline__ void cp_wait(){
    asm volatile("cp.async.wait_group %0;" :: "n"(N) : "memory");
}

// =====================================================================
// Prep: split f32 arrays into bf16 hi/lo pairs in gmem
// =====================================================================
__global__ __launch_bounds__(256) void split_kernel(const float* __restrict__ src, int mode, int n)
{
    __nv_bfloat16 *hp, *lp;
    if (mode == 0){ hp = g_xhi; lp = g_xlo; }
    else if (mode == 1){ hp = g_wqh; lp = g_wql; }
    else { hp = g_wph; lp = g_wpl; }
    int i = (blockIdx.x*blockDim.x + threadIdx.x)*4;
    if (i >= n) return;
    float4 v = *(const float4*)(src + i);
    __nv_bfloat16 h0,h1,h2,h3,l0,l1,l2,l3;
    split1(v.x,h0,l0); split1(v.y,h1,l1); split1(v.z,h2,l2); split1(v.w,h3,l3);
    *(u32*)(hp+i)   = bfpair(h0,h1);
    *(u32*)(hp+i+2) = bfpair(h2,h3);
    *(u32*)(lp+i)   = bfpair(l0,l1);
    *(u32*)(lp+i+2) = bfpair(l2,l3);
}

// =====================================================================
// bf16x3 mma.sync GEMM, RAW-chain-free 3-pass inner loop.
// Block 128x128, BK=16, 4-stage cp.async, 8 warps (4M x 2N).
// mode 0: A=x, B=w_qkv -> q(split,scaled)/k(split)/vT(split,transposed).
// mode 1: A=O(split), B=w_proj, out = C + bias (f32).
// =====================================================================
#define BPITCH      24
#define TILE_BYTES  (128*BPITCH*2)        // 6144
#define STAGE_BYTES (4*TILE_BYTES)        // 24576
#define GEMM_SMEM   (4*STAGE_BYTES)       // 98304

__global__ __launch_bounds__(256, 2) void mma_gemm_kernel(
    const float* __restrict__ bias, float* __restrict__ out, int mode)
{
    extern __shared__ __nv_bfloat16 smb[];
    const __nv_bfloat16 *Ahi, *Alo, *Bhi, *Blo;
    if (mode == 0){ Ahi = g_xhi; Alo = g_xlo; Bhi = g_wqh; Blo = g_wql; }
    else          { Ahi = g_ohi; Alo = g_olo; Bhi = g_wph; Blo = g_wpl; }

    int tid = threadIdx.x;
    int lane = tid & 31, warp = tid >> 5;
    int wm = warp & 3, wn = warp >> 2;
    int m0 = blockIdx.y * 128, n0 = blockIdx.x * 128;

    u32 sbase = smem_u32(smb);
    u32 aoff = (u32)((wm*32 + (lane & 15))*48 + (lane >> 4)*16);
    u32 boff = (u32)((wn*64 + (lane & 7) + ((lane >> 4) & 1)*8)*48 + ((lane >> 3) & 1)*16);

    float c[2][8][4];
    #pragma unroll
    for (int i = 0; i < 2; i++)
        #pragma unroll
        for (int j = 0; j < 8; j++)
            #pragma unroll
            for (int q = 0; q < 4; q++) c[i][j][q] = 0.0f;

    int lrow = tid >> 1, lhalf = tid & 1;
    auto load_chunk = [&](int chunk){
        int st = chunk & 3;
        u32 stb = sbase + st*STAGE_BYTES;
        int kf = chunk*16;
        const __nv_bfloat16* s0 = Ahi + (size_t)(m0 + lrow)*768 + kf + lhalf*8;
        const __nv_bfloat16* s1 = Alo + (size_t)(m0 + lrow)*768 + kf + lhalf*8;
        const __nv_bfloat16* s2 = Bhi + (size_t)(n0 + lrow)*768 + kf + lhalf*8;
        const __nv_bfloat16* s3 = Blo + (size_t)(n0 + lrow)*768 + kf + lhalf*8;
        u32 d = stb + lrow*48 + lhalf*16;
        cp16(d,                s0);
        cp16(d + TILE_BYTES,   s1);
        cp16(d + 2*TILE_BYTES, s2);
        cp16(d + 3*TILE_BYTES, s3);
        cp_commit();
    };

    load_chunk(0); load_chunk(1); load_chunk(2);

    #pragma unroll 1
    for (int i = 0; i < 48; i++){
        if (i < 46)       cp_wait<2>();
        else if (i == 46) cp_wait<1>();
        else              cp_wait<0>();
        __syncthreads();

        u32 stb = sbase + (i & 3)*STAGE_BYTES;
        u32 ah[2][4], al[2][4], bh4[4][4];
        #pragma unroll
        for (int fm = 0; fm < 2; fm++){
            ldsm4(ah[fm], stb + aoff + fm*(16*48));
            ldsm4(al[fm], stb + TILE_BYTES + aoff + fm*(16*48));
        }
        #pragma unroll
        for (int i4 = 0; i4 < 4; i4++)
            ldsm4(bh4[i4], stb + 2*TILE_BYTES + boff + i4*(16*48));

        // pass 1: ah*bh (16 independent accumulators)
        #pragma unroll
        for (int i4 = 0; i4 < 4; i4++)
            #pragma unroll
            for (int fm = 0; fm < 2; fm++){
                mma_bf16(c[fm][2*i4+0], ah[fm], bh4[i4][0], bh4[i4][1]);
                mma_bf16(c[fm][2*i4+1], ah[fm], bh4[i4][2], bh4[i4][3]);
            }
        // pass 2: al*bh
        #pragma unroll
        for (int i4 = 0; i4 < 4; i4++)
            #pragma unroll
            for (int fm = 0; fm < 2; fm++){
                mma_bf16(c[fm][2*i4+0], al[fm], bh4[i4][0], bh4[i4][1]);
                mma_bf16(c[fm][2*i4+1], al[fm], bh4[i4][2], bh4[i4][3]);
            }
        // pass 3: ah*bl (bl loaded per-i4)
        #pragma unroll
        for (int i4 = 0; i4 < 4; i4++){
            u32 bl4[4];
            ldsm4(bl4, stb + 3*TILE_BYTES + boff + i4*(16*48));
            #pragma unroll
            for (int fm = 0; fm < 2; fm++){
                mma_bf16(c[fm][2*i4+0], ah[fm], bl4[0], bl4[1]);
                mma_bf16(c[fm][2*i4+1], ah[fm], bl4[2], bl4[3]);
            }
        }

        if (i + 3 < 48) load_chunk(i + 3);
    }

    // ---------------- epilogue ----------------
    int g = lane >> 2, tig = lane & 3;
    int colbase = n0 + wn*64;
    if (mode == 0){
        int hblk = colbase >> 6;
        int t_sel = hblk / NHEADS;
        int h     = hblk - t_sel*NHEADS;
        float sc  = (t_sel == 0) ? ATT_SCALE : 1.0f;
        #pragma unroll
        for (int fm = 0; fm < 2; fm++){
            int row0 = m0 + wm*32 + fm*16 + g;
            #pragma unroll
            for (int half = 0; half < 2; half++){
                int row = row0 + half*8;
                int b = row >> 10, n = row & 1023;
                int bh_i = b*NHEADS + h;
                if (t_sel == 2){
                    // V transposed: g_vt[bh][d][n]
                    size_t vb = (size_t)bh_i*NHD*NSEQ + n;
                    #pragma unroll
                    for (int nf = 0; nf < 8; nf++){
                        int d0 = nf*8 + tig*2;
                        float x0 = c[fm][nf][half*2], x1 = c[fm][nf][half*2+1];
                        __nv_bfloat16 h0,h1,l0,l1;
                        split1(x0,h0,l0); split1(x1,h1,l1);
                        g_vthi[vb + (size_t)d0*NSEQ]     = h0;
                        g_vthi[vb + (size_t)(d0+1)*NSEQ] = h1;
                        g_vtlo[vb + (size_t)d0*NSEQ]     = l0;
                        g_vtlo[vb + (size_t)(d0+1)*NSEQ] = l1;
                    }
                } else {
                    size_t base_e = ((size_t)bh_i*NSEQ + n)*NHD;
                    __nv_bfloat16* hip = (t_sel == 0) ? g_qhi : g_khi;
                    __nv_bfloat16* lop = (t_sel == 0) ? g_qlo : g_klo;
                    #pragma unroll
                    for (int nf = 0; nf < 8; nf++){
                        int d0 = nf*8 + tig*2;
                        float x0 = c[fm][nf][half*2]*sc, x1 = c[fm][nf][half*2+1]*sc;
                        __nv_bfloat16 h0,h1,l0,l1;
                        split1(x0,h0,l0); split1(x1,h1,l1);
                        *(u32*)(hip + base_e + d0) = bfpair(h0,h1);
                        *(u32*)(lop + base_e + d0) = bfpair(l0,l1);
                    }
                }
            }
        }
    } else {
        #pragma unroll
        for (int fm = 0; fm < 2; fm++){
            int row0 = m0 + wm*32 + fm*16 + g;
            #pragma unroll
            for (int half = 0; half < 2; half++){
                int row = row0 + half*8;
                float* base = out + (size_t)row*768 + colbase;
                #pragma unroll
                for (int nf = 0; nf < 8; nf++){
                    int cg = nf*8 + tig*2;
                    float2 bv = *(const float2*)(bias + colbase + cg);
                    *(float2*)(base + cg) =
                        make_float2(c[fm][nf][half*2] + bv.x,
                                    c[fm][nf][half*2+1] + bv.y);
                }
            }
        }
    }
}

// =====================================================================
// Flash attention, bf16x3 mma.sync, P in registers, V pre-transposed.
// BQ=128 (8 warps x m16), BKV=64, D=64. Smem pitch FPB=72 bf16.
//   Qhi/Qlo[128][72], Khi/Klo[64][72], Vthi/Vtlo[64][72] (all cp.async)
// =====================================================================
#define FPB        72
#define QT_E       (128*FPB)
#define KT_E       (64*FPB)
#define FLASH_SMEM ((2*QT_E + 4*KT_E)*2)   // 73728 bytes

__global__ __launch_bounds__(256, 2) void flash_mma_kernel()
{
    extern __shared__ __nv_bfloat16 fbm[];
    __nv_bfloat16* sQh = fbm;
    __nv_bfloat16* sQl = sQh + QT_E;
    __nv_bfloat16* sKh = sQl + QT_E;
    __nv_bfloat16* sKl = sKh + KT_E;
    __nv_bfloat16* sVh = sKl + KT_E;
    __nv_bfloat16* sVl = sVh + KT_E;

    int tid = threadIdx.x, lane = tid & 31, warp = tid >> 5;
    int q0 = blockIdx.x * 128;
    int bh = blockIdx.y;
    size_t hb  = (size_t)bh * NSEQ * NHD;   // q/k base
    size_t hvt = (size_t)bh * NHD * NSEQ;   // vt base

    u32 qhb = smem_u32(sQh), qlb = smem_u32(sQl);
    u32 khb = smem_u32(sKh), klb = smem_u32(sKl);
    u32 vhb = smem_u32(sVh), vlb = smem_u32(sVl);

    u32 aoffp = (u32)((warp*16 + (lane & 15))*144 + (lane >> 4)*16);
    u32 boffp = (u32)(((lane & 7) + ((lane >> 4) & 1)*8)*144 + ((lane >> 3) & 1)*16);

    // Q hi/lo via cp.async
    #pragma unroll
    for (int it = 0; it < 8; it++){
        int f = tid + 256*it;
        int tile = it >> 2;
        int fr = f & 1023;
        int row = fr >> 3, half = fr & 7;
        const __nv_bfloat16* sp = (tile ? g_qlo : g_qhi) + hb + (size_t)(q0 + row)*NHD + half*8;
        cp16((tile ? qlb : qhb) + row*144 + half*16, sp);
    }
    cp_commit();

    float o[8][4];
    #pragma unroll
    for (int j = 0; j < 8; j++)
        #pragma unroll
        for (int q = 0; q < 4; q++) o[j][q] = 0.0f;
    float m0f = -1e30f, m1f = -1e30f, l0s = 0.0f, l1s = 0.0f;

    #pragma unroll 1
    for (int t = 0; t < 16; t++){
        int c0 = t * 64;
        __syncthreads();   // prev-iter smem reads done

        // K hi/lo
        #pragma unroll
        for (int it = 0; it < 4; it++){
            int f = tid + 256*it;
            int tile = it >> 1;
            int fr = f & 511;
            int row = fr >> 3, half = fr & 7;
            const __nv_bfloat16* sp = (tile ? g_klo : g_khi) + hb + (size_t)(c0 + row)*NHD + half*8;
            cp16((tile ? klb : khb) + row*144 + half*16, sp);
        }
        // Vt hi/lo (rows = d, cols = n slice)
        #pragma unroll
        for (int it = 0; it < 4; it++){
            int f = tid + 256*it;
            int tile = it >> 1;
            int fr = f & 511;
            int row = fr >> 3, ch = fr & 7;
            const __nv_bfloat16* sp = (tile ? g_vtlo : g_vthi) + hvt + (size_t)row*NSEQ + c0 + ch*8;
            cp16((tile ? vlb : vhb) + row*144 + ch*16, sp);
        }
        cp_commit();
        cp_wait<0>();
        __syncthreads();

        // ---- S = Q K^T (bf16x3, 3-pass) ----
        float s[8][4];
        #pragma unroll
        for (int j = 0; j < 8; j++)
            #pragma unroll
            for (int q = 0; q < 4; q++) s[j][q] = 0.0f;

        #pragma unroll
        for (int kc = 0; kc < 4; kc++){
            u32 qh4[4], ql4[4], kh4[4][4];
            ldsm4(qh4, qhb + aoffp + kc*32);
            ldsm4(ql4, qlb + aoffp + kc*32);
            #pragma unroll
            for (int i4 = 0; i4 < 4; i4++)
                ldsm4(kh4[i4], khb + boffp + i4*(16*144) + kc*32);
            #pragma unroll
            for (int i4 = 0; i4 < 4; i4++){
                mma_bf16(s[2*i4+0], qh4, kh4[i4][0], kh4[i4][1]);
                mma_bf16(s[2*i4+1], qh4, kh4[i4][2], kh4[i4][3]);
            }
            #pragma unroll
            for (int i4 = 0; i4 < 4; i4++){
                mma_bf16(s[2*i4+0], ql4, kh4[i4][0], kh4[i4][1]);
                mma_bf16(s[2*i4+1], ql4, kh4[i4][2], kh4[i4][3]);
            }
            #pragma unroll
            for (int i4 = 0; i4 < 4; i4++){
                u32 kl4[4];
                ldsm4(kl4, klb + boffp + i4*(16*144) + kc*32);
                mma_bf16(s[2*i4+0], qh4, kl4[0], kl4[1]);
                mma_bf16(s[2*i4+1], qh4, kl4[2], kl4[3]);
            }
        }

        // ---- streaming softmax (in-place exp into s) ----
        float mx0 = -1e30f, mx1 = -1e30f;
        #pragma unroll
        for (int j = 0; j < 8; j++){
            mx0 = fmaxf(mx0, fmaxf(s[j][0], s[j][1]));
            mx1 = fmaxf(mx1, fmaxf(s[j][2], s[j][3]));
        }
        #pragma unroll
        for (int off = 1; off <= 2; off <<= 1){
            mx0 = fmaxf(mx0, __shfl_xor_sync(0xffffffffu, mx0, off));
            mx1 = fmaxf(mx1, __shfl_xor_sync(0xffffffffu, mx1, off));
        }
        float mn0 = fmaxf(m0f, mx0), mn1 = fmaxf(m1f, mx1);
        float corr0 = fast_exp(m0f - mn0), corr1 = fast_exp(m1f - mn1);
        m0f = mn0; m1f = mn1;

        float sum0 = 0.0f, sum1 = 0.0f;
        #pragma unroll
        for (int j = 0; j < 8; j++){
            s[j][0] = fast_exp(s[j][0] - mn0);
            s[j][1] = fast_exp(s[j][1] - mn0);
            s[j][2] = fast_exp(s[j][2] - mn1);
            s[j][3] = fast_exp(s[j][3] - mn1);
            sum0 += s[j][0] + s[j][1];
            sum1 += s[j][2] + s[j][3];
        }
        #pragma unroll
        for (int off = 1; off <= 2; off <<= 1){
            sum0 += __shfl_xor_sync(0xffffffffu, sum0, off);
            sum1 += __shfl_xor_sync(0xffffffffu, sum1, off);
        }
        l0s = l0s*corr0 + sum0;
        l1s = l1s*corr1 + sum1;
        #pragma unroll
        for (int j = 0; j < 8; j++){
            o[j][0] *= corr0; o[j][1] *= corr0;
            o[j][2] *= corr1; o[j][3] *= corr1;
        }

        // ---- O += P V (P built in registers from s; bf16x3, 3-pass) ----
        #pragma unroll
        for (int kc = 0; kc < 4; kc++){
            // A-frag from S fragment pair (cols 16kc..16kc+15)
            u32 ph4[4], pl4[4];
            {
                __nv_bfloat16 h0,h1,l0,l1;
                split1(s[2*kc][0], h0, l0); split1(s[2*kc][1], h1, l1);
                ph4[0] = bfpair(h0,h1); pl4[0] = bfpair(l0,l1);
                split1(s[2*kc][2], h0, l0); split1(s[2*kc][3], h1, l1);
                ph4[1] = bfpair(h0,h1); pl4[1] = bfpair(l0,l1);
                split1(s[2*kc+1][0], h0, l0); split1(s[2*kc+1][1], h1, l1);
                ph4[2] = bfpair(h0,h1); pl4[2] = bfpair(l0,l1);
                split1(s[2*kc+1][2], h0, l0); split1(s[2*kc+1][3], h1, l1);
                ph4[3] = bfpair(h0,h1); pl4[3] = bfpair(l0,l1);
            }
            u32 vh4[4][4];
            #pragma unroll
            for (int i4 = 0; i4 < 4; i4++)
                ldsm4(vh4[i4], vhb + boffp + i4*(16*144) + kc*32);
            #pragma unroll
            for (int i4 = 0; i4 < 4; i4++){
                mma_bf16(o[2*i4+0], ph4, vh4[i4][0], vh4[i4][1]);
                mma_bf16(o[2*i4+1], ph4, vh4[i4][2], vh4[i4][3]);
            }
            #pragma unroll
            for (int i4 = 0; i4 < 4; i4++){
                mma_bf16(o[2*i4+0], pl4, vh4[i4][0], vh4[i4][1]);
                mma_bf16(o[2*i4+1], pl4, vh4[i4][2], vh4[i4][3]);
            }
            #pragma unroll
            for (int i4 = 0; i4 < 4; i4++){
                u32 vl4[4];
                ldsm4(vl4, vlb + boffp + i4*(16*144) + kc*32);
                mma_bf16(o[2*i4+0], ph4, vl4[0], vl4[1]);
                mma_bf16(o[2*i4+1], ph4, vl4[2], vl4[3]);
            }
        }
    }

    // ---- finalize: O /= l, split, write g_ohi/g_olo[b*N+n][h*64+d] ----
    int b = bh / NHEADS, h = bh % NHEADS;
    float inv0 = 1.0f / l0s, inv1 = 1.0f / l1s;
    int r0 = lane >> 2, colq = 2*(lane & 3);
    int gq0 = q0 + warp*16 + r0;
    size_t base0 = (size_t)(b*NSEQ + gq0    )*NDIM + h*NHD;
    size_t base1 = (size_t)(b*NSEQ + gq0 + 8)*NDIM + h*NHD;
    #pragma unroll
    for (int j = 0; j < 8; j++){
        int d0 = 8*j + colq;
        float x0 = o[j][0]*inv0, x1 = o[j][1]*inv0;
        float y0 = o[j][2]*inv1, y1 = o[j][3]*inv1;
        __nv_bfloat16 hx0,hx1,hy0,hy1,lx0,lx1,ly0,ly1;
        split1(x0,hx0,lx0); split1(x1,hx1,lx1);
        split1(y0,hy0,ly0); split1(y1,hy1,ly1);
        *(u32*)(g_ohi + base0 + d0) = bfpair(hx0,hx1);
        *(u32*)(g_olo + base0 + d0) = bfpair(lx0,lx1);
        *(u32*)(g_ohi + base1 + d0) = bfpair(hy0,hy1);
        *(u32*)(g_olo + base1 + d0) = bfpair(ly0,ly1);
    }
}

// =====================================================================
extern "C" void kernel_launch(void* const* d_in, const int* in_sizes, int n_in,
                              void* d_out, int out_size)
{
    const float* x      = (const float*)d_in[0];
    const float* w_qkv  = (const float*)d_in[1];
    const float* w_proj = (const float*)d_in[2];
    const float* b_proj = (const float*)d_in[3];
    float* out = (float*)d_out;

    cudaFuncSetAttribute(mma_gemm_kernel, cudaFuncAttributeMaxDynamicSharedMemorySize, GEMM_SMEM);
    cudaFuncSetAttribute(flash_mma_kernel, cudaFuncAttributeMaxDynamicSharedMemorySize, FLASH_SMEM);

    split_kernel<<<X_ELEMS/1024, 256>>>(x, 0, X_ELEMS);
    split_kernel<<<(2304*768)/1024, 256>>>(w_qkv, 1, 2304*768);
    split_kernel<<<(768*768)/1024, 256>>>(w_proj, 2, 768*768);
    mma_gemm_kernel<<<dim3(2304/128, 16384/128), 256, GEMM_SMEM>>>(nullptr, nullptr, 0);
    flash_mma_kernel<<<dim3(NSEQ/128, NBATCH*NHEADS), 256, FLASH_SMEM>>>();
    mma_gemm_kernel<<<dim3(768/128, 16384/128), 256, GEMM_SMEM>>>(b_proj, out, 1);
}

// round 9
// speedup vs baseline: 2.6469x; 1.0166x over previous
#include <cuda_runtime.h>
#include <cuda_bf16.h>
#include <cstdint>

typedef unsigned long long u64;
typedef unsigned int u32;

#define NBATCH 16
#define NSEQ   1024
#define NDIM   768
#define NHEADS 12
#define NHD    64
#define ATT_SCALE 0.125f
#define QKV_ELEMS (NBATCH*NHEADS*NSEQ*NHD)    // 12582912
#define X_ELEMS   (NBATCH*NSEQ*NDIM)          // 12582912

// ---------------- static scratch (allocation-free) ----------------
__device__ __nv_bfloat16 g_xhi[X_ELEMS], g_xlo[X_ELEMS];
__device__ __nv_bfloat16 g_wqh[2304*768], g_wql[2304*768];
__device__ __nv_bfloat16 g_wph[768*768],  g_wpl[768*768];
__device__ __nv_bfloat16 g_qhi[QKV_ELEMS], g_qlo[QKV_ELEMS];   // [B*H, N, D], pre-scaled
__device__ __nv_bfloat16 g_khi[QKV_ELEMS], g_klo[QKV_ELEMS];   // [B*H, N, D]
__device__ __nv_bfloat16 g_vthi[QKV_ELEMS], g_vtlo[QKV_ELEMS]; // [B*H, D, N] (transposed)
__device__ __nv_bfloat16 g_ohi[X_ELEMS], g_olo[X_ELEMS];       // [B*N, C]

// ---------------- helpers ----------------
__device__ __forceinline__ u32 smem_u32(const void* p){
    u32 a; asm("{ .reg .u64 t; cvta.to.shared.u64 t, %1; cvt.u32.u64 %0, t; }" : "=r"(a) : "l"(p));
    return a;
}
__device__ __forceinline__ u32 bfpair(__nv_bfloat16 a, __nv_bfloat16 b){
    u32 lo = (u32)__bfloat16_as_ushort(a);
    u32 hi = (u32)__bfloat16_as_ushort(b);
    return lo | (hi << 16);
}
__device__ __forceinline__ void split1(float x, __nv_bfloat16& h, __nv_bfloat16& l){
    h = __float2bfloat16(x);
    l = __float2bfloat16(x - __bfloat162float(h));
}

// fast exp on the FMA pipe (no MUFU), x <= ~0
__device__ __forceinline__ float fast_exp(float x){
    x = fmaxf(x, -80.0f);
    float t  = x * 1.4426950408889634f;
    float tr = t + 12582912.0f;
    int   n  = __float_as_int(tr) - 0x4B400000;
    float rn = tr - 12582912.0f;
    float f  = t - rn;
    float p = 1.3333558146428443e-3f;
    p = fmaf(p, f, 9.618129107628477e-3f);
    p = fmaf(p, f, 5.550410866482158e-2f);
    p = fmaf(p, f, 2.402265069591007e-1f);
    p = fmaf(p, f, 6.931471805599453e-1f);
    p = fmaf(p, f, 1.0f);
    return p * __int_as_float((n + 127) << 23);
}

// ---------------- mma/ldsm/cp.async primitives ----------------
__device__ __forceinline__ void ldsm4(u32* r, u32 addr){
    asm volatile("ldmatrix.sync.aligned.m8n8.x4.shared.b16 {%0,%1,%2,%3}, [%4];"
        : "=r"(r[0]), "=r"(r[1]), "=r"(r[2]), "=r"(r[3]) : "r"(addr));
}
__device__ __forceinline__ void mma_bf16(float* c, const u32* a, u32 b0, u32 b1){
    asm volatile("mma.sync.aligned.m16n8k16.row.col.f32.bf16.bf16.f32 "
        "{%0,%1,%2,%3}, {%4,%5,%6,%7}, {%8,%9}, {%0,%1,%2,%3};"
        : "+f"(c[0]), "+f"(c[1]), "+f"(c[2]), "+f"(c[3])
        : "r"(a[0]), "r"(a[1]), "r"(a[2]), "r"(a[3]), "r"(b0), "r"(b1));
}
__device__ __forceinline__ void cp16(u32 dst, const void* src){
    asm volatile("cp.async.cg.shared.global [%0], [%1], 16;" :: "r"(dst), "l"(src));
}
__device__ __forceinline__ void cp_commit(){ asm volatile("cp.async.commit_group;" ::: "memory"); }
template<int N> __device__ __forceinline__ void cp_wait(){
    asm volatile("cp.async.wait_group %0;" :: "n"(N) : "memory");
}

// =====================================================================
// Prep: split f32 arrays into bf16 hi/lo pairs in gmem
// =====================================================================
__global__ __launch_bounds__(256) void split_kernel(const float* __restrict__ src, int mode, int n)
{
    __nv_bfloat16 *hp, *lp;
    if (mode == 0){ hp = g_xhi; lp = g_xlo; }
    else if (mode == 1){ hp = g_wqh; lp = g_wql; }
    else { hp = g_wph; lp = g_wpl; }
    int i = (blockIdx.x*blockDim.x + threadIdx.x)*4;
    if (i >= n) return;
    float4 v = *(const float4*)(src + i);
    __nv_bfloat16 h0,h1,h2,h3,l0,l1,l2,l3;
    split1(v.x,h0,l0); split1(v.y,h1,l1); split1(v.z,h2,l2); split1(v.w,h3,l3);
    *(u32*)(hp+i)   = bfpair(h0,h1);
    *(u32*)(hp+i+2) = bfpair(h2,h3);
    *(u32*)(lp+i)   = bfpair(l0,l1);
    *(u32*)(lp+i+2) = bfpair(l2,l3);
}

// =====================================================================
// bf16x3 mma.sync GEMM. Block 128x128, BK=32, 2-stage cp.async
// double-buffer with one-chunk prefetch. 8 warps (4M x 2N).
// Row pitch 80 bytes (16B-aligned; 20 words -> conflict-free ldsm).
// mode 0: A=x, B=w_qkv -> q(split,scaled)/k(split)/vT(split,transposed).
// mode 1: A=O(split), B=w_proj, out = C + bias (f32).
// =====================================================================
#define GP          80                    // bytes per row (5*16)
#define TILE2_B     (128*GP)              // 10240
#define STAGE2_B    (4*TILE2_B)           // 40960 (Ah, Al, Bh, Bl)
#define GEMM_SMEM   (2*STAGE2_B)          // 81920

__global__ __launch_bounds__(256, 2) void mma_gemm_kernel(
    const float* __restrict__ bias, float* __restrict__ out, int mode)
{
    extern __shared__ __nv_bfloat16 smb[];
    const __nv_bfloat16 *Ahi, *Alo, *Bhi, *Blo;
    if (mode == 0){ Ahi = g_xhi; Alo = g_xlo; Bhi = g_wqh; Blo = g_wql; }
    else          { Ahi = g_ohi; Alo = g_olo; Bhi = g_wph; Blo = g_wpl; }

    int tid = threadIdx.x;
    int lane = tid & 31, warp = tid >> 5;
    int wm = warp & 3, wn = warp >> 2;
    int m0 = blockIdx.y * 128, n0 = blockIdx.x * 128;

    u32 sbase = smem_u32(smb);
    u32 aoff = (u32)((wm*32 + (lane & 15))*GP + (lane >> 4)*16);
    u32 boff = (u32)((wn*64 + (lane & 7) + ((lane >> 4) & 1)*8)*GP + ((lane >> 3) & 1)*16);

    float c[2][8][4];
    #pragma unroll
    for (int i = 0; i < 2; i++)
        #pragma unroll
        for (int j = 0; j < 8; j++)
            #pragma unroll
            for (int q = 0; q < 4; q++) c[i][j][q] = 0.0f;

    auto load_chunk = [&](int chunk){
        int st = chunk & 1;
        u32 stb = sbase + st*STAGE2_B;
        int kf = chunk*32;
        #pragma unroll
        for (int it = 0; it < 8; it++){
            int f = tid + 256*it;
            int tile = it >> 1;                // 0:Ah 1:Al 2:Bh 3:Bl
            int fr = f & 511;
            int row = fr >> 2, qtr = fr & 3;
            const __nv_bfloat16* src;
            if (tile == 0)      src = Ahi + (size_t)(m0 + row)*768 + kf + qtr*8;
            else if (tile == 1) src = Alo + (size_t)(m0 + row)*768 + kf + qtr*8;
            else if (tile == 2) src = Bhi + (size_t)(n0 + row)*768 + kf + qtr*8;
            else                src = Blo + (size_t)(n0 + row)*768 + kf + qtr*8;
            cp16(stb + tile*TILE2_B + row*GP + qtr*16, src);
        }
        cp_commit();
    };

    load_chunk(0);

    #pragma unroll 1
    for (int i = 0; i < 24; i++){
        __syncthreads();                       // prev-iter reads of target buffer done
        if (i + 1 < 24) load_chunk(i + 1);     // prefetch into other buffer
        if (i + 1 < 24) cp_wait<1>();
        else            cp_wait<0>();
        __syncthreads();

        u32 stb = sbase + (i & 1)*STAGE2_B;
        #pragma unroll
        for (int kc = 0; kc < 2; kc++){
            u32 ah[2][4], al[2][4], bh4[4][4];
            #pragma unroll
            for (int fm = 0; fm < 2; fm++){
                ldsm4(ah[fm], stb + aoff + fm*(16*GP) + kc*32);
                ldsm4(al[fm], stb + TILE2_B + aoff + fm*(16*GP) + kc*32);
            }
            #pragma unroll
            for (int i4 = 0; i4 < 4; i4++)
                ldsm4(bh4[i4], stb + 2*TILE2_B + boff + i4*(16*GP) + kc*32);

            #pragma unroll
            for (int i4 = 0; i4 < 4; i4++)
                #pragma unroll
                for (int fm = 0; fm < 2; fm++){
                    mma_bf16(c[fm][2*i4+0], ah[fm], bh4[i4][0], bh4[i4][1]);
                    mma_bf16(c[fm][2*i4+1], ah[fm], bh4[i4][2], bh4[i4][3]);
                }
            #pragma unroll
            for (int i4 = 0; i4 < 4; i4++)
                #pragma unroll
                for (int fm = 0; fm < 2; fm++){
                    mma_bf16(c[fm][2*i4+0], al[fm], bh4[i4][0], bh4[i4][1]);
                    mma_bf16(c[fm][2*i4+1], al[fm], bh4[i4][2], bh4[i4][3]);
                }
            #pragma unroll
            for (int i4 = 0; i4 < 4; i4++){
                u32 bl4[4];
                ldsm4(bl4, stb + 3*TILE2_B + boff + i4*(16*GP) + kc*32);
                #pragma unroll
                for (int fm = 0; fm < 2; fm++){
                    mma_bf16(c[fm][2*i4+0], ah[fm], bl4[0], bl4[1]);
                    mma_bf16(c[fm][2*i4+1], ah[fm], bl4[2], bl4[3]);
                }
            }
        }
    }

    // ---------------- epilogue ----------------
    int g = lane >> 2, tig = lane & 3;
    int colbase = n0 + wn*64;
    if (mode == 0){
        int hblk = colbase >> 6;
        int t_sel = hblk / NHEADS;
        int h     = hblk - t_sel*NHEADS;
        float sc  = (t_sel == 0) ? ATT_SCALE : 1.0f;
        #pragma unroll
        for (int fm = 0; fm < 2; fm++){
            int row0 = m0 + wm*32 + fm*16 + g;
            #pragma unroll
            for (int half = 0; half < 2; half++){
                int row = row0 + half*8;
                int b = row >> 10, n = row & 1023;
                int bh_i = b*NHEADS + h;
                if (t_sel == 2){
                    size_t vb = (size_t)bh_i*NHD*NSEQ + n;
                    #pragma unroll
                    for (int nf = 0; nf < 8; nf++){
                        int d0 = nf*8 + tig*2;
                        float x0 = c[fm][nf][half*2], x1 = c[fm][nf][half*2+1];
                        __nv_bfloat16 h0,h1,l0,l1;
                        split1(x0,h0,l0); split1(x1,h1,l1);
                        g_vthi[vb + (size_t)d0*NSEQ]     = h0;
                        g_vthi[vb + (size_t)(d0+1)*NSEQ] = h1;
                        g_vtlo[vb + (size_t)d0*NSEQ]     = l0;
                        g_vtlo[vb + (size_t)(d0+1)*NSEQ] = l1;
                    }
                } else {
                    size_t base_e = ((size_t)bh_i*NSEQ + n)*NHD;
                    __nv_bfloat16* hip = (t_sel == 0) ? g_qhi : g_khi;
                    __nv_bfloat16* lop = (t_sel == 0) ? g_qlo : g_klo;
                    #pragma unroll
                    for (int nf = 0; nf < 8; nf++){
                        int d0 = nf*8 + tig*2;
                        float x0 = c[fm][nf][half*2]*sc, x1 = c[fm][nf][half*2+1]*sc;
                        __nv_bfloat16 h0,h1,l0,l1;
                        split1(x0,h0,l0); split1(x1,h1,l1);
                        *(u32*)(hip + base_e + d0) = bfpair(h0,h1);
                        *(u32*)(lop + base_e + d0) = bfpair(l0,l1);
                    }
                }
            }
        }
    } else {
        #pragma unroll
        for (int fm = 0; fm < 2; fm++){
            int row0 = m0 + wm*32 + fm*16 + g;
            #pragma unroll
            for (int half = 0; half < 2; half++){
                int row = row0 + half*8;
                float* base = out + (size_t)row*768 + colbase;
                #pragma unroll
                for (int nf = 0; nf < 8; nf++){
                    int cg = nf*8 + tig*2;
                    float2 bv = *(const float2*)(bias + colbase + cg);
                    *(float2*)(base + cg) =
                        make_float2(c[fm][nf][half*2] + bv.x,
                                    c[fm][nf][half*2+1] + bv.y);
                }
            }
        }
    }
}

// =====================================================================
// Flash attention, bf16x3 mma.sync, register P, pre-transposed V,
// double-buffered K/V with one-iteration cp.async prefetch.
// BQ=128 (8 warps x m16), BKV=64, D=64. Pitch 144B.
// =====================================================================
#define FPB        72                    // bf16 per row
#define QT_B       (128*144)             // 18432 bytes per Q tile
#define KT_B       (64*144)              // 9216 bytes per KV tile
#define KVBUF_B    (4*KT_B)              // 36864 (Kh, Kl, Vh, Vl)
#define FLASH_SMEM (2*QT_B + 2*KVBUF_B)  // 110592

__global__ __launch_bounds__(256, 2) void flash_mma_kernel()
{
    extern __shared__ __nv_bfloat16 fbm[];
    int tid = threadIdx.x, lane = tid & 31, warp = tid >> 5;
    int q0 = blockIdx.x * 128;
    int bh = blockIdx.y;
    size_t hb  = (size_t)bh * NSEQ * NHD;   // q/k base
    size_t hvt = (size_t)bh * NHD * NSEQ;   // vt base

    u32 fbase = smem_u32(fbm);
    u32 qhb = fbase, qlb = fbase + QT_B;
    u32 kvb = fbase + 2*QT_B;

    u32 aoffp = (u32)((warp*16 + (lane & 15))*144 + (lane >> 4)*16);
    u32 boffp = (u32)(((lane & 7) + ((lane >> 4) & 1)*8)*144 + ((lane >> 3) & 1)*16);

    // Q hi/lo (one group)
    #pragma unroll
    for (int it = 0; it < 8; it++){
        int f = tid + 256*it;
        int tile = it >> 2;
        int fr = f & 1023;
        int row = fr >> 3, half = fr & 7;
        const __nv_bfloat16* sp = (tile ? g_qlo : g_qhi) + hb + (size_t)(q0 + row)*NHD + half*8;
        cp16((tile ? qlb : qhb) + row*144 + half*16, sp);
    }
    cp_commit();

    auto load_kv = [&](int t, int buf){
        int c0 = t * 64;
        u32 bb = kvb + buf*KVBUF_B;
        #pragma unroll
        for (int it = 0; it < 8; it++){
            int f = tid + 256*it;
            int tile = it >> 1;                 // 0:Kh 1:Kl 2:Vh 3:Vl
            int fr = f & 511;
            int row = fr >> 3, half = fr & 7;
            const __nv_bfloat16* sp;
            if (tile == 0)      sp = g_khi  + hb  + (size_t)(c0 + row)*NHD + half*8;
            else if (tile == 1) sp = g_klo  + hb  + (size_t)(c0 + row)*NHD + half*8;
            else if (tile == 2) sp = g_vthi + hvt + (size_t)row*NSEQ + c0 + half*8;
            else                sp = g_vtlo + hvt + (size_t)row*NSEQ + c0 + half*8;
            cp16(bb + tile*KT_B + row*144 + half*16, sp);
        }
        cp_commit();
    };

    load_kv(0, 0);

    float o[8][4];
    #pragma unroll
    for (int j = 0; j < 8; j++)
        #pragma unroll
        for (int q = 0; q < 4; q++) o[j][q] = 0.0f;
    float m0f = -1e30f, m1f = -1e30f, l0s = 0.0f, l1s = 0.0f;

    #pragma unroll 1
    for (int t = 0; t < 16; t++){
        __syncthreads();                        // prev-iter reads of target buffer done
        if (t + 1 < 16) load_kv(t + 1, (t + 1) & 1);
        if (t + 1 < 16) cp_wait<1>();
        else            cp_wait<0>();
        __syncthreads();

        u32 bb  = kvb + (t & 1)*KVBUF_B;
        u32 khb = bb, klb = bb + KT_B, vhb = bb + 2*KT_B, vlb = bb + 3*KT_B;

        // ---- S = Q K^T (bf16x3, 3-pass) ----
        float s[8][4];
        #pragma unroll
        for (int j = 0; j < 8; j++)
            #pragma unroll
            for (int q = 0; q < 4; q++) s[j][q] = 0.0f;

        #pragma unroll
        for (int kc = 0; kc < 4; kc++){
            u32 qh4[4], ql4[4], kh4[4][4];
            ldsm4(qh4, qhb + aoffp + kc*32);
            ldsm4(ql4, qlb + aoffp + kc*32);
            #pragma unroll
            for (int i4 = 0; i4 < 4; i4++)
                ldsm4(kh4[i4], khb + boffp + i4*(16*144) + kc*32);
            #pragma unroll
            for (int i4 = 0; i4 < 4; i4++){
                mma_bf16(s[2*i4+0], qh4, kh4[i4][0], kh4[i4][1]);
                mma_bf16(s[2*i4+1], qh4, kh4[i4][2], kh4[i4][3]);
            }
            #pragma unroll
            for (int i4 = 0; i4 < 4; i4++){
                mma_bf16(s[2*i4+0], ql4, kh4[i4][0], kh4[i4][1]);
                mma_bf16(s[2*i4+1], ql4, kh4[i4][2], kh4[i4][3]);
            }
            #pragma unroll
            for (int i4 = 0; i4 < 4; i4++){
                u32 kl4[4];
                ldsm4(kl4, klb + boffp + i4*(16*144) + kc*32);
                mma_bf16(s[2*i4+0], qh4, kl4[0], kl4[1]);
                mma_bf16(s[2*i4+1], qh4, kl4[2], kl4[3]);
            }
        }

        // ---- streaming softmax (in-place exp into s) ----
        float mx0 = -1e30f, mx1 = -1e30f;
        #pragma unroll
        for (int j = 0; j < 8; j++){
            mx0 = fmaxf(mx0, fmaxf(s[j][0], s[j][1]));
            mx1 = fmaxf(mx1, fmaxf(s[j][2], s[j][3]));
        }
        #pragma unroll
        for (int off = 1; off <= 2; off <<= 1){
            mx0 = fmaxf(mx0, __shfl_xor_sync(0xffffffffu, mx0, off));
            mx1 = fmaxf(mx1, __shfl_xor_sync(0xffffffffu, mx1, off));
        }
        float mn0 = fmaxf(m0f, mx0), mn1 = fmaxf(m1f, mx1);
        float corr0 = fast_exp(m0f - mn0), corr1 = fast_exp(m1f - mn1);
        m0f = mn0; m1f = mn1;

        float sum0 = 0.0f, sum1 = 0.0f;
        #pragma unroll
        for (int j = 0; j < 8; j++){
            s[j][0] = fast_exp(s[j][0] - mn0);
            s[j][1] = fast_exp(s[j][1] - mn0);
            s[j][2] = fast_exp(s[j][2] - mn1);
            s[j][3] = fast_exp(s[j][3] - mn1);
            sum0 += s[j][0] + s[j][1];
            sum1 += s[j][2] + s[j][3];
        }
        #pragma unroll
        for (int off = 1; off <= 2; off <<= 1){
            sum0 += __shfl_xor_sync(0xffffffffu, sum0, off);
            sum1 += __shfl_xor_sync(0xffffffffu, sum1, off);
        }
        l0s = l0s*corr0 + sum0;
        l1s = l1s*corr1 + sum1;
        #pragma unroll
        for (int j = 0; j < 8; j++){
            o[j][0] *= corr0; o[j][1] *= corr0;
            o[j][2] *= corr1; o[j][3] *= corr1;
        }

        // ---- O += P V (register P; bf16x3, 3-pass) ----
        #pragma unroll
        for (int kc = 0; kc < 4; kc++){
            u32 ph4[4], pl4[4];
            {
                __nv_bfloat16 h0,h1,l0,l1;
                split1(s[2*kc][0], h0, l0); split1(s[2*kc][1], h1, l1);
                ph4[0] = bfpair(h0,h1); pl4[0] = bfpair(l0,l1);
                split1(s[2*kc][2], h0, l0); split1(s[2*kc][3], h1, l1);
                ph4[1] = bfpair(h0,h1); pl4[1] = bfpair(l0,l1);
                split1(s[2*kc+1][0], h0, l0); split1(s[2*kc+1][1], h1, l1);
                ph4[2] = bfpair(h0,h1); pl4[2] = bfpair(l0,l1);
                split1(s[2*kc+1][2], h0, l0); split1(s[2*kc+1][3], h1, l1);
                ph4[3] = bfpair(h0,h1); pl4[3] = bfpair(l0,l1);
            }
            u32 vh4[4][4];
            #pragma unroll
            for (int i4 = 0; i4 < 4; i4++)
                ldsm4(vh4[i4], vhb + boffp + i4*(16*144) + kc*32);
            #pragma unroll
            for (int i4 = 0; i4 < 4; i4++){
                mma_bf16(o[2*i4+0], ph4, vh4[i4][0], vh4[i4][1]);
                mma_bf16(o[2*i4+1], ph4, vh4[i4][2], vh4[i4][3]);
            }
            #pragma unroll
            for (int i4 = 0; i4 < 4; i4++){
                mma_bf16(o[2*i4+0], pl4, vh4[i4][0], vh4[i4][1]);
                mma_bf16(o[2*i4+1], pl4, vh4[i4][2], vh4[i4][3]);
            }
            #pragma unroll
            for (int i4 = 0; i4 < 4; i4++){
                u32 vl4[4];
                ldsm4(vl4, vlb + boffp + i4*(16*144) + kc*32);
                mma_bf16(o[2*i4+0], ph4, vl4[0], vl4[1]);
                mma_bf16(o[2*i4+1], ph4, vl4[2], vl4[3]);
            }
        }
    }

    // ---- finalize: O /= l, split, write g_ohi/g_olo[b*N+n][h*64+d] ----
    int b = bh / NHEADS, h = bh % NHEADS;
    float inv0 = 1.0f / l0s, inv1 = 1.0f / l1s;
    int r0 = lane >> 2, colq = 2*(lane & 3);
    int gq0 = q0 + warp*16 + r0;
    size_t base0 = (size_t)(b*NSEQ + gq0    )*NDIM + h*NHD;
    size_t base1 = (size_t)(b*NSEQ + gq0 + 8)*NDIM + h*NHD;
    #pragma unroll
    for (int j = 0; j < 8; j++){
        int d0 = 8*j + colq;
        float x0 = o[j][0]*inv0, x1 = o[j][1]*inv0;
        float y0 = o[j][2]*inv1, y1 = o[j][3]*inv1;
        __nv_bfloat16 hx0,hx1,hy0,hy1,lx0,lx1,ly0,ly1;
        split1(x0,hx0,lx0); split1(x1,hx1,lx1);
        split1(y0,hy0,ly0); split1(y1,hy1,ly1);
        *(u32*)(g_ohi + base0 + d0) = bfpair(hx0,hx1);
        *(u32*)(g_olo + base0 + d0) = bfpair(lx0,lx1);
        *(u32*)(g_ohi + base1 + d0) = bfpair(hy0,hy1);
        *(u32*)(g_olo + base1 + d0) = bfpair(ly0,ly1);
    }
}

// =====================================================================
extern "C" void kernel_launch(void* const* d_in, const int* in_sizes, int n_in,
                              void* d_out, int out_size)
{
    const float* x      = (const float*)d_in[0];
    const float* w_qkv  = (const float*)d_in[1];
    const float* w_proj = (const float*)d_in[2];
    const float* b_proj = (const float*)d_in[3];
    float* out = (float*)d_out;

    cudaFuncSetAttribute(mma_gemm_kernel, cudaFuncAttributeMaxDynamicSharedMemorySize, GEMM_SMEM);
    cudaFuncSetAttribute(flash_mma_kernel, cudaFuncAttributeMaxDynamicSharedMemorySize, FLASH_SMEM);

    split_kernel<<<X_ELEMS/1024, 256>>>(x, 0, X_ELEMS);
    split_kernel<<<(2304*768)/1024, 256>>>(w_qkv, 1, 2304*768);
    split_kernel<<<(768*768)/1024, 256>>>(w_proj, 2, 768*768);
    mma_gemm_kernel<<<dim3(2304/128, 16384/128), 256, GEMM_SMEM>>>(nullptr, nullptr, 0);
    flash_mma_kernel<<<dim3(NSEQ/128, NBATCH*NHEADS), 256, FLASH_SMEM>>>();
    mma_gemm_kernel<<<dim3(768/128, 16384/128), 256, GEMM_SMEM>>>(b_proj, out, 1);
}

// round 10
// speedup vs baseline: 2.6506x; 1.0014x over previous
#include <cuda_runtime.h>
#include <cuda_bf16.h>
#include <cstdint>

typedef unsigned long long u64;
typedef unsigned int u32;

#define NBATCH 16
#define NSEQ   1024
#define NDIM   768
#define NHEADS 12
#define NHD    64
#define ATT_SCALE 0.125f
#define QKV_ELEMS (NBATCH*NHEADS*NSEQ*NHD)    // 12582912
#define X_ELEMS   (NBATCH*NSEQ*NDIM)          // 12582912

// ---------------- static scratch (allocation-free) ----------------
__device__ __nv_bfloat16 g_xhi[X_ELEMS], g_xlo[X_ELEMS];
__device__ __nv_bfloat16 g_wqh[2304*768], g_wql[2304*768];
__device__ __nv_bfloat16 g_wph[768*768],  g_wpl[768*768];
__device__ __nv_bfloat16 g_qhi[QKV_ELEMS], g_qlo[QKV_ELEMS];   // [B*H, N, D], pre-scaled
__device__ __nv_bfloat16 g_khi[QKV_ELEMS], g_klo[QKV_ELEMS];   // [B*H, N, D]
__device__ __nv_bfloat16 g_vthi[QKV_ELEMS], g_vtlo[QKV_ELEMS]; // [B*H, D, N] (transposed)
__device__ __nv_bfloat16 g_ohi[X_ELEMS], g_olo[X_ELEMS];       // [B*N, C]

// ---------------- helpers ----------------
__device__ __forceinline__ u32 smem_u32(const void* p){
    u32 a; asm("{ .reg .u64 t; cvta.to.shared.u64 t, %1; cvt.u32.u64 %0, t; }" : "=r"(a) : "l"(p));
    return a;
}
__device__ __forceinline__ u32 bfpair(__nv_bfloat16 a, __nv_bfloat16 b){
    u32 lo = (u32)__bfloat16_as_ushort(a);
    u32 hi = (u32)__bfloat16_as_ushort(b);
    return lo | (hi << 16);
}
__device__ __forceinline__ void split1(float x, __nv_bfloat16& h, __nv_bfloat16& l){
    h = __float2bfloat16(x);
    l = __float2bfloat16(x - __bfloat162float(h));
}

// fast exp on the FMA pipe (no MUFU), x <= ~0
__device__ __forceinline__ float fast_exp(float x){
    x = fmaxf(x, -80.0f);
    float t  = x * 1.4426950408889634f;
    float tr = t + 12582912.0f;
    int   n  = __float_as_int(tr) - 0x4B400000;
    float rn = tr - 12582912.0f;
    float f  = t - rn;
    float p = 1.3333558146428443e-3f;
    p = fmaf(p, f, 9.618129107628477e-3f);
    p = fmaf(p, f, 5.550410866482158e-2f);
    p = fmaf(p, f, 2.402265069591007e-1f);
    p = fmaf(p, f, 6.931471805599453e-1f);
    p = fmaf(p, f, 1.0f);
    return p * __int_as_float((n + 127) << 23);
}

// ---------------- mma/ldsm/cp.async primitives ----------------
__device__ __forceinline__ void ldsm4(u32* r, u32 addr){
    asm volatile("ldmatrix.sync.aligned.m8n8.x4.shared.b16 {%0,%1,%2,%3}, [%4];"
        : "=r"(r[0]), "=r"(r[1]), "=r"(r[2]), "=r"(r[3]) : "r"(addr));
}
__device__ __forceinline__ void mma_bf16(float* c, const u32* a, u32 b0, u32 b1){
    asm volatile("mma.sync.aligned.m16n8k16.row.col.f32.bf16.bf16.f32 "
        "{%0,%1,%2,%3}, {%4,%5,%6,%7}, {%8,%9}, {%0,%1,%2,%3};"
        : "+f"(c[0]), "+f"(c[1]), "+f"(c[2]), "+f"(c[3])
        : "r"(a[0]), "r"(a[1]), "r"(a[2]), "r"(a[3]), "r"(b0), "r"(b1));
}
__device__ __forceinline__ void cp16(u32 dst, const void* src){
    asm volatile("cp.async.cg.shared.global [%0], [%1], 16;" :: "r"(dst), "l"(src));
}
__device__ __forceinline__ void cp_commit(){ asm volatile("cp.async.commit_group;" ::: "memory"); }
template<int N> __device__ __forceinline__ void cp_wait(){
    asm volatile("cp.async.wait_group %0;" :: "n"(N) : "memory");
}

// =====================================================================
// Prep: split f32 arrays into bf16 hi/lo pairs in gmem
// =====================================================================
__global__ __launch_bounds__(256) void split_kernel(const float* __restrict__ src, int mode, int n)
{
    __nv_bfloat16 *hp, *lp;
    if (mode == 0){ hp = g_xhi; lp = g_xlo; }
    else if (mode == 1){ hp = g_wqh; lp = g_wql; }
    else { hp = g_wph; lp = g_wpl; }
    int i = (blockIdx.x*blockDim.x + threadIdx.x)*4;
    if (i >= n) return;
    float4 v = *(const float4*)(src + i);
    __nv_bfloat16 h0,h1,h2,h3,l0,l1,l2,l3;
    split1(v.x,h0,l0); split1(v.y,h1,l1); split1(v.z,h2,l2); split1(v.w,h3,l3);
    *(u32*)(hp+i)   = bfpair(h0,h1);
    *(u32*)(hp+i+2) = bfpair(h2,h3);
    *(u32*)(lp+i)   = bfpair(l0,l1);
    *(u32*)(lp+i+2) = bfpair(l2,l3);
}

// =====================================================================
// bf16x3 mma.sync GEMM. Block 128x128, BK=32, 2-stage cp.async
// double-buffer with one-chunk prefetch. 8 warps (4M x 2N).
// Row pitch 80 bytes (16B-aligned; 20 words -> conflict-free ldsm).
// mode 0: A=x, B=w_qkv -> q(split,scaled)/k(split)/vT(split,transposed).
// mode 1: A=O(split), B=w_proj, out = C + bias (f32).
// =====================================================================
#define GP          80                    // bytes per row (5*16)
#define TILE2_B     (128*GP)              // 10240
#define STAGE2_B    (4*TILE2_B)           // 40960 (Ah, Al, Bh, Bl)
#define GEMM_SMEM   (2*STAGE2_B)          // 81920

__global__ __launch_bounds__(256, 2) void mma_gemm_kernel(
    const float* __restrict__ bias, float* __restrict__ out, int mode)
{
    extern __shared__ __nv_bfloat16 smb[];
    const __nv_bfloat16 *Ahi, *Alo, *Bhi, *Blo;
    if (mode == 0){ Ahi = g_xhi; Alo = g_xlo; Bhi = g_wqh; Blo = g_wql; }
    else          { Ahi = g_ohi; Alo = g_olo; Bhi = g_wph; Blo = g_wpl; }

    int tid = threadIdx.x;
    int lane = tid & 31, warp = tid >> 5;
    int wm = warp & 3, wn = warp >> 2;
    int m0 = blockIdx.y * 128, n0 = blockIdx.x * 128;

    u32 sbase = smem_u32(smb);
    u32 aoff = (u32)((wm*32 + (lane & 15))*GP + (lane >> 4)*16);
    u32 boff = (u32)((wn*64 + (lane & 7) + ((lane >> 4) & 1)*8)*GP + ((lane >> 3) & 1)*16);

    float c[2][8][4];
    #pragma unroll
    for (int i = 0; i < 2; i++)
        #pragma unroll
        for (int j = 0; j < 8; j++)
            #pragma unroll
            for (int q = 0; q < 4; q++) c[i][j][q] = 0.0f;

    auto load_chunk = [&](int chunk){
        int st = chunk & 1;
        u32 stb = sbase + st*STAGE2_B;
        int kf = chunk*32;
        #pragma unroll
        for (int it = 0; it < 8; it++){
            int f = tid + 256*it;
            int tile = it >> 1;                // 0:Ah 1:Al 2:Bh 3:Bl
            int fr = f & 511;
            int row = fr >> 2, qtr = fr & 3;
            const __nv_bfloat16* src;
            if (tile == 0)      src = Ahi + (size_t)(m0 + row)*768 + kf + qtr*8;
            else if (tile == 1) src = Alo + (size_t)(m0 + row)*768 + kf + qtr*8;
            else if (tile == 2) src = Bhi + (size_t)(n0 + row)*768 + kf + qtr*8;
            else                src = Blo + (size_t)(n0 + row)*768 + kf + qtr*8;
            cp16(stb + tile*TILE2_B + row*GP + qtr*16, src);
        }
        cp_commit();
    };

    load_chunk(0);

    #pragma unroll 1
    for (int i = 0; i < 24; i++){
        __syncthreads();                       // prev-iter reads of target buffer done
        if (i + 1 < 24) load_chunk(i + 1);     // prefetch into other buffer
        if (i + 1 < 24) cp_wait<1>();
        else            cp_wait<0>();
        __syncthreads();

        u32 stb = sbase + (i & 1)*STAGE2_B;
        #pragma unroll
        for (int kc = 0; kc < 2; kc++){
            u32 ah[2][4], al[2][4], bh4[4][4];
            #pragma unroll
            for (int fm = 0; fm < 2; fm++){
                ldsm4(ah[fm], stb + aoff + fm*(16*GP) + kc*32);
                ldsm4(al[fm], stb + TILE2_B + aoff + fm*(16*GP) + kc*32);
            }
            #pragma unroll
            for (int i4 = 0; i4 < 4; i4++)
                ldsm4(bh4[i4], stb + 2*TILE2_B + boff + i4*(16*GP) + kc*32);

            #pragma unroll
            for (int i4 = 0; i4 < 4; i4++)
                #pragma unroll
                for (int fm = 0; fm < 2; fm++){
                    mma_bf16(c[fm][2*i4+0], ah[fm], bh4[i4][0], bh4[i4][1]);
                    mma_bf16(c[fm][2*i4+1], ah[fm], bh4[i4][2], bh4[i4][3]);
                }
            #pragma unroll
            for (int i4 = 0; i4 < 4; i4++)
                #pragma unroll
                for (int fm = 0; fm < 2; fm++){
                    mma_bf16(c[fm][2*i4+0], al[fm], bh4[i4][0], bh4[i4][1]);
                    mma_bf16(c[fm][2*i4+1], al[fm], bh4[i4][2], bh4[i4][3]);
                }
            #pragma unroll
            for (int i4 = 0; i4 < 4; i4++){
                u32 bl4[4];
                ldsm4(bl4, stb + 3*TILE2_B + boff + i4*(16*GP) + kc*32);
                #pragma unroll
                for (int fm = 0; fm < 2; fm++){
                    mma_bf16(c[fm][2*i4+0], ah[fm], bl4[0], bl4[1]);
                    mma_bf16(c[fm][2*i4+1], ah[fm], bl4[2], bl4[3]);
                }
            }
        }
    }

    // ---------------- epilogue ----------------
    int g = lane >> 2, tig = lane & 3;
    int colbase = n0 + wn*64;
    if (mode == 0){
        int hblk = colbase >> 6;
        int t_sel = hblk / NHEADS;
        int h     = hblk - t_sel*NHEADS;
        float sc  = (t_sel == 0) ? ATT_SCALE : 1.0f;
        #pragma unroll
        for (int fm = 0; fm < 2; fm++){
            int row0 = m0 + wm*32 + fm*16 + g;
            #pragma unroll
            for (int half = 0; half < 2; half++){
                int row = row0 + half*8;
                int b = row >> 10, n = row & 1023;
                int bh_i = b*NHEADS + h;
                if (t_sel == 2){
                    size_t vb = (size_t)bh_i*NHD*NSEQ + n;
                    #pragma unroll
                    for (int nf = 0; nf < 8; nf++){
                        int d0 = nf*8 + tig*2;
                        float x0 = c[fm][nf][half*2], x1 = c[fm][nf][half*2+1];
                        __nv_bfloat16 h0,h1,l0,l1;
                        split1(x0,h0,l0); split1(x1,h1,l1);
                        g_vthi[vb + (size_t)d0*NSEQ]     = h0;
                        g_vthi[vb + (size_t)(d0+1)*NSEQ] = h1;
                        g_vtlo[vb + (size_t)d0*NSEQ]     = l0;
                        g_vtlo[vb + (size_t)(d0+1)*NSEQ] = l1;
                    }
                } else {
                    size_t base_e = ((size_t)bh_i*NSEQ + n)*NHD;
                    __nv_bfloat16* hip = (t_sel == 0) ? g_qhi : g_khi;
                    __nv_bfloat16* lop = (t_sel == 0) ? g_qlo : g_klo;
                    #pragma unroll
                    for (int nf = 0; nf < 8; nf++){
                        int d0 = nf*8 + tig*2;
                        float x0 = c[fm][nf][half*2]*sc, x1 = c[fm][nf][half*2+1]*sc;
                        __nv_bfloat16 h0,h1,l0,l1;
                        split1(x0,h0,l0); split1(x1,h1,l1);
                        *(u32*)(hip + base_e + d0) = bfpair(h0,h1);
                        *(u32*)(lop + base_e + d0) = bfpair(l0,l1);
                    }
                }
            }
        }
    } else {
        #pragma unroll
        for (int fm = 0; fm < 2; fm++){
            int row0 = m0 + wm*32 + fm*16 + g;
            #pragma unroll
            for (int half = 0; half < 2; half++){
                int row = row0 + half*8;
                float* base = out + (size_t)row*768 + colbase;
                #pragma unroll
                for (int nf = 0; nf < 8; nf++){
                    int cg = nf*8 + tig*2;
                    float2 bv = *(const float2*)(bias + colbase + cg);
                    *(float2*)(base + cg) =
                        make_float2(c[fm][nf][half*2] + bv.x,
                                    c[fm][nf][half*2+1] + bv.y);
                }
            }
        }
    }
}

// =====================================================================
// Flash attention, bf16x3 mma.sync, register P, pre-transposed V,
// double-buffered K/V with one-iteration cp.async prefetch.
// BQ=128 (8 warps x m16), BKV=64, D=64. Pitch 144B.
// =====================================================================
#define FPB        72                    // bf16 per row
#define QT_B       (128*144)             // 18432 bytes per Q tile
#define KT_B       (64*144)              // 9216 bytes per KV tile
#define KVBUF_B    (4*KT_B)              // 36864 (Kh, Kl, Vh, Vl)
#define FLASH_SMEM (2*QT_B + 2*KVBUF_B)  // 110592

__global__ __launch_bounds__(256, 2) void flash_mma_kernel()
{
    extern __shared__ __nv_bfloat16 fbm[];
    int tid = threadIdx.x, lane = tid & 31, warp = tid >> 5;
    int q0 = blockIdx.x * 128;
    int bh = blockIdx.y;
    size_t hb  = (size_t)bh * NSEQ * NHD;   // q/k base
    size_t hvt = (size_t)bh * NHD * NSEQ;   // vt base

    u32 fbase = smem_u32(fbm);
    u32 qhb = fbase, qlb = fbase + QT_B;
    u32 kvb = fbase + 2*QT_B;

    u32 aoffp = (u32)((warp*16 + (lane & 15))*144 + (lane >> 4)*16);
    u32 boffp = (u32)(((lane & 7) + ((lane >> 4) & 1)*8)*144 + ((lane >> 3) & 1)*16);

    // Q hi/lo (one group)
    #pragma unroll
    for (int it = 0; it < 8; it++){
        int f = tid + 256*it;
        int tile = it >> 2;
        int fr = f & 1023;
        int row = fr >> 3, half = fr & 7;
        const __nv_bfloat16* sp = (tile ? g_qlo : g_qhi) + hb + (size_t)(q0 + row)*NHD + half*8;
        cp16((tile ? qlb : qhb) + row*144 + half*16, sp);
    }
    cp_commit();

    auto load_kv = [&](int t, int buf){
        int c0 = t * 64;
        u32 bb = kvb + buf*KVBUF_B;
        #pragma unroll
        for (int it = 0; it < 8; it++){
            int f = tid + 256*it;
            int tile = it >> 1;                 // 0:Kh 1:Kl 2:Vh 3:Vl
            int fr = f & 511;
            int row = fr >> 3, half = fr & 7;
            const __nv_bfloat16* sp;
            if (tile == 0)      sp = g_khi  + hb  + (size_t)(c0 + row)*NHD + half*8;
            else if (tile == 1) sp = g_klo  + hb  + (size_t)(c0 + row)*NHD + half*8;
            else if (tile == 2) sp = g_vthi + hvt + (size_t)row*NSEQ + c0 + half*8;
            else                sp = g_vtlo + hvt + (size_t)row*NSEQ + c0 + half*8;
            cp16(bb + tile*KT_B + row*144 + half*16, sp);
        }
        cp_commit();
    };

    load_kv(0, 0);

    float o[8][4];
    #pragma unroll
    for (int j = 0; j < 8; j++)
        #pragma unroll
        for (int q = 0; q < 4; q++) o[j][q] = 0.0f;
    float m0f = -1e30f, m1f = -1e30f, l0s = 0.0f, l1s = 0.0f;

    #pragma unroll 1
    for (int t = 0; t < 16; t++){
        __syncthreads();                        // prev-iter reads of target buffer done
        if (t + 1 < 16) load_kv(t + 1, (t + 1) & 1);
        if (t + 1 < 16) cp_wait<1>();
        else            cp_wait<0>();
        __syncthreads();

        u32 bb  = kvb + (t & 1)*KVBUF_B;
        u32 khb = bb, klb = bb + KT_B, vhb = bb + 2*KT_B, vlb = bb + 3*KT_B;

        // ---- S = Q K^T (bf16x3, 3-pass) ----
        float s[8][4];
        #pragma unroll
        for (int j = 0; j < 8; j++)
            #pragma unroll
            for (int q = 0; q < 4; q++) s[j][q] = 0.0f;

        #pragma unroll
        for (int kc = 0; kc < 4; kc++){
            u32 qh4[4], ql4[4], kh4[4][4];
            ldsm4(qh4, qhb + aoffp + kc*32);
            ldsm4(ql4, qlb + aoffp + kc*32);
            #pragma unroll
            for (int i4 = 0; i4 < 4; i4++)
                ldsm4(kh4[i4], khb + boffp + i4*(16*144) + kc*32);
            #pragma unroll
            for (int i4 = 0; i4 < 4; i4++){
                mma_bf16(s[2*i4+0], qh4, kh4[i4][0], kh4[i4][1]);
                mma_bf16(s[2*i4+1], qh4, kh4[i4][2], kh4[i4][3]);
            }
            #pragma unroll
            for (int i4 = 0; i4 < 4; i4++){
                mma_bf16(s[2*i4+0], ql4, kh4[i4][0], kh4[i4][1]);
                mma_bf16(s[2*i4+1], ql4, kh4[i4][2], kh4[i4][3]);
            }
            #pragma unroll
            for (int i4 = 0; i4 < 4; i4++){
                u32 kl4[4];
                ldsm4(kl4, klb + boffp + i4*(16*144) + kc*32);
                mma_bf16(s[2*i4+0], qh4, kl4[0], kl4[1]);
                mma_bf16(s[2*i4+1], qh4, kl4[2], kl4[3]);
            }
        }

        // ---- streaming softmax (in-place exp into s) ----
        float mx0 = -1e30f, mx1 = -1e30f;
        #pragma unroll
        for (int j = 0; j < 8; j++){
            mx0 = fmaxf(mx0, fmaxf(s[j][0], s[j][1]));
            mx1 = fmaxf(mx1, fmaxf(s[j][2], s[j][3]));
        }
        #pragma unroll
        for (int off = 1; off <= 2; off <<= 1){
            mx0 = fmaxf(mx0, __shfl_xor_sync(0xffffffffu, mx0, off));
            mx1 = fmaxf(mx1, __shfl_xor_sync(0xffffffffu, mx1, off));
        }
        float mn0 = fmaxf(m0f, mx0), mn1 = fmaxf(m1f, mx1);
        float corr0 = fast_exp(m0f - mn0), corr1 = fast_exp(m1f - mn1);
        m0f = mn0; m1f = mn1;

        float sum0 = 0.0f, sum1 = 0.0f;
        #pragma unroll
        for (int j = 0; j < 8; j++){
            s[j][0] = fast_exp(s[j][0] - mn0);
            s[j][1] = fast_exp(s[j][1] - mn0);
            s[j][2] = fast_exp(s[j][2] - mn1);
            s[j][3] = fast_exp(s[j][3] - mn1);
            sum0 += s[j][0] + s[j][1];
            sum1 += s[j][2] + s[j][3];
        }
        #pragma unroll
        for (int off = 1; off <= 2; off <<= 1){
            sum0 += __shfl_xor_sync(0xffffffffu, sum0, off);
            sum1 += __shfl_xor_sync(0xffffffffu, sum1, off);
        }
        l0s = l0s*corr0 + sum0;
        l1s = l1s*corr1 + sum1;
        #pragma unroll
        for (int j = 0; j < 8; j++){
            o[j][0] *= corr0; o[j][1] *= corr0;
            o[j][2] *= corr1; o[j][3] *= corr1;
        }

        // ---- O += P V (register P; bf16x3, 3-pass) ----
        #pragma unroll
        for (int kc = 0; kc < 4; kc++){
            u32 ph4[4], pl4[4];
            {
                __nv_bfloat16 h0,h1,l0,l1;
                split1(s[2*kc][0], h0, l0); split1(s[2*kc][1], h1, l1);
                ph4[0] = bfpair(h0,h1); pl4[0] = bfpair(l0,l1);
                split1(s[2*kc][2], h0, l0); split1(s[2*kc][3], h1, l1);
                ph4[1] = bfpair(h0,h1); pl4[1] = bfpair(l0,l1);
                split1(s[2*kc+1][0], h0, l0); split1(s[2*kc+1][1], h1, l1);
                ph4[2] = bfpair(h0,h1); pl4[2] = bfpair(l0,l1);
                split1(s[2*kc+1][2], h0, l0); split1(s[2*kc+1][3], h1, l1);
                ph4[3] = bfpair(h0,h1); pl4[3] = bfpair(l0,l1);
            }
            u32 vh4[4][4];
            #pragma unroll
            for (int i4 = 0; i4 < 4; i4++)
                ldsm4(vh4[i4], vhb + boffp + i4*(16*144) + kc*32);
            #pragma unroll
            for (int i4 = 0; i4 < 4; i4++){
                mma_bf16(o[2*i4+0], ph4, vh4[i4][0], vh4[i4][1]);
                mma_bf16(o[2*i4+1], ph4, vh4[i4][2], vh4[i4][3]);
            }
            #pragma unroll
            for (int i4 = 0; i4 < 4; i4++){
                mma_bf16(o[2*i4+0], pl4, vh4[i4][0], vh4[i4][1]);
                mma_bf16(o[2*i4+1], pl4, vh4[i4][2], vh4[i4][3]);
            }
            #pragma unroll
            for (int i4 = 0; i4 < 4; i4++){
                u32 vl4[4];
                ldsm4(vl4, vlb + boffp + i4*(16*144) + kc*32);
                mma_bf16(o[2*i4+0], ph4, vl4[0], vl4[1]);
                mma_bf16(o[2*i4+1], ph4, vl4[2], vl4[3]);
            }
        }
    }

    // ---- finalize: O /= l, split, write g_ohi/g_olo[b*N+n][h*64+d] ----
    int b = bh / NHEADS, h = bh % NHEADS;
    float inv0 = 1.0f / l0s, inv1 = 1.0f / l1s;
    int r0 = lane >> 2, colq = 2*(lane & 3);
    int gq0 = q0 + warp*16 + r0;
    size_t base0 = (size_t)(b*NSEQ + gq0    )*NDIM + h*NHD;
    size_t base1 = (size_t)(b*NSEQ + gq0 + 8)*NDIM + h*NHD;
    #pragma unroll
    for (int j = 0; j < 8; j++){
        int d0 = 8*j + colq;
        float x0 = o[j][0]*inv0, x1 = o[j][1]*inv0;
        float y0 = o[j][2]*inv1, y1 = o[j][3]*inv1;
        __nv_bfloat16 hx0,hx1,hy0,hy1,lx0,lx1,ly0,ly1;
        split1(x0,hx0,lx0); split1(x1,hx1,lx1);
        split1(y0,hy0,ly0); split1(y1,hy1,ly1);
        *(u32*)(g_ohi + base0 + d0) = bfpair(hx0,hx1);
        *(u32*)(g_olo + base0 + d0) = bfpair(lx0,lx1);
        *(u32*)(g_ohi + base1 + d0) = bfpair(hy0,hy1);
        *(u32*)(g_olo + base1 + d0) = bfpair(ly0,ly1);
    }
}

// =====================================================================
extern "C" void kernel_launch(void* const* d_in, const int* in_sizes, int n_in,
                              void* d_out, int out_size)
{
    const float* x      = (const float*)d_in[0];
    const float* w_qkv  = (const float*)d_in[1];
    const float* w_proj = (const float*)d_in[2];
    const float* b_proj = (const float*)d_in[3];
    float* out = (float*)d_out;

    cudaFuncSetAttribute(mma_gemm_kernel, cudaFuncAttributeMaxDynamicSharedMemorySize, GEMM_SMEM);
    cudaFuncSetAttribute(flash_mma_kernel, cudaFuncAttributeMaxDynamicSharedMemorySize, FLASH_SMEM);

    split_kernel<<<X_ELEMS/1024, 256>>>(x, 0, X_ELEMS);
    split_kernel<<<(2304*768)/1024, 256>>>(w_qkv, 1, 2304*768);
    split_kernel<<<(768*768)/1024, 256>>>(w_proj, 2, 768*768);
    mma_gemm_kernel<<<dim3(2304/128, 16384/128), 256, GEMM_SMEM>>>(nullptr, nullptr, 0);
    flash_mma_kernel<<<dim3(NSEQ/128, NBATCH*NHEADS), 256, FLASH_SMEM>>>();
    mma_gemm_kernel<<<dim3(768/128, 16384/128), 256, GEMM_SMEM>>>(b_proj, out, 1);
}

// round 11
// speedup vs baseline: 3.7095x; 1.3995x over previous
#include <cuda_runtime.h>
#include <cuda_fp16.h>
#include <cstdint>

typedef unsigned long long u64;
typedef unsigned int u32;

#define NBATCH 16
#define NSEQ   1024
#define NDIM   768
#define NHEADS 12
#define NHD    64
#define ATT_SCALE 0.125f
#define QKV_ELEMS (NBATCH*NHEADS*NSEQ*NHD)    // 12582912
#define X_ELEMS   (NBATCH*NSEQ*NDIM)          // 12582912
#define WQ_E      (2304*768)
#define WP_E      (768*768)

// ---------------- static scratch (allocation-free) ----------------
// A-side operands: fp16 hi/lo pairs. B-side operands: single rn fp16.
__device__ __half g_xhi[X_ELEMS], g_xlo[X_ELEMS];
__device__ __half g_wq[WQ_E];                         // single
__device__ __half g_wp[WP_E];                         // single
__device__ __half g_qhi[QKV_ELEMS], g_qlo[QKV_ELEMS]; // [B*H, N, D], pre-scaled (A of S)
__device__ __half g_k [QKV_ELEMS];                    // [B*H, N, D] single (B of S)
__device__ __half g_vt[QKV_ELEMS];                    // [B*H, D, N] single transposed (B of PV)
__device__ __half g_ohi[X_ELEMS], g_olo[X_ELEMS];     // [B*N, C] pair (A of proj)

// ---------------- helpers ----------------
__device__ __forceinline__ u32 smem_u32(const void* p){
    u32 a; asm("{ .reg .u64 t; cvta.to.shared.u64 t, %1; cvt.u32.u64 %0, t; }" : "=r"(a) : "l"(p));
    return a;
}
__device__ __forceinline__ u32 hpair(__half a, __half b){
    return (u32)__half_as_ushort(a) | ((u32)__half_as_ushort(b) << 16);
}
__device__ __forceinline__ void split1h(float x, __half& h, __half& l){
    h = __float2half_rn(x);
    l = __float2half_rn(x - __half2float(h));
}

// fast exp on the FMA pipe (no MUFU), x <= ~0
__device__ __forceinline__ float fast_exp(float x){
    x = fmaxf(x, -80.0f);
    float t  = x * 1.4426950408889634f;
    float tr = t + 12582912.0f;
    int   n  = __float_as_int(tr) - 0x4B400000;
    float rn = tr - 12582912.0f;
    float f  = t - rn;
    float p = 1.3333558146428443e-3f;
    p = fmaf(p, f, 9.618129107628477e-3f);
    p = fmaf(p, f, 5.550410866482158e-2f);
    p = fmaf(p, f, 2.402265069591007e-1f);
    p = fmaf(p, f, 6.931471805599453e-1f);
    p = fmaf(p, f, 1.0f);
    return p * __int_as_float((n + 127) << 23);
}

// ---------------- mma/ldsm/cp.async primitives ----------------
__device__ __forceinline__ void ldsm4(u32* r, u32 addr){
    asm volatile("ldmatrix.sync.aligned.m8n8.x4.shared.b16 {%0,%1,%2,%3}, [%4];"
        : "=r"(r[0]), "=r"(r[1]), "=r"(r[2]), "=r"(r[3]) : "r"(addr));
}
__device__ __forceinline__ void mma_f16(float* c, const u32* a, u32 b0, u32 b1){
    asm volatile("mma.sync.aligned.m16n8k16.row.col.f32.f16.f16.f32 "
        "{%0,%1,%2,%3}, {%4,%5,%6,%7}, {%8,%9}, {%0,%1,%2,%3};"
        : "+f"(c[0]), "+f"(c[1]), "+f"(c[2]), "+f"(c[3])
        : "r"(a[0]), "r"(a[1]), "r"(a[2]), "r"(a[3]), "r"(b0), "r"(b1));
}
__device__ __forceinline__ void cp16(u32 dst, const void* src){
    asm volatile("cp.async.cg.shared.global [%0], [%1], 16;" :: "r"(dst), "l"(src));
}
__device__ __forceinline__ void cp_commit(){ asm volatile("cp.async.commit_group;" ::: "memory"); }
template<int N> __device__ __forceinline__ void cp_wait(){
    asm volatile("cp.async.wait_group %0;" :: "n"(N) : "memory");
}

// =====================================================================
// Prep (single fused launch): x -> fp16 hi/lo pair; w_qkv, w_proj -> single fp16
// =====================================================================
__global__ __launch_bounds__(256) void split_kernel(
    const float* __restrict__ x, const float* __restrict__ wq, const float* __restrict__ wp)
{
    int i = (blockIdx.x*blockDim.x + threadIdx.x)*4;
    if (i < X_ELEMS){
        float4 v = *(const float4*)(x + i);
        __half h0,h1,h2,h3,l0,l1,l2,l3;
        split1h(v.x,h0,l0); split1h(v.y,h1,l1); split1h(v.z,h2,l2); split1h(v.w,h3,l3);
        *(u32*)(g_xhi+i)   = hpair(h0,h1);
        *(u32*)(g_xhi+i+2) = hpair(h2,h3);
        *(u32*)(g_xlo+i)   = hpair(l0,l1);
        *(u32*)(g_xlo+i+2) = hpair(l2,l3);
    } else if (i < X_ELEMS + WQ_E){
        int j = i - X_ELEMS;
        float4 v = *(const float4*)(wq + j);
        *(u32*)(g_wq+j)   = hpair(__float2half_rn(v.x), __float2half_rn(v.y));
        *(u32*)(g_wq+j+2) = hpair(__float2half_rn(v.z), __float2half_rn(v.w));
    } else {
        int j = i - X_ELEMS - WQ_E;
        if (j < WP_E){
            float4 v = *(const float4*)(wp + j);
            *(u32*)(g_wp+j)   = hpair(__float2half_rn(v.x), __float2half_rn(v.y));
            *(u32*)(g_wp+j+2) = hpair(__float2half_rn(v.z), __float2half_rn(v.w));
        }
    }
}

// =====================================================================
// fp16x2 mma.sync GEMM: C = (Ah+Al) * Bh^T. Block 128x128, BK=32,
// 2-stage double buffer, prefetch distance 1, single barrier per iter.
// 8 warps (4M x 2N). Row pitch 80B (16B-aligned, conflict-free ldsm).
// mode 0: A=x pair, B=w_qkv -> q(pair,scaled)/k(single)/vT(single).
// mode 1: A=O pair, B=w_proj, out = C + bias (f32).
// =====================================================================
#define GP          80
#define TILE2_B     (128*GP)              // 10240
#define STAGE2_B    (3*TILE2_B)           // 30720 (Ah, Al, B)
#define GEMM_SMEM   (2*STAGE2_B)          // 61440

__global__ __launch_bounds__(256, 2) void mma_gemm_kernel(
    const float* __restrict__ bias, float* __restrict__ out, int mode)
{
    extern __shared__ __half smb[];
    const __half *Ahi, *Alo, *Bs;
    if (mode == 0){ Ahi = g_xhi; Alo = g_xlo; Bs = g_wq; }
    else          { Ahi = g_ohi; Alo = g_olo; Bs = g_wp; }

    int tid = threadIdx.x;
    int lane = tid & 31, warp = tid >> 5;
    int wm = warp & 3, wn = warp >> 2;
    int m0 = blockIdx.y * 128, n0 = blockIdx.x * 128;

    u32 sbase = smem_u32(smb);
    u32 aoff = (u32)((wm*32 + (lane & 15))*GP + (lane >> 4)*16);
    u32 boff = (u32)((wn*64 + (lane & 7) + ((lane >> 4) & 1)*8)*GP + ((lane >> 3) & 1)*16);

    float c[2][8][4];
    #pragma unroll
    for (int i = 0; i < 2; i++)
        #pragma unroll
        for (int j = 0; j < 8; j++)
            #pragma unroll
            for (int q = 0; q < 4; q++) c[i][j][q] = 0.0f;

    auto load_chunk = [&](int chunk){
        int st = chunk & 1;
        u32 stb = sbase + st*STAGE2_B;
        int kf = chunk*32;
        #pragma unroll
        for (int it = 0; it < 6; it++){
            int tile = it >> 1;               // 0:Ah 1:Al 2:B
            int fr = (it & 1)*256 + tid;      // 0..511
            int row = fr >> 2, qtr = fr & 3;
            const __half* src;
            if (tile == 0)      src = Ahi + (size_t)(m0 + row)*768 + kf + qtr*8;
            else if (tile == 1) src = Alo + (size_t)(m0 + row)*768 + kf + qtr*8;
            else                src = Bs  + (size_t)(n0 + row)*768 + kf + qtr*8;
            cp16(stb + tile*TILE2_B + row*GP + qtr*16, src);
        }
        cp_commit();
    };

    load_chunk(0);

    #pragma unroll 1
    for (int i = 0; i < 24; i++){
        cp_wait<0>();                          // only load(i) in flight here
        __syncthreads();                       // visibility + buffer-reuse fence
        if (i + 1 < 24) load_chunk(i + 1);     // overlaps with compute below

        u32 stb = sbase + (i & 1)*STAGE2_B;
        #pragma unroll
        for (int kc = 0; kc < 2; kc++){
            u32 ah[2][4], al[2][4], b4[4][4];
            #pragma unroll
            for (int fm = 0; fm < 2; fm++){
                ldsm4(ah[fm], stb + aoff + fm*(16*GP) + kc*32);
                ldsm4(al[fm], stb + TILE2_B + aoff + fm*(16*GP) + kc*32);
            }
            #pragma unroll
            for (int i4 = 0; i4 < 4; i4++)
                ldsm4(b4[i4], stb + 2*TILE2_B + boff + i4*(16*GP) + kc*32);

            #pragma unroll
            for (int i4 = 0; i4 < 4; i4++)
                #pragma unroll
                for (int fm = 0; fm < 2; fm++){
                    mma_f16(c[fm][2*i4+0], ah[fm], b4[i4][0], b4[i4][1]);
                    mma_f16(c[fm][2*i4+1], ah[fm], b4[i4][2], b4[i4][3]);
                }
            #pragma unroll
            for (int i4 = 0; i4 < 4; i4++)
                #pragma unroll
                for (int fm = 0; fm < 2; fm++){
                    mma_f16(c[fm][2*i4+0], al[fm], b4[i4][0], b4[i4][1]);
                    mma_f16(c[fm][2*i4+1], al[fm], b4[i4][2], b4[i4][3]);
                }
        }
    }

    // ---------------- epilogue ----------------
    int g = lane >> 2, tig = lane & 3;
    int colbase = n0 + wn*64;
    if (mode == 0){
        int hblk = colbase >> 6;
        int t_sel = hblk / NHEADS;
        int h     = hblk - t_sel*NHEADS;
        float sc  = (t_sel == 0) ? ATT_SCALE : 1.0f;
        #pragma unroll
        for (int fm = 0; fm < 2; fm++){
            int row0 = m0 + wm*32 + fm*16 + g;
            #pragma unroll
            for (int half = 0; half < 2; half++){
                int row = row0 + half*8;
                int b = row >> 10, n = row & 1023;
                int bh_i = b*NHEADS + h;
                if (t_sel == 2){
                    // V transposed single: g_vt[bh][d][n]
                    size_t vb = (size_t)bh_i*NHD*NSEQ + n;
                    #pragma unroll
                    for (int nf = 0; nf < 8; nf++){
                        int d0 = nf*8 + tig*2;
                        g_vt[vb + (size_t)d0*NSEQ]     = __float2half_rn(c[fm][nf][half*2]);
                        g_vt[vb + (size_t)(d0+1)*NSEQ] = __float2half_rn(c[fm][nf][half*2+1]);
                    }
                } else if (t_sel == 1){
                    // K single
                    size_t base_e = ((size_t)bh_i*NSEQ + n)*NHD;
                    #pragma unroll
                    for (int nf = 0; nf < 8; nf++){
                        int d0 = nf*8 + tig*2;
                        *(u32*)(g_k + base_e + d0) =
                            hpair(__float2half_rn(c[fm][nf][half*2]),
                                  __float2half_rn(c[fm][nf][half*2+1]));
                    }
                } else {
                    // Q pair, pre-scaled
                    size_t base_e = ((size_t)bh_i*NSEQ + n)*NHD;
                    #pragma unroll
                    for (int nf = 0; nf < 8; nf++){
                        int d0 = nf*8 + tig*2;
                        float x0 = c[fm][nf][half*2]*sc, x1 = c[fm][nf][half*2+1]*sc;
                        __half h0,h1,l0,l1;
                        split1h(x0,h0,l0); split1h(x1,h1,l1);
                        *(u32*)(g_qhi + base_e + d0) = hpair(h0,h1);
                        *(u32*)(g_qlo + base_e + d0) = hpair(l0,l1);
                    }
                }
            }
        }
    } else {
        #pragma unroll
        for (int fm = 0; fm < 2; fm++){
            int row0 = m0 + wm*32 + fm*16 + g;
            #pragma unroll
            for (int half = 0; half < 2; half++){
                int row = row0 + half*8;
                float* base = out + (size_t)row*768 + colbase;
                #pragma unroll
                for (int nf = 0; nf < 8; nf++){
                    int cg = nf*8 + tig*2;
                    float2 bv = *(const float2*)(bias + colbase + cg);
                    *(float2*)(base + cg) =
                        make_float2(c[fm][nf][half*2] + bv.x,
                                    c[fm][nf][half*2+1] + bv.y);
                }
            }
        }
    }
}

// =====================================================================
// Flash attention, fp16x2 mma.sync. Q pair / K single; P pair (regs) / V single.
// BQ=128 (8 warps x m16), BKV=64, D=64. Pitch 144B.
// Double-buffered K/V, prefetch distance 1, single barrier per iter.
// =====================================================================
#define QT_B       (128*144)             // 18432 bytes per Q tile
#define KT_B       (64*144)              // 9216 bytes per KV tile
#define KVBUF_B    (2*KT_B)              // 18432 (K, V)
#define FLASH_SMEM (2*QT_B + 2*KVBUF_B)  // 73728

__global__ __launch_bounds__(256, 2) void flash_mma_kernel()
{
    extern __shared__ __half fbm[];
    int tid = threadIdx.x, lane = tid & 31, warp = tid >> 5;
    int q0 = blockIdx.x * 128;
    int bh = blockIdx.y;
    size_t hb  = (size_t)bh * NSEQ * NHD;   // q/k base
    size_t hvt = (size_t)bh * NHD * NSEQ;   // vt base

    u32 fbase = smem_u32(fbm);
    u32 qhb = fbase, qlb = fbase + QT_B;
    u32 kvb = fbase + 2*QT_B;

    u32 aoffp = (u32)((warp*16 + (lane & 15))*144 + (lane >> 4)*16);
    u32 boffp = (u32)(((lane & 7) + ((lane >> 4) & 1)*8)*144 + ((lane >> 3) & 1)*16);

    // Q hi/lo (8 cp16/thread)
    #pragma unroll
    for (int it = 0; it < 8; it++){
        int f = tid + 256*it;
        int tile = it >> 2;
        int fr = f & 1023;
        int row = fr >> 3, half = fr & 7;
        const __half* sp = (tile ? g_qlo : g_qhi) + hb + (size_t)(q0 + row)*NHD + half*8;
        cp16((tile ? qlb : qhb) + row*144 + half*16, sp);
    }
    cp_commit();

    auto load_kv = [&](int t, int buf){
        int c0 = t * 64;
        u32 bb = kvb + buf*KVBUF_B;
        #pragma unroll
        for (int it = 0; it < 4; it++){
            int tile = it >> 1;                 // 0:K 1:V
            int fr = (it & 1)*256 + tid;        // 0..511
            int row = fr >> 3, half = fr & 7;
            const __half* sp;
            if (tile == 0) sp = g_k  + hb  + (size_t)(c0 + row)*NHD + half*8;
            else           sp = g_vt + hvt + (size_t)row*NSEQ + c0 + half*8;
            cp16(bb + tile*KT_B + row*144 + half*16, sp);
        }
        cp_commit();
    };

    load_kv(0, 0);

    float o[8][4];
    #pragma unroll
    for (int j = 0; j < 8; j++)
        #pragma unroll
        for (int q = 0; q < 4; q++) o[j][q] = 0.0f;
    float m0f = -1e30f, m1f = -1e30f, l0s = 0.0f, l1s = 0.0f;

    #pragma unroll 1
    for (int t = 0; t < 16; t++){
        cp_wait<0>();                           // Q (t=0) + KV(t) complete
        __syncthreads();
        if (t + 1 < 16) load_kv(t + 1, (t + 1) & 1);   // overlaps with compute

        u32 bb  = kvb + (t & 1)*KVBUF_B;
        u32 khb = bb, vhb = bb + KT_B;

        // ---- S = Q K^T (fp16x2, 2-pass) ----
        float s[8][4];
        #pragma unroll
        for (int j = 0; j < 8; j++)
            #pragma unroll
            for (int q = 0; q < 4; q++) s[j][q] = 0.0f;

        #pragma unroll
        for (int kc = 0; kc < 4; kc++){
            u32 qh4[4], ql4[4], kh4[4][4];
            ldsm4(qh4, qhb + aoffp + kc*32);
            ldsm4(ql4, qlb + aoffp + kc*32);
            #pragma unroll
            for (int i4 = 0; i4 < 4; i4++)
                ldsm4(kh4[i4], khb + boffp + i4*(16*144) + kc*32);
            #pragma unroll
            for (int i4 = 0; i4 < 4; i4++){
                mma_f16(s[2*i4+0], qh4, kh4[i4][0], kh4[i4][1]);
                mma_f16(s[2*i4+1], qh4, kh4[i4][2], kh4[i4][3]);
            }
            #pragma unroll
            for (int i4 = 0; i4 < 4; i4++){
                mma_f16(s[2*i4+0], ql4, kh4[i4][0], kh4[i4][1]);
                mma_f16(s[2*i4+1], ql4, kh4[i4][2], kh4[i4][3]);
            }
        }

        // ---- streaming softmax (in-place exp into s) ----
        float mx0 = -1e30f, mx1 = -1e30f;
        #pragma unroll
        for (int j = 0; j < 8; j++){
            mx0 = fmaxf(mx0, fmaxf(s[j][0], s[j][1]));
            mx1 = fmaxf(mx1, fmaxf(s[j][2], s[j][3]));
        }
        #pragma unroll
        for (int off = 1; off <= 2; off <<= 1){
            mx0 = fmaxf(mx0, __shfl_xor_sync(0xffffffffu, mx0, off));
            mx1 = fmaxf(mx1, __shfl_xor_sync(0xffffffffu, mx1, off));
        }
        float mn0 = fmaxf(m0f, mx0), mn1 = fmaxf(m1f, mx1);
        float corr0 = fast_exp(m0f - mn0), corr1 = fast_exp(m1f - mn1);
        m0f = mn0; m1f = mn1;

        float sum0 = 0.0f, sum1 = 0.0f;
        #pragma unroll
        for (int j = 0; j < 8; j++){
            s[j][0] = fast_exp(s[j][0] - mn0);
            s[j][1] = fast_exp(s[j][1] - mn0);
            s[j][2] = fast_exp(s[j][2] - mn1);
            s[j][3] = fast_exp(s[j][3] - mn1);
            sum0 += s[j][0] + s[j][1];
            sum1 += s[j][2] + s[j][3];
        }
        #pragma unroll
        for (int off = 1; off <= 2; off <<= 1){
            sum0 += __shfl_xor_sync(0xffffffffu, sum0, off);
            sum1 += __shfl_xor_sync(0xffffffffu, sum1, off);
        }
        l0s = l0s*corr0 + sum0;
        l1s = l1s*corr1 + sum1;
        #pragma unroll
        for (int j = 0; j < 8; j++){
            o[j][0] *= corr0; o[j][1] *= corr0;
            o[j][2] *= corr1; o[j][3] *= corr1;
        }

        // ---- O += P V (register P pair; fp16x2, 2-pass) ----
        #pragma unroll
        for (int kc = 0; kc < 4; kc++){
            u32 ph4[4], pl4[4];
            {
                __half h0,h1,l0,l1;
                split1h(s[2*kc][0], h0, l0); split1h(s[2*kc][1], h1, l1);
                ph4[0] = hpair(h0,h1); pl4[0] = hpair(l0,l1);
                split1h(s[2*kc][2], h0, l0); split1h(s[2*kc][3], h1, l1);
                ph4[1] = hpair(h0,h1); pl4[1] = hpair(l0,l1);
                split1h(s[2*kc+1][0], h0, l0); split1h(s[2*kc+1][1], h1, l1);
                ph4[2] = hpair(h0,h1); pl4[2] = hpair(l0,l1);
                split1h(s[2*kc+1][2], h0, l0); split1h(s[2*kc+1][3], h1, l1);
                ph4[3] = hpair(h0,h1); pl4[3] = hpair(l0,l1);
            }
            u32 vh4[4][4];
            #pragma unroll
            for (int i4 = 0; i4 < 4; i4++)
                ldsm4(vh4[i4], vhb + boffp + i4*(16*144) + kc*32);
            #pragma unroll
            for (int i4 = 0; i4 < 4; i4++){
                mma_f16(o[2*i4+0], ph4, vh4[i4][0], vh4[i4][1]);
                mma_f16(o[2*i4+1], ph4, vh4[i4][2], vh4[i4][3]);
            }
            #pragma unroll
            for (int i4 = 0; i4 < 4; i4++){
                mma_f16(o[2*i4+0], pl4, vh4[i4][0], vh4[i4][1]);
                mma_f16(o[2*i4+1], pl4, vh4[i4][2], vh4[i4][3]);
            }
        }
    }

    // ---- finalize: O /= l, split, write g_ohi/g_olo[b*N+n][h*64+d] ----
    int b = bh / NHEADS, h = bh % NHEADS;
    float inv0 = 1.0f / l0s, inv1 = 1.0f / l1s;
    int r0 = lane >> 2, colq = 2*(lane & 3);
    int gq0 = q0 + warp*16 + r0;
    size_t base0 = (size_t)(b*NSEQ + gq0    )*NDIM + h*NHD;
    size_t base1 = (size_t)(b*NSEQ + gq0 + 8)*NDIM + h*NHD;
    #pragma unroll
    for (int j = 0; j < 8; j++){
        int d0 = 8*j + colq;
        float x0 = o[j][0]*inv0, x1 = o[j][1]*inv0;
        float y0 = o[j][2]*inv1, y1 = o[j][3]*inv1;
        __half hx0,hx1,hy0,hy1,lx0,lx1,ly0,ly1;
        split1h(x0,hx0,lx0); split1h(x1,hx1,lx1);
        split1h(y0,hy0,ly0); split1h(y1,hy1,ly1);
        *(u32*)(g_ohi + base0 + d0) = hpair(hx0,hx1);
        *(u32*)(g_olo + base0 + d0) = hpair(lx0,lx1);
        *(u32*)(g_ohi + base1 + d0) = hpair(hy0,hy1);
        *(u32*)(g_olo + base1 + d0) = hpair(ly0,ly1);
    }
}

// =====================================================================
extern "C" void kernel_launch(void* const* d_in, const int* in_sizes, int n_in,
                              void* d_out, int out_size)
{
    const float* x      = (const float*)d_in[0];
    const float* w_qkv  = (const float*)d_in[1];
    const float* w_proj = (const float*)d_in[2];
    const float* b_proj = (const float*)d_in[3];
    float* out = (float*)d_out;

    cudaFuncSetAttribute(mma_gemm_kernel, cudaFuncAttributeMaxDynamicSharedMemorySize, GEMM_SMEM);
    cudaFuncSetAttribute(flash_mma_kernel, cudaFuncAttributeMaxDynamicSharedMemorySize, FLASH_SMEM);

    int total_quads = (X_ELEMS + WQ_E + WP_E) / 4;
    split_kernel<<<(total_quads + 255)/256, 256>>>(x, w_qkv, w_proj);
    mma_gemm_kernel<<<dim3(2304/128, 16384/128), 256, GEMM_SMEM>>>(nullptr, nullptr, 0);
    flash_mma_kernel<<<dim3(NSEQ/128, NBATCH*NHEADS), 256, FLASH_SMEM>>>();
    mma_gemm_kernel<<<dim3(768/128, 16384/128), 256, GEMM_SMEM>>>(b_proj, out, 1);
}

// round 12
// speedup vs baseline: 5.3692x; 1.4474x over previous
#include <cuda_runtime.h>
#include <cuda_fp16.h>
#include <cstdint>

typedef unsigned long long u64;
typedef unsigned int u32;

#define NBATCH 16
#define NSEQ   1024
#define NDIM   768
#define NHEADS 12
#define NHD    64
#define ATT_SCALE 0.125f
#define QKV_ELEMS (NBATCH*NHEADS*NSEQ*NHD)    // 12582912
#define X_ELEMS   (NBATCH*NSEQ*NDIM)          // 12582912
#define WQ_E      (2304*768)
#define WP_E      (768*768)

// ---------------- static scratch (allocation-free) ----------------
__device__ __half g_x [X_ELEMS];                      // x single
__device__ __half g_wq[WQ_E];                         // w_qkv single
__device__ __half g_wp[WP_E];                         // w_proj single
__device__ __half g_qhi[QKV_ELEMS], g_qlo[QKV_ELEMS]; // [B*H, N, D] pair, pre-scaled
__device__ __half g_k [QKV_ELEMS];                    // [B*H, N, D] single
__device__ __half g_vt[QKV_ELEMS];                    // [B*H, D, N] single, transposed
__device__ __half g_o [X_ELEMS];                      // [B*N, C] single

// ---------------- helpers ----------------
__device__ __forceinline__ u32 smem_u32(const void* p){
    u32 a; asm("{ .reg .u64 t; cvta.to.shared.u64 t, %1; cvt.u32.u64 %0, t; }" : "=r"(a) : "l"(p));
    return a;
}
__device__ __forceinline__ u32 hpair(__half a, __half b){
    return (u32)__half_as_ushort(a) | ((u32)__half_as_ushort(b) << 16);
}
__device__ __forceinline__ void split1h(float x, __half& h, __half& l){
    h = __float2half_rn(x);
    l = __float2half_rn(x - __half2float(h));
}

// fast exp on the FMA pipe (no MUFU), x <= ~0
__device__ __forceinline__ float fast_exp(float x){
    x = fmaxf(x, -80.0f);
    float t  = x * 1.4426950408889634f;
    float tr = t + 12582912.0f;
    int   n  = __float_as_int(tr) - 0x4B400000;
    float rn = tr - 12582912.0f;
    float f  = t - rn;
    float p = 1.3333558146428443e-3f;
    p = fmaf(p, f, 9.618129107628477e-3f);
    p = fmaf(p, f, 5.550410866482158e-2f);
    p = fmaf(p, f, 2.402265069591007e-1f);
    p = fmaf(p, f, 6.931471805599453e-1f);
    p = fmaf(p, f, 1.0f);
    return p * __int_as_float((n + 127) << 23);
}

// ---------------- mma/ldsm/cp.async primitives ----------------
__device__ __forceinline__ void ldsm4(u32* r, u32 addr){
    asm volatile("ldmatrix.sync.aligned.m8n8.x4.shared.b16 {%0,%1,%2,%3}, [%4];"
        : "=r"(r[0]), "=r"(r[1]), "=r"(r[2]), "=r"(r[3]) : "r"(addr));
}
__device__ __forceinline__ void mma_f16(float* c, const u32* a, u32 b0, u32 b1){
    asm volatile("mma.sync.aligned.m16n8k16.row.col.f32.f16.f16.f32 "
        "{%0,%1,%2,%3}, {%4,%5,%6,%7}, {%8,%9}, {%0,%1,%2,%3};"
        : "+f"(c[0]), "+f"(c[1]), "+f"(c[2]), "+f"(c[3])
        : "r"(a[0]), "r"(a[1]), "r"(a[2]), "r"(a[3]), "r"(b0), "r"(b1));
}
__device__ __forceinline__ void cp16(u32 dst, const void* src){
    asm volatile("cp.async.cg.shared.global [%0], [%1], 16;" :: "r"(dst), "l"(src));
}
__device__ __forceinline__ void cp_commit(){ asm volatile("cp.async.commit_group;" ::: "memory"); }
template<int N> __device__ __forceinline__ void cp_wait(){
    asm volatile("cp.async.wait_group %0;" :: "n"(N) : "memory");
}

// =====================================================================
// Prep: x, w_qkv, w_proj -> single rn fp16
// =====================================================================
__global__ __launch_bounds__(256) void split_kernel(
    const float* __restrict__ x, const float* __restrict__ wq, const float* __restrict__ wp)
{
    int i = (blockIdx.x*blockDim.x + threadIdx.x)*4;
    if (i < X_ELEMS){
        float4 v = *(const float4*)(x + i);
        *(u32*)(g_x+i)   = hpair(__float2half_rn(v.x), __float2half_rn(v.y));
        *(u32*)(g_x+i+2) = hpair(__float2half_rn(v.z), __float2half_rn(v.w));
    } else if (i < X_ELEMS + WQ_E){
        int j = i - X_ELEMS;
        float4 v = *(const float4*)(wq + j);
        *(u32*)(g_wq+j)   = hpair(__float2half_rn(v.x), __float2half_rn(v.y));
        *(u32*)(g_wq+j+2) = hpair(__float2half_rn(v.z), __float2half_rn(v.w));
    } else {
        int j = i - X_ELEMS - WQ_E;
        if (j < WP_E){
            float4 v = *(const float4*)(wp + j);
            *(u32*)(g_wp+j)   = hpair(__float2half_rn(v.x), __float2half_rn(v.y));
            *(u32*)(g_wp+j+2) = hpair(__float2half_rn(v.z), __float2half_rn(v.w));
        }
    }
}

// =====================================================================
// fp16 mma.sync GEMM: C = A * B^T (single precision operands).
// Block 128x128, BK=32, 3-stage cp.async (prefetch distance 2).
// 8 warps (4M x 2N), warp 32x64. Row pitch 80B.
// mode 0: A=x, B=w_qkv -> q(pair, scaled)/k(single)/vT(single).
// mode 1: A=O(single), B=w_proj, out = C + bias (f32).
// =====================================================================
#define GP          80
#define TILE2_B     (128*GP)              // 10240
#define STAGE2_B    (2*TILE2_B)           // 20480 (A, B)
#define GEMM_SMEM   (3*STAGE2_B)          // 61440

__global__ __launch_bounds__(256, 2) void mma_gemm_kernel(
    const float* __restrict__ bias, float* __restrict__ out, int mode)
{
    extern __shared__ __half smb[];
    const __half *As, *Bs;
    if (mode == 0){ As = g_x; Bs = g_wq; }
    else          { As = g_o; Bs = g_wp; }

    int tid = threadIdx.x;
    int lane = tid & 31, warp = tid >> 5;
    int wm = warp & 3, wn = warp >> 2;
    int m0 = blockIdx.y * 128, n0 = blockIdx.x * 128;

    u32 sbase = smem_u32(smb);
    u32 aoff = (u32)((wm*32 + (lane & 15))*GP + (lane >> 4)*16);
    u32 boff = (u32)((wn*64 + (lane & 7) + ((lane >> 4) & 1)*8)*GP + ((lane >> 3) & 1)*16);

    float c[2][8][4];
    #pragma unroll
    for (int i = 0; i < 2; i++)
        #pragma unroll
        for (int j = 0; j < 8; j++)
            #pragma unroll
            for (int q = 0; q < 4; q++) c[i][j][q] = 0.0f;

    auto load_chunk = [&](int chunk){
        int st = chunk % 3;
        u32 stb = sbase + st*STAGE2_B;
        int kf = chunk*32;
        #pragma unroll
        for (int it = 0; it < 4; it++){
            int tile = it >> 1;               // 0:A 1:B
            int fr = (it & 1)*256 + tid;      // 0..511
            int row = fr >> 2, qtr = fr & 3;
            const __half* src = tile ? (Bs + (size_t)(n0 + row)*768 + kf + qtr*8)
                                     : (As + (size_t)(m0 + row)*768 + kf + qtr*8);
            cp16(stb + tile*TILE2_B + row*GP + qtr*16, src);
        }
        cp_commit();
    };

    load_chunk(0); load_chunk(1);

    #pragma unroll 1
    for (int i = 0; i < 24; i++){
        if (i < 23) cp_wait<1>();              // load(i) done, load(i+1) may fly
        else        cp_wait<0>();
        __syncthreads();
        if (i + 2 < 24) load_chunk(i + 2);     // overlaps with compute below

        u32 stb = sbase + (i % 3)*STAGE2_B;
        #pragma unroll
        for (int kc = 0; kc < 2; kc++){
            u32 a4[2][4], b4[4][4];
            #pragma unroll
            for (int fm = 0; fm < 2; fm++)
                ldsm4(a4[fm], stb + aoff + fm*(16*GP) + kc*32);
            #pragma unroll
            for (int i4 = 0; i4 < 4; i4++)
                ldsm4(b4[i4], stb + TILE2_B + boff + i4*(16*GP) + kc*32);

            #pragma unroll
            for (int i4 = 0; i4 < 4; i4++)
                #pragma unroll
                for (int fm = 0; fm < 2; fm++){
                    mma_f16(c[fm][2*i4+0], a4[fm], b4[i4][0], b4[i4][1]);
                    mma_f16(c[fm][2*i4+1], a4[fm], b4[i4][2], b4[i4][3]);
                }
        }
    }

    // ---------------- epilogue ----------------
    int g = lane >> 2, tig = lane & 3;
    int colbase = n0 + wn*64;
    if (mode == 0){
        int hblk = colbase >> 6;
        int t_sel = hblk / NHEADS;
        int h     = hblk - t_sel*NHEADS;
        #pragma unroll
        for (int fm = 0; fm < 2; fm++){
            int row0 = m0 + wm*32 + fm*16 + g;
            #pragma unroll
            for (int half = 0; half < 2; half++){
                int row = row0 + half*8;
                int b = row >> 10, n = row & 1023;
                int bh_i = b*NHEADS + h;
                if (t_sel == 2){
                    // V transposed single: g_vt[bh][d][n]
                    size_t vb = (size_t)bh_i*NHD*NSEQ + n;
                    #pragma unroll
                    for (int nf = 0; nf < 8; nf++){
                        int d0 = nf*8 + tig*2;
                        g_vt[vb + (size_t)d0*NSEQ]     = __float2half_rn(c[fm][nf][half*2]);
                        g_vt[vb + (size_t)(d0+1)*NSEQ] = __float2half_rn(c[fm][nf][half*2+1]);
                    }
                } else if (t_sel == 1){
                    size_t base_e = ((size_t)bh_i*NSEQ + n)*NHD;
                    #pragma unroll
                    for (int nf = 0; nf < 8; nf++){
                        int d0 = nf*8 + tig*2;
                        *(u32*)(g_k + base_e + d0) =
                            hpair(__float2half_rn(c[fm][nf][half*2]),
                                  __float2half_rn(c[fm][nf][half*2+1]));
                    }
                } else {
                    // Q pair, pre-scaled
                    size_t base_e = ((size_t)bh_i*NSEQ + n)*NHD;
                    #pragma unroll
                    for (int nf = 0; nf < 8; nf++){
                        int d0 = nf*8 + tig*2;
                        float x0 = c[fm][nf][half*2]*ATT_SCALE, x1 = c[fm][nf][half*2+1]*ATT_SCALE;
                        __half h0,h1,l0,l1;
                        split1h(x0,h0,l0); split1h(x1,h1,l1);
                        *(u32*)(g_qhi + base_e + d0) = hpair(h0,h1);
                        *(u32*)(g_qlo + base_e + d0) = hpair(l0,l1);
                    }
                }
            }
        }
    } else {
        #pragma unroll
        for (int fm = 0; fm < 2; fm++){
            int row0 = m0 + wm*32 + fm*16 + g;
            #pragma unroll
            for (int half = 0; half < 2; half++){
                int row = row0 + half*8;
                float* base = out + (size_t)row*768 + colbase;
                #pragma unroll
                for (int nf = 0; nf < 8; nf++){
                    int cg = nf*8 + tig*2;
                    float2 bv = *(const float2*)(bias + colbase + cg);
                    *(float2*)(base + cg) =
                        make_float2(c[fm][nf][half*2] + bv.x,
                                    c[fm][nf][half*2+1] + bv.y);
                }
            }
        }
    }
}

// =====================================================================
// Flash attention. QK: Q pair (2-pass) x K single. PV: P single x V single.
// BQ=128 (8 warps x m16), BKV=64, D=64. Pitch 144B.
// 3-buffer KV cp.async pipeline, prefetch distance 2.
// =====================================================================
#define QT_B       (128*144)             // 18432 bytes per Q tile
#define KT_B       (64*144)              // 9216 bytes per KV tile
#define KVBUF_B    (2*KT_B)              // 18432 (K, V)
#define FLASH_SMEM (2*QT_B + 3*KVBUF_B)  // 92160

__global__ __launch_bounds__(256, 2) void flash_mma_kernel()
{
    extern __shared__ __half fbm[];
    int tid = threadIdx.x, lane = tid & 31, warp = tid >> 5;
    int q0 = blockIdx.x * 128;
    int bh = blockIdx.y;
    size_t hb  = (size_t)bh * NSEQ * NHD;   // q/k base
    size_t hvt = (size_t)bh * NHD * NSEQ;   // vt base

    u32 fbase = smem_u32(fbm);
    u32 qhb = fbase, qlb = fbase + QT_B;
    u32 kvb = fbase + 2*QT_B;

    u32 aoffp = (u32)((warp*16 + (lane & 15))*144 + (lane >> 4)*16);
    u32 boffp = (u32)(((lane & 7) + ((lane >> 4) & 1)*8)*144 + ((lane >> 3) & 1)*16);

    // Q hi/lo (group 1)
    #pragma unroll
    for (int it = 0; it < 8; it++){
        int f = tid + 256*it;
        int tile = it >> 2;
        int fr = f & 1023;
        int row = fr >> 3, half = fr & 7;
        const __half* sp = (tile ? g_qlo : g_qhi) + hb + (size_t)(q0 + row)*NHD + half*8;
        cp16((tile ? qlb : qhb) + row*144 + half*16, sp);
    }
    cp_commit();

    auto load_kv = [&](int t){
        int c0 = t * 64;
        u32 bb = kvb + (t % 3)*KVBUF_B;
        #pragma unroll
        for (int it = 0; it < 4; it++){
            int tile = it >> 1;                 // 0:K 1:V
            int fr = (it & 1)*256 + tid;        // 0..511
            int row = fr >> 3, half = fr & 7;
            const __half* sp;
            if (tile == 0) sp = g_k  + hb  + (size_t)(c0 + row)*NHD + half*8;
            else           sp = g_vt + hvt + (size_t)row*NSEQ + c0 + half*8;
            cp16(bb + tile*KT_B + row*144 + half*16, sp);
        }
        cp_commit();
    };

    load_kv(0); load_kv(1);

    float o[8][4];
    #pragma unroll
    for (int j = 0; j < 8; j++)
        #pragma unroll
        for (int q = 0; q < 4; q++) o[j][q] = 0.0f;
    float m0f = -1e30f, m1f = -1e30f, l0s = 0.0f, l1s = 0.0f;

    #pragma unroll 1
    for (int t = 0; t < 16; t++){
        if (t < 15) cp_wait<1>();               // Q + kv(t) done; kv(t+1) may fly
        else        cp_wait<0>();
        __syncthreads();
        if (t + 2 < 16) load_kv(t + 2);         // overlaps with compute

        u32 bb  = kvb + (t % 3)*KVBUF_B;
        u32 khb = bb, vhb = bb + KT_B;

        // ---- S = Q K^T (Q pair, 2-pass) ----
        float s[8][4];
        #pragma unroll
        for (int j = 0; j < 8; j++)
            #pragma unroll
            for (int q = 0; q < 4; q++) s[j][q] = 0.0f;

        #pragma unroll
        for (int kc = 0; kc < 4; kc++){
            u32 qh4[4], ql4[4], kh4[4][4];
            ldsm4(qh4, qhb + aoffp + kc*32);
            ldsm4(ql4, qlb + aoffp + kc*32);
            #pragma unroll
            for (int i4 = 0; i4 < 4; i4++)
                ldsm4(kh4[i4], khb + boffp + i4*(16*144) + kc*32);
            #pragma unroll
            for (int i4 = 0; i4 < 4; i4++){
                mma_f16(s[2*i4+0], qh4, kh4[i4][0], kh4[i4][1]);
                mma_f16(s[2*i4+1], qh4, kh4[i4][2], kh4[i4][3]);
            }
            #pragma unroll
            for (int i4 = 0; i4 < 4; i4++){
                mma_f16(s[2*i4+0], ql4, kh4[i4][0], kh4[i4][1]);
                mma_f16(s[2*i4+1], ql4, kh4[i4][2], kh4[i4][3]);
            }
        }

        // ---- streaming softmax (in-place exp into s) ----
        float mx0 = -1e30f, mx1 = -1e30f;
        #pragma unroll
        for (int j = 0; j < 8; j++){
            mx0 = fmaxf(mx0, fmaxf(s[j][0], s[j][1]));
            mx1 = fmaxf(mx1, fmaxf(s[j][2], s[j][3]));
        }
        #pragma unroll
        for (int off = 1; off <= 2; off <<= 1){
            mx0 = fmaxf(mx0, __shfl_xor_sync(0xffffffffu, mx0, off));
            mx1 = fmaxf(mx1, __shfl_xor_sync(0xffffffffu, mx1, off));
        }
        float mn0 = fmaxf(m0f, mx0), mn1 = fmaxf(m1f, mx1);
        float corr0 = fast_exp(m0f - mn0), corr1 = fast_exp(m1f - mn1);
        m0f = mn0; m1f = mn1;

        float sum0 = 0.0f, sum1 = 0.0f;
        #pragma unroll
        for (int j = 0; j < 8; j++){
            s[j][0] = fast_exp(s[j][0] - mn0);
            s[j][1] = fast_exp(s[j][1] - mn0);
            s[j][2] = fast_exp(s[j][2] - mn1);
            s[j][3] = fast_exp(s[j][3] - mn1);
            sum0 += s[j][0] + s[j][1];
            sum1 += s[j][2] + s[j][3];
        }
        #pragma unroll
        for (int off = 1; off <= 2; off <<= 1){
            sum0 += __shfl_xor_sync(0xffffffffu, sum0, off);
            sum1 += __shfl_xor_sync(0xffffffffu, sum1, off);
        }
        l0s = l0s*corr0 + sum0;
        l1s = l1s*corr1 + sum1;
        #pragma unroll
        for (int j = 0; j < 8; j++){
            o[j][0] *= corr0; o[j][1] *= corr0;
            o[j][2] *= corr1; o[j][3] *= corr1;
        }

        // ---- O += P V (register P single; 1-pass) ----
        #pragma unroll
        for (int kc = 0; kc < 4; kc++){
            u32 ph4[4];
            ph4[0] = hpair(__float2half_rn(s[2*kc][0]),   __float2half_rn(s[2*kc][1]));
            ph4[1] = hpair(__float2half_rn(s[2*kc][2]),   __float2half_rn(s[2*kc][3]));
            ph4[2] = hpair(__float2half_rn(s[2*kc+1][0]), __float2half_rn(s[2*kc+1][1]));
            ph4[3] = hpair(__float2half_rn(s[2*kc+1][2]), __float2half_rn(s[2*kc+1][3]));
            #pragma unroll
            for (int i4 = 0; i4 < 4; i4++){
                u32 vh4[4];
                ldsm4(vh4, vhb + boffp + i4*(16*144) + kc*32);
                mma_f16(o[2*i4+0], ph4, vh4[0], vh4[1]);
                mma_f16(o[2*i4+1], ph4, vh4[2], vh4[3]);
            }
        }
    }

    // ---- finalize: O /= l, write single fp16 g_o[b*N+n][h*64+d] ----
    int b = bh / NHEADS, h = bh % NHEADS;
    float inv0 = 1.0f / l0s, inv1 = 1.0f / l1s;
    int r0 = lane >> 2, colq = 2*(lane & 3);
    int gq0 = q0 + warp*16 + r0;
    size_t base0 = (size_t)(b*NSEQ + gq0    )*NDIM + h*NHD;
    size_t base1 = (size_t)(b*NSEQ + gq0 + 8)*NDIM + h*NHD;
    #pragma unroll
    for (int j = 0; j < 8; j++){
        int d0 = 8*j + colq;
        *(u32*)(g_o + base0 + d0) = hpair(__float2half_rn(o[j][0]*inv0),
                                          __float2half_rn(o[j][1]*inv0));
        *(u32*)(g_o + base1 + d0) = hpair(__float2half_rn(o[j][2]*inv1),
                                          __float2half_rn(o[j][3]*inv1));
    }
}

// =====================================================================
extern "C" void kernel_launch(void* const* d_in, const int* in_sizes, int n_in,
                              void* d_out, int out_size)
{
    const float* x      = (const float*)d_in[0];
    const float* w_qkv  = (const float*)d_in[1];
    const float* w_proj = (const float*)d_in[2];
    const float* b_proj = (const float*)d_in[3];
    float* out = (float*)d_out;

    cudaFuncSetAttribute(mma_gemm_kernel, cudaFuncAttributeMaxDynamicSharedMemorySize, GEMM_SMEM);
    cudaFuncSetAttribute(flash_mma_kernel, cudaFuncAttributeMaxDynamicSharedMemorySize, FLASH_SMEM);

    int total_quads = (X_ELEMS + WQ_E + WP_E) / 4;
    split_kernel<<<(total_quads + 255)/256, 256>>>(x, w_qkv, w_proj);
    mma_gemm_kernel<<<dim3(2304/128, 16384/128), 256, GEMM_SMEM>>>(nullptr, nullptr, 0);
    flash_mma_kernel<<<dim3(NSEQ/128, NBATCH*NHEADS), 256, FLASH_SMEM>>>();
    mma_gemm_kernel<<<dim3(768/128, 16384/128), 256, GEMM_SMEM>>>(b_proj, out, 1);
}

// round 13
// speedup vs baseline: 6.1743x; 1.1499x over previous
#include <cuda_runtime.h>
#include <cuda_fp16.h>
#include <cstdint>

typedef unsigned long long u64;
typedef unsigned int u32;

#define NBATCH 16
#define NSEQ   1024
#define NDIM   768
#define NHEADS 12
#define NHD    64
#define ATT_SCALE 0.125f
#define QKV_ELEMS (NBATCH*NHEADS*NSEQ*NHD)    // 12582912
#define X_ELEMS   (NBATCH*NSEQ*NDIM)          // 12582912
#define WQ_E      (2304*768)
#define WP_E      (768*768)

// ---------------- static scratch (allocation-free) ----------------
__device__ __half g_x [X_ELEMS];                      // x single
__device__ __half g_wq[WQ_E];                         // w_qkv single
__device__ __half g_wp[WP_E];                         // w_proj single
__device__ __half g_q [QKV_ELEMS];                    // [B*H, N, D] single, pre-scaled
__device__ __half g_k [QKV_ELEMS];                    // [B*H, N, D] single
__device__ __half g_vt[QKV_ELEMS];                    // [B*H, D, N] single, transposed
__device__ __half g_o [X_ELEMS];                      // [B*N, C] single

// ---------------- helpers ----------------
__device__ __forceinline__ u32 smem_u32(const void* p){
    u32 a; asm("{ .reg .u64 t; cvta.to.shared.u64 t, %1; cvt.u32.u64 %0, t; }" : "=r"(a) : "l"(p));
    return a;
}
__device__ __forceinline__ u32 hpair(__half a, __half b){
    return (u32)__half_as_ushort(a) | ((u32)__half_as_ushort(b) << 16);
}

// fast exp on the FMA pipe (no MUFU), x <= ~0
__device__ __forceinline__ float fast_exp(float x){
    x = fmaxf(x, -80.0f);
    float t  = x * 1.4426950408889634f;
    float tr = t + 12582912.0f;
    int   n  = __float_as_int(tr) - 0x4B400000;
    float rn = tr - 12582912.0f;
    float f  = t - rn;
    float p = 1.3333558146428443e-3f;
    p = fmaf(p, f, 9.618129107628477e-3f);
    p = fmaf(p, f, 5.550410866482158e-2f);
    p = fmaf(p, f, 2.402265069591007e-1f);
    p = fmaf(p, f, 6.931471805599453e-1f);
    p = fmaf(p, f, 1.0f);
    return p * __int_as_float((n + 127) << 23);
}

// ---------------- mma/ldsm/cp.async primitives ----------------
__device__ __forceinline__ void ldsm4(u32* r, u32 addr){
    asm volatile("ldmatrix.sync.aligned.m8n8.x4.shared.b16 {%0,%1,%2,%3}, [%4];"
        : "=r"(r[0]), "=r"(r[1]), "=r"(r[2]), "=r"(r[3]) : "r"(addr));
}
__device__ __forceinline__ void mma_f16(float* c, const u32* a, u32 b0, u32 b1){
    asm volatile("mma.sync.aligned.m16n8k16.row.col.f32.f16.f16.f32 "
        "{%0,%1,%2,%3}, {%4,%5,%6,%7}, {%8,%9}, {%0,%1,%2,%3};"
        : "+f"(c[0]), "+f"(c[1]), "+f"(c[2]), "+f"(c[3])
        : "r"(a[0]), "r"(a[1]), "r"(a[2]), "r"(a[3]), "r"(b0), "r"(b1));
}
__device__ __forceinline__ void cp16(u32 dst, const void* src){
    asm volatile("cp.async.cg.shared.global [%0], [%1], 16;" :: "r"(dst), "l"(src));
}
__device__ __forceinline__ void cp_commit(){ asm volatile("cp.async.commit_group;" ::: "memory"); }
template<int N> __device__ __forceinline__ void cp_wait(){
    asm volatile("cp.async.wait_group %0;" :: "n"(N) : "memory");
}

// =====================================================================
// Prep: x, w_qkv, w_proj -> single rn fp16
// =====================================================================
__global__ __launch_bounds__(256) void split_kernel(
    const float* __restrict__ x, const float* __restrict__ wq, const float* __restrict__ wp)
{
    int i = (blockIdx.x*blockDim.x + threadIdx.x)*4;
    if (i < X_ELEMS){
        float4 v = *(const float4*)(x + i);
        *(u32*)(g_x+i)   = hpair(__float2half_rn(v.x), __float2half_rn(v.y));
        *(u32*)(g_x+i+2) = hpair(__float2half_rn(v.z), __float2half_rn(v.w));
    } else if (i < X_ELEMS + WQ_E){
        int j = i - X_ELEMS;
        float4 v = *(const float4*)(wq + j);
        *(u32*)(g_wq+j)   = hpair(__float2half_rn(v.x), __float2half_rn(v.y));
        *(u32*)(g_wq+j+2) = hpair(__float2half_rn(v.z), __float2half_rn(v.w));
    } else {
        int j = i - X_ELEMS - WQ_E;
        if (j < WP_E){
            float4 v = *(const float4*)(wp + j);
            *(u32*)(g_wp+j)   = hpair(__float2half_rn(v.x), __float2half_rn(v.y));
            *(u32*)(g_wp+j+2) = hpair(__float2half_rn(v.z), __float2half_rn(v.w));
        }
    }
}

// =====================================================================
// fp16 mma.sync GEMM: C = A * B^T. Block 128x128, BK=64,
// 2-stage cp.async double buffer (prefetch distance 1).
// 8 warps (4M x 2N), warp 32x64. Row pitch 144B (72 halves).
// mode 0: A=x, B=w_qkv -> q(single, scaled)/k(single)/vT(single).
// mode 1: A=O(single), B=w_proj, out = C + bias (f32).
// =====================================================================
#define GP          144                   // bytes per row
#define TILE3_B     (128*GP)              // 18432
#define STAGE3_B    (2*TILE3_B)           // 36864 (A, B)
#define GEMM_SMEM   (2*STAGE3_B)          // 73728

__global__ __launch_bounds__(256, 2) void mma_gemm_kernel(
    const float* __restrict__ bias, float* __restrict__ out, int mode)
{
    extern __shared__ __half smb[];
    const __half *As, *Bs;
    if (mode == 0){ As = g_x; Bs = g_wq; }
    else          { As = g_o; Bs = g_wp; }

    int tid = threadIdx.x;
    int lane = tid & 31, warp = tid >> 5;
    int wm = warp & 3, wn = warp >> 2;
    int m0 = blockIdx.y * 128, n0 = blockIdx.x * 128;

    u32 sbase = smem_u32(smb);
    u32 aoff = (u32)((wm*32 + (lane & 15))*GP + (lane >> 4)*16);
    u32 boff = (u32)((wn*64 + (lane & 7) + ((lane >> 4) & 1)*8)*GP + ((lane >> 3) & 1)*16);

    float c[2][8][4];
    #pragma unroll
    for (int i = 0; i < 2; i++)
        #pragma unroll
        for (int j = 0; j < 8; j++)
            #pragma unroll
            for (int q = 0; q < 4; q++) c[i][j][q] = 0.0f;

    auto load_chunk = [&](int chunk){
        int st = chunk & 1;
        u32 stb = sbase + st*STAGE3_B;
        int kf = chunk*64;
        #pragma unroll
        for (int it = 0; it < 8; it++){
            int tile = it >> 2;               // 0:A 1:B
            int fr = (it & 3)*256 + tid;      // 0..1023
            int row = fr >> 3, half = fr & 7;
            const __half* src = tile ? (Bs + (size_t)(n0 + row)*768 + kf + half*8)
                                     : (As + (size_t)(m0 + row)*768 + kf + half*8);
            cp16(stb + tile*TILE3_B + row*GP + half*16, src);
        }
        cp_commit();
    };

    load_chunk(0);

    #pragma unroll 1
    for (int i = 0; i < 12; i++){
        cp_wait<0>();
        __syncthreads();
        if (i + 1 < 12) load_chunk(i + 1);     // overlaps with compute below

        u32 stb = sbase + (i & 1)*STAGE3_B;
        #pragma unroll
        for (int kc = 0; kc < 4; kc++){
            u32 a4[2][4], b4[4][4];
            #pragma unroll
            for (int fm = 0; fm < 2; fm++)
                ldsm4(a4[fm], stb + aoff + fm*(16*GP) + kc*32);
            #pragma unroll
            for (int i4 = 0; i4 < 4; i4++)
                ldsm4(b4[i4], stb + TILE3_B + boff + i4*(16*GP) + kc*32);

            #pragma unroll
            for (int i4 = 0; i4 < 4; i4++)
                #pragma unroll
                for (int fm = 0; fm < 2; fm++){
                    mma_f16(c[fm][2*i4+0], a4[fm], b4[i4][0], b4[i4][1]);
                    mma_f16(c[fm][2*i4+1], a4[fm], b4[i4][2], b4[i4][3]);
                }
        }
    }

    // ---------------- epilogue ----------------
    int g = lane >> 2, tig = lane & 3;
    int colbase = n0 + wn*64;
    if (mode == 0){
        int hblk = colbase >> 6;
        int t_sel = hblk / NHEADS;
        int h     = hblk - t_sel*NHEADS;
        float sc  = (t_sel == 0) ? ATT_SCALE : 1.0f;
        #pragma unroll
        for (int fm = 0; fm < 2; fm++){
            int row0 = m0 + wm*32 + fm*16 + g;
            #pragma unroll
            for (int half = 0; half < 2; half++){
                int row = row0 + half*8;
                int b = row >> 10, n = row & 1023;
                int bh_i = b*NHEADS + h;
                if (t_sel == 2){
                    // V transposed single: g_vt[bh][d][n]
                    size_t vb = (size_t)bh_i*NHD*NSEQ + n;
                    #pragma unroll
                    for (int nf = 0; nf < 8; nf++){
                        int d0 = nf*8 + tig*2;
                        g_vt[vb + (size_t)d0*NSEQ]     = __float2half_rn(c[fm][nf][half*2]);
                        g_vt[vb + (size_t)(d0+1)*NSEQ] = __float2half_rn(c[fm][nf][half*2+1]);
                    }
                } else {
                    __half* dst = (t_sel == 0) ? g_q : g_k;
                    size_t base_e = ((size_t)bh_i*NSEQ + n)*NHD;
                    #pragma unroll
                    for (int nf = 0; nf < 8; nf++){
                        int d0 = nf*8 + tig*2;
                        *(u32*)(dst + base_e + d0) =
                            hpair(__float2half_rn(c[fm][nf][half*2]*sc),
                                  __float2half_rn(c[fm][nf][half*2+1]*sc));
                    }
                }
            }
        }
    } else {
        #pragma unroll
        for (int fm = 0; fm < 2; fm++){
            int row0 = m0 + wm*32 + fm*16 + g;
            #pragma unroll
            for (int half = 0; half < 2; half++){
                int row = row0 + half*8;
                float* base = out + (size_t)row*768 + colbase;
                #pragma unroll
                for (int nf = 0; nf < 8; nf++){
                    int cg = nf*8 + tig*2;
                    float2 bv = *(const float2*)(bias + colbase + cg);
                    *(float2*)(base + cg) =
                        make_float2(c[fm][nf][half*2] + bv.x,
                                    c[fm][nf][half*2+1] + bv.y);
                }
            }
        }
    }
}

// =====================================================================
// Flash attention, all-single fp16. QK: Q x K (1-pass). PV: P x V (1-pass).
// BQ=128 (8 warps x m16), BKV=64, D=64. Pitch 144B.
// 3-buffer KV cp.async pipeline, prefetch distance 2.
// =====================================================================
#define QT_B       (128*144)             // 18432 bytes (single Q tile)
#define KT_B       (64*144)              // 9216 bytes per KV tile
#define KVBUF_B    (2*KT_B)              // 18432 (K, V)
#define FLASH_SMEM (QT_B + 3*KVBUF_B)    // 73728

__global__ __launch_bounds__(256, 2) void flash_mma_kernel()
{
    extern __shared__ __half fbm[];
    int tid = threadIdx.x, lane = tid & 31, warp = tid >> 5;
    int q0 = blockIdx.x * 128;
    int bh = blockIdx.y;
    size_t hb  = (size_t)bh * NSEQ * NHD;   // q/k base
    size_t hvt = (size_t)bh * NHD * NSEQ;   // vt base

    u32 fbase = smem_u32(fbm);
    u32 qhb = fbase;
    u32 kvb = fbase + QT_B;

    u32 aoffp = (u32)((warp*16 + (lane & 15))*144 + (lane >> 4)*16);
    u32 boffp = (u32)(((lane & 7) + ((lane >> 4) & 1)*8)*144 + ((lane >> 3) & 1)*16);

    // Q single (group 1)
    #pragma unroll
    for (int it = 0; it < 4; it++){
        int f = tid + 256*it;
        int row = f >> 3, half = f & 7;
        cp16(qhb + row*144 + half*16, g_q + hb + (size_t)(q0 + row)*NHD + half*8);
    }
    cp_commit();

    auto load_kv = [&](int t){
        int c0 = t * 64;
        u32 bb = kvb + (t % 3)*KVBUF_B;
        #pragma unroll
        for (int it = 0; it < 4; it++){
            int tile = it >> 1;                 // 0:K 1:V
            int fr = (it & 1)*256 + tid;        // 0..511
            int row = fr >> 3, half = fr & 7;
            const __half* sp;
            if (tile == 0) sp = g_k  + hb  + (size_t)(c0 + row)*NHD + half*8;
            else           sp = g_vt + hvt + (size_t)row*NSEQ + c0 + half*8;
            cp16(bb + tile*KT_B + row*144 + half*16, sp);
        }
        cp_commit();
    };

    load_kv(0); load_kv(1);

    float o[8][4];
    #pragma unroll
    for (int j = 0; j < 8; j++)
        #pragma unroll
        for (int q = 0; q < 4; q++) o[j][q] = 0.0f;
    float m0f = -1e30f, m1f = -1e30f, l0s = 0.0f, l1s = 0.0f;

    #pragma unroll 1
    for (int t = 0; t < 16; t++){
        if (t < 15) cp_wait<1>();               // Q + kv(t) done; kv(t+1) may fly
        else        cp_wait<0>();
        __syncthreads();
        if (t + 2 < 16) load_kv(t + 2);         // overlaps with compute

        u32 bb  = kvb + (t % 3)*KVBUF_B;
        u32 khb = bb, vhb = bb + KT_B;

        // ---- S = Q K^T (single, 1-pass) ----
        float s[8][4];
        #pragma unroll
        for (int j = 0; j < 8; j++)
            #pragma unroll
            for (int q = 0; q < 4; q++) s[j][q] = 0.0f;

        #pragma unroll
        for (int kc = 0; kc < 4; kc++){
            u32 q4[4], kh4[4][4];
            ldsm4(q4, qhb + aoffp + kc*32);
            #pragma unroll
            for (int i4 = 0; i4 < 4; i4++)
                ldsm4(kh4[i4], khb + boffp + i4*(16*144) + kc*32);
            #pragma unroll
            for (int i4 = 0; i4 < 4; i4++){
                mma_f16(s[2*i4+0], q4, kh4[i4][0], kh4[i4][1]);
                mma_f16(s[2*i4+1], q4, kh4[i4][2], kh4[i4][3]);
            }
        }

        // ---- streaming softmax (in-place exp into s) ----
        float mx0 = -1e30f, mx1 = -1e30f;
        #pragma unroll
        for (int j = 0; j < 8; j++){
            mx0 = fmaxf(mx0, fmaxf(s[j][0], s[j][1]));
            mx1 = fmaxf(mx1, fmaxf(s[j][2], s[j][3]));
        }
        #pragma unroll
        for (int off = 1; off <= 2; off <<= 1){
            mx0 = fmaxf(mx0, __shfl_xor_sync(0xffffffffu, mx0, off));
            mx1 = fmaxf(mx1, __shfl_xor_sync(0xffffffffu, mx1, off));
        }
        float mn0 = fmaxf(m0f, mx0), mn1 = fmaxf(m1f, mx1);
        float corr0 = fast_exp(m0f - mn0), corr1 = fast_exp(m1f - mn1);
        m0f = mn0; m1f = mn1;

        float sum0 = 0.0f, sum1 = 0.0f;
        #pragma unroll
        for (int j = 0; j < 8; j++){
            s[j][0] = fast_exp(s[j][0] - mn0);
            s[j][1] = fast_exp(s[j][1] - mn0);
            s[j][2] = fast_exp(s[j][2] - mn1);
            s[j][3] = fast_exp(s[j][3] - mn1);
            sum0 += s[j][0] + s[j][1];
            sum1 += s[j][2] + s[j][3];
        }
        #pragma unroll
        for (int off = 1; off <= 2; off <<= 1){
            sum0 += __shfl_xor_sync(0xffffffffu, sum0, off);
            sum1 += __shfl_xor_sync(0xffffffffu, sum1, off);
        }
        l0s = l0s*corr0 + sum0;
        l1s = l1s*corr1 + sum1;
        #pragma unroll
        for (int j = 0; j < 8; j++){
            o[j][0] *= corr0; o[j][1] *= corr0;
            o[j][2] *= corr1; o[j][3] *= corr1;
        }

        // ---- O += P V (register P single; 1-pass) ----
        #pragma unroll
        for (int kc = 0; kc < 4; kc++){
            u32 ph4[4];
            ph4[0] = hpair(__float2half_rn(s[2*kc][0]),   __float2half_rn(s[2*kc][1]));
            ph4[1] = hpair(__float2half_rn(s[2*kc][2]),   __float2half_rn(s[2*kc][3]));
            ph4[2] = hpair(__float2half_rn(s[2*kc+1][0]), __float2half_rn(s[2*kc+1][1]));
            ph4[3] = hpair(__float2half_rn(s[2*kc+1][2]), __float2half_rn(s[2*kc+1][3]));
            #pragma unroll
            for (int i4 = 0; i4 < 4; i4++){
                u32 vh4[4];
                ldsm4(vh4, vhb + boffp + i4*(16*144) + kc*32);
                mma_f16(o[2*i4+0], ph4, vh4[0], vh4[1]);
                mma_f16(o[2*i4+1], ph4, vh4[2], vh4[3]);
            }
        }
    }

    // ---- finalize: O /= l, write single fp16 g_o[b*N+n][h*64+d] ----
    int b = bh / NHEADS, h = bh % NHEADS;
    float inv0 = 1.0f / l0s, inv1 = 1.0f / l1s;
    int r0 = lane >> 2, colq = 2*(lane & 3);
    int gq0 = q0 + warp*16 + r0;
    size_t base0 = (size_t)(b*NSEQ + gq0    )*NDIM + h*NHD;
    size_t base1 = (size_t)(b*NSEQ + gq0 + 8)*NDIM + h*NHD;
    #pragma unroll
    for (int j = 0; j < 8; j++){
        int d0 = 8*j + colq;
        *(u32*)(g_o + base0 + d0) = hpair(__float2half_rn(o[j][0]*inv0),
                                          __float2half_rn(o[j][1]*inv0));
        *(u32*)(g_o + base1 + d0) = hpair(__float2half_rn(o[j][2]*inv1),
                                          __float2half_rn(o[j][3]*inv1));
    }
}

// =====================================================================
extern "C" void kernel_launch(void* const* d_in, const int* in_sizes, int n_in,
                              void* d_out, int out_size)
{
    const float* x      = (const float*)d_in[0];
    const float* w_qkv  = (const float*)d_in[1];
    const float* w_proj = (const float*)d_in[2];
    const float* b_proj = (const float*)d_in[3];
    float* out = (float*)d_out;

    cudaFuncSetAttribute(mma_gemm_kernel, cudaFuncAttributeMaxDynamicSharedMemorySize, GEMM_SMEM);
    cudaFuncSetAttribute(flash_mma_kernel, cudaFuncAttributeMaxDynamicSharedMemorySize, FLASH_SMEM);

    int total_quads = (X_ELEMS + WQ_E + WP_E) / 4;
    split_kernel<<<(total_quads + 255)/256, 256>>>(x, w_qkv, w_proj);
    mma_gemm_kernel<<<dim3(2304/128, 16384/128), 256, GEMM_SMEM>>>(nullptr, nullptr, 0);
    flash_mma_kernel<<<dim3(NSEQ/128, NBATCH*NHEADS), 256, FLASH_SMEM>>>();
    mma_gemm_kernel<<<dim3(768/128, 16384/128), 256, GEMM_SMEM>>>(b_proj, out, 1);
}